// round 3
// baseline (speedup 1.0000x reference)
#include <cuda_runtime.h>
#include <math.h>

#define NB  512
#define NC  112
#define NP  64
#define NHW 256
#define NOC 256
#define CCH 16          // C-chunk for corr GEMM (112 = 7*16)

typedef unsigned long long u64;

// ---- f32x2 helpers (Blackwell packed fp32 pipe) ----
__device__ __forceinline__ u64 pk2(float lo, float hi) {
    u64 r; asm("mov.b64 %0, {%1,%2};" : "=l"(r) : "f"(lo), "f"(hi)); return r;
}
__device__ __forceinline__ void up2(u64 v, float& a, float& b) {
    asm("mov.b64 {%0,%1}, %2;" : "=f"(a), "=f"(b) : "l"(v));
}
__device__ __forceinline__ void fma2(u64& d, u64 a, u64 b) {
    asm("fma.rn.f32x2 %0, %1, %2, %0;" : "+l"(d) : "l"(a), "l"(b));
}

// ---- shared memory layout (floats). total 57344 floats = 229376 B ----
#define SM_MISC 0        // 4096 floats
#define SM_CORR 4096     // 64*256
#define SM_DW   20480    // 64*256 (phase A: search chunk + z-dup live here)
#define SM_FT   36864    // 64*256
#define SM_PWT  53248    // 64*64
#define SM_TOTF 57344

// misc sub-offsets
#define MS_ATT  0      // 64
#define MS_H    64     // 64
#define MS_A    128    // 64
#define MS_DWW  192    // 576
#define MS_BNSC 768    // 256
#define MS_BNSH 1024   // 256
#define MS_WP   1280   // up to 2304

// One tower: depthwise 3x3 -> pointwise GEMM (4 o-tiles of 64) -> BN+ReLU ->
// 3x3 pred-conv partial accumulation into acc_pred[NPRED].
template<int NPRED>
__device__ __forceinline__ void tower(
    float* sm, int tid, int lane, int warp,
    const float* __restrict__ dwW, const float* __restrict__ pwW,
    const float* __restrict__ bng, const float* __restrict__ bnb,
    const float* __restrict__ bnm, const float* __restrict__ bnv,
    const float* __restrict__ predW, float* acc_pred)
{
    float* s_a    = sm + MS_A;
    float* s_dww  = sm + MS_DWW;
    float* s_bnsc = sm + MS_BNSC;
    float* s_bnsh = sm + MS_BNSH;
    float* s_wp   = sm + MS_WP;
    float* s_corr = sm + SM_CORR;
    float* s_dw   = sm + SM_DW;
    float* s_ft   = sm + SM_FT;
    float* s_pwt  = sm + SM_PWT;

    // load depthwise weights + BN affine fold
    for (int i = tid; i < NP * 9; i += 256) s_dww[i] = dwW[i];
    if (tid < NOC) {
        float sc = bng[tid] * rsqrtf(bnv[tid] + 1e-5f);
        s_bnsc[tid] = sc;
        s_bnsh[tid] = bnb[tid] - bnm[tid] * sc;
    }
    __syncthreads();

    // ---- depthwise 3x3 (attention scale folded in), thread = pixel ----
    {
        const int px = tid, y = tid >> 4, x = tid & 15;
        const bool okU = y > 0, okD = y < 15, okL = x > 0, okR = x < 15;
#pragma unroll 4
        for (int p = 0; p < NP; p++) {
            const float* r = s_corr + p * NHW + px;
            const float* w = s_dww + p * 9;
            float acc = r[0] * w[4];
            if (okU) { acc = fmaf(r[-16], w[1], acc);
                       if (okL) acc = fmaf(r[-17], w[0], acc);
                       if (okR) acc = fmaf(r[-15], w[2], acc); }
            if (okD) { acc = fmaf(r[16], w[7], acc);
                       if (okL) acc = fmaf(r[15], w[6], acc);
                       if (okR) acc = fmaf(r[17], w[8], acc); }
            if (okL) acc = fmaf(r[-1], w[3], acc);
            if (okR) acc = fmaf(r[1],  w[5], acc);
            s_dw[p * NHW + px] = acc * s_a[p];
        }
    }
    __syncthreads();

    const int o0l = warp * 8;

    for (int ot = 0; ot < 4; ot++) {
        // load pointwise weights (transposed) + pred-conv weight tile
        for (int i = tid; i < 64 * 64; i += 256) {
            int o = i >> 6, k = i & 63;
            s_pwt[k * 64 + o] = pwW[(ot * 64 + o) * 64 + k];
        }
        for (int i = tid; i < NPRED * 576; i += 256) {
            int oc = i / 576, j = i - oc * 576;
            s_wp[i] = predW[oc * 2304 + ot * 576 + j];
        }
        __syncthreads();

        // ---- pointwise GEMM: 64o x 256px, K=64, f32x2 packed ----
        u64 acc[8][4];
#pragma unroll
        for (int j = 0; j < 8; j++)
#pragma unroll
            for (int i = 0; i < 4; i++) acc[j][i] = 0ull;

#pragma unroll 4
        for (int k = 0; k < 64; k++) {
            u64 wr[8];
#pragma unroll
            for (int j = 0; j < 8; j++) {
                float t = s_pwt[k * 64 + o0l + j];   // warp-broadcast
                wr[j] = pk2(t, t);
            }
            float xv[8];
#pragma unroll
            for (int jj = 0; jj < 8; jj++) xv[jj] = s_dw[k * NHW + lane + 32 * jj];
            u64 xr[4];
#pragma unroll
            for (int i = 0; i < 4; i++) xr[i] = pk2(xv[i], xv[i + 4]);
#pragma unroll
            for (int j = 0; j < 8; j++)
#pragma unroll
                for (int i = 0; i < 4; i++) fma2(acc[j][i], wr[j], xr[i]);
        }

        // BN + ReLU -> s_ft
#pragma unroll
        for (int j = 0; j < 8; j++) {
            int o = ot * 64 + o0l + j;
            float sc = s_bnsc[o], sh = s_bnsh[o];
#pragma unroll
            for (int i = 0; i < 4; i++) {
                float a0, a1; up2(acc[j][i], a0, a1);
                a0 = fmaxf(fmaf(a0, sc, sh), 0.0f);
                a1 = fmaxf(fmaf(a1, sc, sh), 0.0f);
                s_ft[(o0l + j) * NHW + lane + 32 * i]       = a0;
                s_ft[(o0l + j) * NHW + lane + 32 * (i + 4)] = a1;
            }
        }
        __syncthreads();

        // ---- pred-conv partial over this 64-channel tile, thread = pixel ----
        {
            const int px = tid, y = tid >> 4, x = tid & 15;
            const bool okU = y > 0, okD = y < 15, okL = x > 0, okR = x < 15;
#pragma unroll 2
            for (int c = 0; c < 64; c++) {
                const float* r = s_ft + c * NHW + px;
                float nv[9];
                nv[4] = r[0];
                nv[1] = okU ? r[-16] : 0.0f;
                nv[0] = (okU && okL) ? r[-17] : 0.0f;
                nv[2] = (okU && okR) ? r[-15] : 0.0f;
                nv[7] = okD ? r[16] : 0.0f;
                nv[6] = (okD && okL) ? r[15] : 0.0f;
                nv[8] = (okD && okR) ? r[17] : 0.0f;
                nv[3] = okL ? r[-1] : 0.0f;
                nv[5] = okR ? r[1] : 0.0f;
#pragma unroll
                for (int oc = 0; oc < NPRED; oc++) {
                    const float* wc = s_wp + oc * 576 + c * 9;
                    float a = acc_pred[oc];
#pragma unroll
                    for (int k = 0; k < 9; k++) a = fmaf(nv[k], wc[k], a);
                    acc_pred[oc] = a;
                }
            }
        }
        __syncthreads();
    }
}

__global__ void __launch_bounds__(256, 1)
btl_kernel(
    const float* __restrict__ search, const float* __restrict__ kern,
    const float* __restrict__ ca_w1, const float* __restrict__ ca_b1,
    const float* __restrict__ ca_w2, const float* __restrict__ ca_b2,
    const float* __restrict__ cls_dw, const float* __restrict__ cls_pw,
    const float* __restrict__ cls_bng, const float* __restrict__ cls_bnb,
    const float* __restrict__ cls_bnm, const float* __restrict__ cls_bnv,
    const float* __restrict__ cls_predw, const float* __restrict__ cls_predb,
    const float* __restrict__ box_dw, const float* __restrict__ box_pw,
    const float* __restrict__ box_bng, const float* __restrict__ box_bnb,
    const float* __restrict__ box_bnm, const float* __restrict__ box_bnv,
    const float* __restrict__ box_predw, const float* __restrict__ box_predb,
    const float* __restrict__ adjust, const float* __restrict__ biasp,
    float* __restrict__ out)
{
    extern __shared__ float sm[];
    const int tid  = threadIdx.x;
    const int lane = tid & 31;
    const int warp = tid >> 5;
    const int b    = blockIdx.x;

    float* s_att = sm + MS_ATT;
    float* s_h   = sm + MS_H;
    float* s_a   = sm + MS_A;
    float* s_corr = sm + SM_CORR;

    // ===== Phase A: pixel-wise correlation GEMM  corr[64p x 256px] K=112 =====
    // thread px-set: px = lane + 32*jj (jj 0..7); p-set: p = warp*8 + j
    float* s_search = sm + SM_DW;             // 4096 floats
    u64*   s_zd     = (u64*)(sm + SM_DW + 4096); // 1024 u64 (z duplicated pairs)

    const float* gS = search + (size_t)b * NC * NHW;
    const float* gZ = kern   + (size_t)b * NC * NP;

    u64 cacc[8][4];
#pragma unroll
    for (int j = 0; j < 8; j++)
#pragma unroll
        for (int i = 0; i < 4; i++) cacc[j][i] = 0ull;

    for (int c0 = 0; c0 < NC; c0 += CCH) {
        __syncthreads();
        const float4* src4 = (const float4*)(gS + c0 * NHW);
        float4* dst4 = (float4*)s_search;
#pragma unroll
        for (int i = tid; i < CCH * NHW / 4; i += 256) dst4[i] = src4[i];
        const float* zsrc = gZ + c0 * NP;
#pragma unroll
        for (int i = tid; i < CCH * NP; i += 256) {
            float v = zsrc[i];
            s_zd[i] = pk2(v, v);
        }
        __syncthreads();

#pragma unroll 4
        for (int cc = 0; cc < CCH; cc++) {
            u64 zr[8];
#pragma unroll
            for (int j = 0; j < 8; j++) zr[j] = s_zd[cc * NP + warp * 8 + j]; // broadcast
            float xv[8];
#pragma unroll
            for (int jj = 0; jj < 8; jj++) xv[jj] = s_search[cc * NHW + lane + 32 * jj];
            u64 xr[4];
#pragma unroll
            for (int i = 0; i < 4; i++) xr[i] = pk2(xv[i], xv[i + 4]);
#pragma unroll
            for (int j = 0; j < 8; j++)
#pragma unroll
                for (int i = 0; i < 4; i++) fma2(cacc[j][i], zr[j], xr[i]);
        }
    }

    // store corr to SMEM + warp-shuffle channel means (for attention)
#pragma unroll
    for (int j = 0; j < 8; j++) {
        const int p = warp * 8 + j;
        float ps = 0.0f;
#pragma unroll
        for (int i = 0; i < 4; i++) {
            float a0, a1; up2(cacc[j][i], a0, a1);
            s_corr[p * NHW + lane + 32 * i]       = a0;
            s_corr[p * NHW + lane + 32 * (i + 4)] = a1;
            ps += a0 + a1;
        }
#pragma unroll
        for (int o = 16; o > 0; o >>= 1) ps += __shfl_xor_sync(0xffffffffu, ps, o);
        if (lane == 0) s_att[p] = ps * (1.0f / 256.0f);
    }
    __syncthreads();

    // ===== Phase B: channel-attention MLP (64->64->64), sigmoid =====
    if (tid < 64) {
        float s1 = ca_b1[tid];
        const float* w = ca_w1 + tid * 64;
#pragma unroll 8
        for (int j = 0; j < 64; j++) s1 = fmaf(w[j], s_att[j], s1);
        s_h[tid] = fmaxf(s1, 0.0f);
    }
    __syncthreads();
    if (tid < 64) {
        float s2 = ca_b2[tid];
        const float* w = ca_w2 + tid * 64;
#pragma unroll 8
        for (int j = 0; j < 64; j++) s2 = fmaf(w[j], s_h[j], s2);
        s_a[tid] = 1.0f / (1.0f + expf(-s2));
    }
    __syncthreads();

    // ===== Phase C: towers =====
    float acc_cls[1] = {0.0f};
    tower<1>(sm, tid, lane, warp, cls_dw, cls_pw,
             cls_bng, cls_bnb, cls_bnm, cls_bnv, cls_predw, acc_cls);

    float acc_box[4] = {0.0f, 0.0f, 0.0f, 0.0f};
    tower<4>(sm, tid, lane, warp, box_dw, box_pw,
             box_bng, box_bnb, box_bnm, box_bnv, box_predw, acc_box);

    // ===== epilogue: thread = pixel =====
    const int px = tid;
    // cls: [B,1,16,16] stored after x: offset NB*4*NHW
    out[(size_t)NB * 4 * NHW + (size_t)b * NHW + px] = 0.1f * (acc_cls[0] + cls_predb[0]);
    const float adj = adjust[0];
#pragma unroll
    for (int oc = 0; oc < 4; oc++) {
        float pred = acc_box[oc] + box_predb[oc];
        out[((size_t)b * 4 + oc) * NHW + px] = expf(adj * pred + biasp[oc]);
    }
}

extern "C" void kernel_launch(void* const* d_in, const int* in_sizes, int n_in,
                              void* d_out, int out_size)
{
    const float* search    = (const float*)d_in[0];
    const float* kern      = (const float*)d_in[1];
    const float* ca_w1     = (const float*)d_in[2];
    const float* ca_b1     = (const float*)d_in[3];
    const float* ca_w2     = (const float*)d_in[4];
    const float* ca_b2     = (const float*)d_in[5];
    const float* cls_dw    = (const float*)d_in[6];
    const float* cls_pw    = (const float*)d_in[7];
    const float* cls_bng   = (const float*)d_in[8];
    const float* cls_bnb   = (const float*)d_in[9];
    const float* cls_bnm   = (const float*)d_in[10];
    const float* cls_bnv   = (const float*)d_in[11];
    const float* cls_predw = (const float*)d_in[12];
    const float* cls_predb = (const float*)d_in[13];
    const float* box_dw    = (const float*)d_in[14];
    const float* box_pw    = (const float*)d_in[15];
    const float* box_bng   = (const float*)d_in[16];
    const float* box_bnb   = (const float*)d_in[17];
    const float* box_bnm   = (const float*)d_in[18];
    const float* box_bnv   = (const float*)d_in[19];
    const float* box_predw = (const float*)d_in[20];
    const float* box_predb = (const float*)d_in[21];
    const float* adjust    = (const float*)d_in[22];
    const float* biasp     = (const float*)d_in[23];

    const int smbytes = SM_TOTF * 4;  // 229376 B
    cudaFuncSetAttribute(btl_kernel, cudaFuncAttributeMaxDynamicSharedMemorySize, smbytes);

    btl_kernel<<<NB, 256, smbytes>>>(
        search, kern, ca_w1, ca_b1, ca_w2, ca_b2,
        cls_dw, cls_pw, cls_bng, cls_bnb, cls_bnm, cls_bnv, cls_predw, cls_predb,
        box_dw, box_pw, box_bng, box_bnb, box_bnm, box_bnv, box_predw, box_predb,
        adjust, biasp, (float*)d_out);
}

// round 4
// speedup vs baseline: 1.5135x; 1.5135x over previous
#include <cuda_runtime.h>
#include <math.h>

#define NB   512
#define NC   112
#define NP   64
#define NHW  256
#define NOC  256
#define CCH  16
#define NT   512   // threads per CTA

typedef unsigned long long u64;

// ---- f32x2 helpers ----
__device__ __forceinline__ u64 pk2(float lo, float hi) {
    u64 r; asm("mov.b64 %0, {%1,%2};" : "=l"(r) : "f"(lo), "f"(hi)); return r;
}
__device__ __forceinline__ void up2(u64 v, float& a, float& b) {
    asm("mov.b64 {%0,%1}, %2;" : "=f"(a), "=f"(b) : "l"(v));
}
__device__ __forceinline__ void fma2(u64& d, u64 a, u64 b) {
    asm("fma.rn.f32x2 %0, %1, %2, %0;" : "+l"(d) : "l"(a), "l"(b));
}

// ---- shared memory layout (float index). total 57344 floats = 229376 B ----
#define SM_MISC 0        // 4096
#define SM_CORR 4096     // 64*256
#define SM_DW   20480    // 64*256  (phase A: search chunk + z-dup; end: S partials)
#define SM_FT   36864    // 64*256
#define SM_PWT  53248    // 64*64
#define SM_TOTF 57344

#define MS_ATT   0      // 64
#define MS_H     64     // 64
#define MS_A     128    // 64
#define MS_DWW   192    // 576
#define MS_BNSC  768    // 256
#define MS_BNSH  1024   // 256
#define MS_WP    1280   // 2304 (box) / 768 (cls, padded 12)
#define MS_CLSO  3584   // 256

// One tower. Produces tap-sum partials S (registers) per thread, written by the
// caller-side code below into smem for the final 9-tap gather.
// NPRED==1: S has 5 u64 (k-pairs (0,1)(2,3)(4,5)(6,7)(8,pad)).
// NPRED==4: S has 18 u64 (k*2+{0,1} = oc-pairs (0,1)(2,3)).
template<int NPRED, int NS>
__device__ __forceinline__ void tower(
    float* sm, int tid, int lane, int warp,
    const float* __restrict__ dwW, const float* __restrict__ pwW,
    const float* __restrict__ bng, const float* __restrict__ bnb,
    const float* __restrict__ bnm, const float* __restrict__ bnv,
    const float* __restrict__ predW, u64 (&S)[NS])
{
    float* s_a    = sm + MS_A;
    float* s_dww  = sm + MS_DWW;
    float* s_bnsc = sm + MS_BNSC;
    float* s_bnsh = sm + MS_BNSH;
    float* s_wp   = sm + MS_WP;
    float* s_corr = sm + SM_CORR;
    float* s_dw   = sm + SM_DW;
    float* s_ft   = sm + SM_FT;
    float* s_pwt  = sm + SM_PWT;

    // stage depthwise weights + folded BN affine
    for (int i = tid; i < NP * 9; i += NT) s_dww[i] = dwW[i];
    if (tid < NOC) {
        float sc = bng[tid] * rsqrtf(bnv[tid] + 1e-5f);
        s_bnsc[tid] = sc;
        s_bnsh[tid] = bnb[tid] - bnm[tid] * sc;
    }
    __syncthreads();

    // ---- depthwise 3x3 (+attention fold). 512 thr: p-half x 256 px ----
    {
        const int px = tid & 255, ph = tid >> 8;
        const int y = px >> 4, x = px & 15;
        const bool okU = y > 0, okD = y < 15, okL = x > 0, okR = x < 15;
#pragma unroll 4
        for (int pi = 0; pi < 32; pi++) {
            const int p = ph * 32 + pi;
            const float* r = s_corr + p * NHW + px;
            const float* w = s_dww + p * 9;
            float acc = r[0] * w[4];
            if (okU) { acc = fmaf(r[-16], w[1], acc);
                       if (okL) acc = fmaf(r[-17], w[0], acc);
                       if (okR) acc = fmaf(r[-15], w[2], acc); }
            if (okD) { acc = fmaf(r[16], w[7], acc);
                       if (okL) acc = fmaf(r[15], w[6], acc);
                       if (okR) acc = fmaf(r[17], w[8], acc); }
            if (okL) acc = fmaf(r[-1], w[3], acc);
            if (okR) acc = fmaf(r[1],  w[5], acc);
            s_dw[p * NHW + px] = acc * s_a[p];
        }
    }
    __syncthreads();

    const int o0l = warp * 4;   // 16 warps x 4 o = 64-o tile

    for (int ot = 0; ot < 4; ot++) {
        // stage pointwise weights (k-major) + pred-conv weights (re-laid out)
        for (int i = tid; i < 64 * 64; i += NT) {
            int o = i >> 6, k = i & 63;
            s_pwt[k * 64 + o] = pwW[(ot * 64 + o) * 64 + k];
        }
        if (NPRED == 4) {
            for (int i = tid; i < 2304; i += NT) {
                int oc = i & 3, r = i >> 2, k = r % 9, c = r / 9;
                s_wp[i] = predW[oc * 2304 + (ot * 64 + c) * 9 + k];
            }
        } else {
            for (int i = tid; i < 768; i += NT) {
                int c = i / 12, k = i % 12;
                s_wp[i] = (k < 9) ? predW[(ot * 64 + c) * 9 + k] : 0.0f;
            }
        }
        __syncthreads();

        // ---- pointwise GEMM: warp tile 4o x 256px, K=64, packed f32x2 ----
        u64 acc[4][4];
#pragma unroll
        for (int j = 0; j < 4; j++)
#pragma unroll
            for (int q = 0; q < 4; q++) acc[j][q] = 0ull;

#pragma unroll 2
        for (int k = 0; k < 64; k++) {
            u64 wr[4];
#pragma unroll
            for (int j = 0; j < 4; j++) {
                float t = s_pwt[k * 64 + o0l + j];      // warp-broadcast
                wr[j] = pk2(t, t);
            }
            ulonglong2 x0 = *(const ulonglong2*)(s_dw + k * NHW + 4 * lane);
            ulonglong2 x1 = *(const ulonglong2*)(s_dw + k * NHW + 128 + 4 * lane);
            u64 xr[4] = {x0.x, x0.y, x1.x, x1.y};
#pragma unroll
            for (int j = 0; j < 4; j++)
#pragma unroll
                for (int q = 0; q < 4; q++) fma2(acc[j][q], wr[j], xr[q]);
        }

        // BN + ReLU -> s_ft (packed stores)
#pragma unroll
        for (int j = 0; j < 4; j++) {
            const int o = ot * 64 + o0l + j;
            const float sc = s_bnsc[o], sh = s_bnsh[o];
#pragma unroll
            for (int q = 0; q < 4; q++) {
                float a0, a1; up2(acc[j][q], a0, a1);
                a0 = fmaxf(fmaf(a0, sc, sh), 0.0f);
                a1 = fmaxf(fmaf(a1, sc, sh), 0.0f);
                const int px0 = (q >> 1) * 128 + 4 * lane + (q & 1) * 2;
                *(u64*)(s_ft + (o0l + j) * NHW + px0) = pk2(a0, a1);
            }
        }
        __syncthreads();

        // ---- tap-sum accumulation (NO neighbor gather): c-half x 256 px ----
        {
            const int px = tid & 255, ch = tid >> 8;
#pragma unroll 2
            for (int ci = 0; ci < 32; ci++) {
                const int c = ch * 32 + ci;
                const float xv = s_ft[c * NHW + px];
                const u64 xd = pk2(xv, xv);
                if (NPRED == 4) {
                    const ulonglong2* wp2 = (const ulonglong2*)(s_wp + c * 36);
#pragma unroll
                    for (int k = 0; k < 9; k++) {
                        ulonglong2 w = wp2[k];          // LDS.128 broadcast
                        fma2(S[k * 2], xd, w.x);
                        fma2(S[k * 2 + 1], xd, w.y);
                    }
                } else {
                    const ulonglong2* wp2 = (const ulonglong2*)(s_wp + c * 12);
                    ulonglong2 wA = wp2[0];
                    ulonglong2 wB = wp2[1];
                    float w8 = s_wp[c * 12 + 8];
                    fma2(S[0], xd, wA.x);
                    fma2(S[1], xd, wA.y);
                    fma2(S[2], xd, wB.x);
                    fma2(S[3], xd, wB.y);
                    fma2(S[4], xd, pk2(w8, 0.0f));
                }
            }
        }
        __syncthreads();   // before next tile overwrites pwt/wp/ft
    }
}

__global__ void __launch_bounds__(NT, 1)
btl_kernel(
    const float* __restrict__ search, const float* __restrict__ kern,
    const float* __restrict__ ca_w1, const float* __restrict__ ca_b1,
    const float* __restrict__ ca_w2, const float* __restrict__ ca_b2,
    const float* __restrict__ cls_dw, const float* __restrict__ cls_pw,
    const float* __restrict__ cls_bng, const float* __restrict__ cls_bnb,
    const float* __restrict__ cls_bnm, const float* __restrict__ cls_bnv,
    const float* __restrict__ cls_predw, const float* __restrict__ cls_predb,
    const float* __restrict__ box_dw, const float* __restrict__ box_pw,
    const float* __restrict__ box_bng, const float* __restrict__ box_bnb,
    const float* __restrict__ box_bnm, const float* __restrict__ box_bnv,
    const float* __restrict__ box_predw, const float* __restrict__ box_predb,
    const float* __restrict__ adjust, const float* __restrict__ biasp,
    float* __restrict__ out)
{
    extern __shared__ float sm[];
    const int tid  = threadIdx.x;
    const int lane = tid & 31;
    const int warp = tid >> 5;
    const int b    = blockIdx.x;

    float* s_att  = sm + MS_ATT;
    float* s_h    = sm + MS_H;
    float* s_a    = sm + MS_A;
    float* s_clso = sm + MS_CLSO;
    float* s_corr = sm + SM_CORR;

    // ===== Phase A: correlation GEMM corr[64p x 256px], K=112 =====
    float* s_search = sm + SM_DW;                    // 4096 floats
    u64*   s_zd     = (u64*)(sm + SM_DW + 4096);     // 1024 u64

    const float* gS = search + (size_t)b * NC * NHW;
    const float* gZ = kern   + (size_t)b * NC * NP;

    u64 cacc[4][4];
#pragma unroll
    for (int j = 0; j < 4; j++)
#pragma unroll
        for (int q = 0; q < 4; q++) cacc[j][q] = 0ull;

    for (int c0 = 0; c0 < NC; c0 += CCH) {
        __syncthreads();
        const float4* src4 = (const float4*)(gS + c0 * NHW);
        float4* dst4 = (float4*)s_search;
#pragma unroll
        for (int i = tid; i < CCH * NHW / 4; i += NT) dst4[i] = src4[i];
        const float* zsrc = gZ + c0 * NP;
#pragma unroll
        for (int i = tid; i < CCH * NP; i += NT) {
            float v = zsrc[i];
            s_zd[i] = pk2(v, v);
        }
        __syncthreads();

#pragma unroll 2
        for (int cc = 0; cc < CCH; cc++) {
            u64 zr[4];
#pragma unroll
            for (int j = 0; j < 4; j++) zr[j] = s_zd[cc * NP + warp * 4 + j];
            ulonglong2 x0 = *(const ulonglong2*)(s_search + cc * NHW + 4 * lane);
            ulonglong2 x1 = *(const ulonglong2*)(s_search + cc * NHW + 128 + 4 * lane);
            u64 xr[4] = {x0.x, x0.y, x1.x, x1.y};
#pragma unroll
            for (int j = 0; j < 4; j++)
#pragma unroll
                for (int q = 0; q < 4; q++) fma2(cacc[j][q], zr[j], xr[q]);
        }
    }

    // store corr (packed) + per-p means via shuffle
#pragma unroll
    for (int j = 0; j < 4; j++) {
        const int p = warp * 4 + j;
        float ps = 0.0f;
#pragma unroll
        for (int q = 0; q < 4; q++) {
            float a0, a1; up2(cacc[j][q], a0, a1);
            const int px0 = (q >> 1) * 128 + 4 * lane + (q & 1) * 2;
            *(u64*)(s_corr + p * NHW + px0) = cacc[j][q];
            ps += a0 + a1;
        }
#pragma unroll
        for (int o = 16; o > 0; o >>= 1) ps += __shfl_xor_sync(0xffffffffu, ps, o);
        if (lane == 0) s_att[p] = ps * (1.0f / 256.0f);
    }
    __syncthreads();

    // ===== Phase B: channel-attention MLP =====
    if (tid < 64) {
        float s1 = ca_b1[tid];
        const float* w = ca_w1 + tid * 64;
#pragma unroll 8
        for (int j = 0; j < 64; j++) s1 = fmaf(w[j], s_att[j], s1);
        s_h[tid] = fmaxf(s1, 0.0f);
    }
    __syncthreads();
    if (tid < 64) {
        float s2 = ca_b2[tid];
        const float* w = ca_w2 + tid * 64;
#pragma unroll 8
        for (int j = 0; j < 64; j++) s2 = fmaf(w[j], s_h[j], s2);
        s_a[tid] = 1.0f / (1.0f + expf(-s2));
    }
    __syncthreads();

    // ===== cls tower =====
    {
        u64 Sc[5];
#pragma unroll
        for (int i = 0; i < 5; i++) Sc[i] = 0ull;
        tower<1, 5>(sm, tid, lane, warp, cls_dw, cls_pw,
                    cls_bng, cls_bnb, cls_bnm, cls_bnv, cls_predw, Sc);

        // write cls tap-sum partials: s_dw[(ch*9+k)*256 + px]
        {
            const int px = tid & 255, ch = tid >> 8;
            float* dst = sm + SM_DW;
#pragma unroll
            for (int kp = 0; kp < 4; kp++) {
                float a0, a1; up2(Sc[kp], a0, a1);
                dst[(ch * 9 + 2 * kp) * 256 + px]     = a0;
                dst[(ch * 9 + 2 * kp + 1) * 256 + px] = a1;
            }
            float a0, a1; up2(Sc[4], a0, a1);
            dst[(ch * 9 + 8) * 256 + px] = a0;
        }
        __syncthreads();

        // masked 9-tap gather -> s_clso
        if (tid < 256) {
            const int px = tid, y = px >> 4, x = px & 15;
            const float* dst = sm + SM_DW;
            float acc = 0.0f;
#pragma unroll
            for (int dy = -1; dy <= 1; dy++) {
                if (y + dy < 0 || y + dy > 15) continue;
#pragma unroll
                for (int dx = -1; dx <= 1; dx++) {
                    if (x + dx < 0 || x + dx > 15) continue;
                    const int k = (dy + 1) * 3 + (dx + 1);
                    const int q = px + dy * 16 + dx;
                    acc += dst[k * 256 + q] + dst[(9 + k) * 256 + q];
                }
            }
            s_clso[px] = acc;
        }
        __syncthreads();
    }

    // ===== box tower =====
    u64 Sb[18];
#pragma unroll
    for (int i = 0; i < 18; i++) Sb[i] = 0ull;
    tower<4, 18>(sm, tid, lane, warp, box_dw, box_pw,
                 box_bng, box_bnb, box_bnm, box_bnv, box_predw, Sb);

    // write box tap-sum partials: layout [k][px][4oc], half0->SM_DW, half1->SM_CORR
    {
        const int px = tid & 255, ch = tid >> 8;
        float* dst = (ch == 0) ? (sm + SM_DW) : (sm + SM_CORR);
#pragma unroll
        for (int k = 0; k < 9; k++) {
            ulonglong2 v; v.x = Sb[k * 2]; v.y = Sb[k * 2 + 1];
            *(ulonglong2*)(dst + (k * 256 + px) * 4) = v;
        }
    }
    __syncthreads();

    // ===== epilogue: masked box gather + stores (thread = pixel) =====
    if (tid < 256) {
        const int px = tid, y = px >> 4, x = px & 15;
        out[(size_t)NB * 4 * NHW + (size_t)b * NHW + px] =
            0.1f * (s_clso[px] + cls_predb[0]);

        float bx0 = 0.0f, bx1 = 0.0f, bx2 = 0.0f, bx3 = 0.0f;
        const float* d0 = sm + SM_DW;
        const float* d1 = sm + SM_CORR;
#pragma unroll
        for (int dy = -1; dy <= 1; dy++) {
            if (y + dy < 0 || y + dy > 15) continue;
#pragma unroll
            for (int dx = -1; dx <= 1; dx++) {
                if (x + dx < 0 || x + dx > 15) continue;
                const int k = (dy + 1) * 3 + (dx + 1);
                const int q = (k * 256 + px + dy * 16 + dx) * 4;
                float4 v0 = *(const float4*)(d0 + q);
                float4 v1 = *(const float4*)(d1 + q);
                bx0 += v0.x + v1.x; bx1 += v0.y + v1.y;
                bx2 += v0.z + v1.z; bx3 += v0.w + v1.w;
            }
        }
        const float adj = adjust[0];
        out[((size_t)b * 4 + 0) * NHW + px] = expf(adj * (bx0 + box_predb[0]) + biasp[0]);
        out[((size_t)b * 4 + 1) * NHW + px] = expf(adj * (bx1 + box_predb[1]) + biasp[1]);
        out[((size_t)b * 4 + 2) * NHW + px] = expf(adj * (bx2 + box_predb[2]) + biasp[2]);
        out[((size_t)b * 4 + 3) * NHW + px] = expf(adj * (bx3 + box_predb[3]) + biasp[3]);
    }
}

extern "C" void kernel_launch(void* const* d_in, const int* in_sizes, int n_in,
                              void* d_out, int out_size)
{
    const float* search    = (const float*)d_in[0];
    const float* kern      = (const float*)d_in[1];
    const float* ca_w1     = (const float*)d_in[2];
    const float* ca_b1     = (const float*)d_in[3];
    const float* ca_w2     = (const float*)d_in[4];
    const float* ca_b2     = (const float*)d_in[5];
    const float* cls_dw    = (const float*)d_in[6];
    const float* cls_pw    = (const float*)d_in[7];
    const float* cls_bng   = (const float*)d_in[8];
    const float* cls_bnb   = (const float*)d_in[9];
    const float* cls_bnm   = (const float*)d_in[10];
    const float* cls_bnv   = (const float*)d_in[11];
    const float* cls_predw = (const float*)d_in[12];
    const float* cls_predb = (const float*)d_in[13];
    const float* box_dw    = (const float*)d_in[14];
    const float* box_pw    = (const float*)d_in[15];
    const float* box_bng   = (const float*)d_in[16];
    const float* box_bnb   = (const float*)d_in[17];
    const float* box_bnm   = (const float*)d_in[18];
    const float* box_bnv   = (const float*)d_in[19];
    const float* box_predw = (const float*)d_in[20];
    const float* box_predb = (const float*)d_in[21];
    const float* adjust    = (const float*)d_in[22];
    const float* biasp     = (const float*)d_in[23];

    const int smbytes = SM_TOTF * 4;  // 229376 B
    cudaFuncSetAttribute(btl_kernel, cudaFuncAttributeMaxDynamicSharedMemorySize, smbytes);

    btl_kernel<<<NB, NT, smbytes>>>(
        search, kern, ca_w1, ca_b1, ca_w2, ca_b2,
        cls_dw, cls_pw, cls_bng, cls_bnb, cls_bnm, cls_bnv, cls_predw, cls_predb,
        box_dw, box_pw, box_bng, box_bnb, box_bnm, box_bnv, box_predw, box_predb,
        adjust, biasp, (float*)d_out);
}

// round 5
// speedup vs baseline: 1.5719x; 1.0386x over previous
#include <cuda_runtime.h>
#include <math.h>

#define NB   512
#define NC   112
#define NP   64
#define NHW  256
#define NOC  256
#define CCH  16
#define NT   1024   // threads per CTA (32 warps)

typedef unsigned long long u64;

// ---- f32x2 helpers ----
__device__ __forceinline__ u64 pk2(float lo, float hi) {
    u64 r; asm("mov.b64 %0, {%1,%2};" : "=l"(r) : "f"(lo), "f"(hi)); return r;
}
__device__ __forceinline__ void up2(u64 v, float& a, float& b) {
    asm("mov.b64 {%0,%1}, %2;" : "=f"(a), "=f"(b) : "l"(v));
}
__device__ __forceinline__ void fma2(u64& d, u64 a, u64 b) {
    asm("fma.rn.f32x2 %0, %1, %2, %0;" : "+l"(d) : "l"(a), "l"(b));
}

// ---- shared memory layout (float index). total 57344 floats = 229376 B ----
#define SM_MISC 0        // 4096
#define SM_CORR 4096     // 64*256
#define SM_DW   20480    // 64*256
#define SM_FT   36864    // 64*256
#define SM_PWT  53248    // 64*64
#define SM_TOTF 57344

#define MS_ATT   0      // 64
#define MS_H     64     // 64
#define MS_A     128    // 64
#define MS_DWW   192    // 576
#define MS_BNSC  768    // 256
#define MS_BNSH  1024   // 256
#define MS_WP    1280   // 2560 (box, padded 20/c/op) or 768 (cls, padded 12/c)
#define MS_CLSO  3840   // 256

// One tower. Tap-sum partials S per thread:
// NPRED==1: thread group = c-quarter (16 c). S[5]: k-pairs (0,1)(2,3)(4,5)(6,7)(8,-).
// NPRED==4: thread group = (c-half, oc-pair). S[9]: S[k] = (oc_lo, oc_hi) pair.
template<int NPRED, int NS>
__device__ __forceinline__ void tower(
    float* sm, int tid, int lane, int warp,
    const float* __restrict__ dwW, const float* __restrict__ pwW,
    const float* __restrict__ bng, const float* __restrict__ bnb,
    const float* __restrict__ bnm, const float* __restrict__ bnv,
    const float* __restrict__ predW, u64 (&S)[NS])
{
    float* s_a    = sm + MS_A;
    float* s_dww  = sm + MS_DWW;
    float* s_bnsc = sm + MS_BNSC;
    float* s_bnsh = sm + MS_BNSH;
    float* s_wp   = sm + MS_WP;
    float* s_corr = sm + SM_CORR;
    float* s_dw   = sm + SM_DW;
    float* s_ft   = sm + SM_FT;
    float* s_pwt  = sm + SM_PWT;

    // stage depthwise weights + folded BN affine
    for (int i = tid; i < NP * 9; i += NT) s_dww[i] = dwW[i];
    if (tid < NOC) {
        float sc = bng[tid] * rsqrtf(bnv[tid] + 1e-5f);
        s_bnsc[tid] = sc;
        s_bnsh[tid] = bnb[tid] - bnm[tid] * sc;
    }
    __syncthreads();

    // ---- depthwise 3x3 (+attention fold). 1024 thr: p-quarter x 256 px ----
    {
        const int px = tid & 255, pq = tid >> 8;
        const int y = px >> 4, x = px & 15;
        const bool okU = y > 0, okD = y < 15, okL = x > 0, okR = x < 15;
#pragma unroll 4
        for (int pi = 0; pi < 16; pi++) {
            const int p = pq * 16 + pi;
            const float* r = s_corr + p * NHW + px;
            const float* w = s_dww + p * 9;
            float acc = r[0] * w[4];
            if (okU) { acc = fmaf(r[-16], w[1], acc);
                       if (okL) acc = fmaf(r[-17], w[0], acc);
                       if (okR) acc = fmaf(r[-15], w[2], acc); }
            if (okD) { acc = fmaf(r[16], w[7], acc);
                       if (okL) acc = fmaf(r[15], w[6], acc);
                       if (okR) acc = fmaf(r[17], w[8], acc); }
            if (okL) acc = fmaf(r[-1], w[3], acc);
            if (okR) acc = fmaf(r[1],  w[5], acc);
            s_dw[p * NHW + px] = acc * s_a[p];
        }
    }
    __syncthreads();

    const int o0l = (warp & 15) * 4;   // 16 o-groups
    const int pxh = warp >> 4;         // px-half (0..1)

    for (int ot = 0; ot < 4; ot++) {
        // stage pointwise weights (k-major)
        for (int i = tid; i < 64 * 64; i += NT) {
            int o = i >> 6, k = i & 63;
            s_pwt[k * 64 + o] = pwW[(ot * 64 + o) * 64 + k];
        }
        // stage pred-conv weights
        if (NPRED == 4) {
            // layout: [c][op][20]: floats (2k, 2k+1) = (w[oc=2op], w[oc=2op+1]) tap k
            for (int i = tid; i < 64 * 2 * 20; i += NT) {
                int c = i / 40, r = i % 40, op = r / 20, t = r % 20;
                float v = 0.0f;
                if (t < 18) {
                    int k = t >> 1, h = t & 1;
                    v = predW[(op * 2 + h) * 2304 + (ot * 64 + c) * 9 + k];
                }
                s_wp[i] = v;
            }
        } else {
            for (int i = tid; i < 768; i += NT) {
                int c = i / 12, k = i % 12;
                s_wp[i] = (k < 9) ? predW[(ot * 64 + c) * 9 + k] : 0.0f;
            }
        }
        __syncthreads();

        // ---- pointwise GEMM: warp tile 4o x 128px, K=64 ----
        u64 acc[4][2];
#pragma unroll
        for (int j = 0; j < 4; j++) { acc[j][0] = 0ull; acc[j][1] = 0ull; }

#pragma unroll 4
        for (int k = 0; k < 64; k++) {
            float4 wv = *(const float4*)(s_pwt + k * 64 + o0l);  // broadcast LDS.128
            u64 wr[4] = {pk2(wv.x, wv.x), pk2(wv.y, wv.y),
                         pk2(wv.z, wv.z), pk2(wv.w, wv.w)};
            ulonglong2 xq = *(const ulonglong2*)(s_dw + k * NHW + pxh * 128 + 4 * lane);
            u64 xr[2] = {xq.x, xq.y};
#pragma unroll
            for (int j = 0; j < 4; j++) {
                fma2(acc[j][0], wr[j], xr[0]);
                fma2(acc[j][1], wr[j], xr[1]);
            }
        }

        // BN + ReLU -> s_ft (packed stores)
#pragma unroll
        for (int j = 0; j < 4; j++) {
            const int o = ot * 64 + o0l + j;
            const float sc = s_bnsc[o], sh = s_bnsh[o];
#pragma unroll
            for (int q = 0; q < 2; q++) {
                float a0, a1; up2(acc[j][q], a0, a1);
                a0 = fmaxf(fmaf(a0, sc, sh), 0.0f);
                a1 = fmaxf(fmaf(a1, sc, sh), 0.0f);
                *(u64*)(s_ft + (o0l + j) * NHW + pxh * 128 + 4 * lane + 2 * q) = pk2(a0, a1);
            }
        }
        __syncthreads();

        // ---- tap-sum accumulation (no neighbor gather) ----
        {
            const int px = tid & 255, grp = tid >> 8;
            if (NPRED == 4) {
                const int ch = grp & 1, op = grp >> 1;
#pragma unroll 2
                for (int ci = 0; ci < 32; ci++) {
                    const int c = ch * 32 + ci;
                    const float xv = s_ft[c * NHW + px];
                    const u64 xd = pk2(xv, xv);
                    const float* wb = s_wp + (c * 2 + op) * 20;
                    const ulonglong2* w2 = (const ulonglong2*)wb;   // 16B aligned
                    ulonglong2 wa = w2[0], wc = w2[1], wd = w2[2], we = w2[3];
                    u64 w8 = *(const u64*)(wb + 16);
                    fma2(S[0], xd, wa.x); fma2(S[1], xd, wa.y);
                    fma2(S[2], xd, wc.x); fma2(S[3], xd, wc.y);
                    fma2(S[4], xd, wd.x); fma2(S[5], xd, wd.y);
                    fma2(S[6], xd, we.x); fma2(S[7], xd, we.y);
                    fma2(S[8], xd, w8);
                }
            } else {
                const int cq = grp;
#pragma unroll 2
                for (int ci = 0; ci < 16; ci++) {
                    const int c = cq * 16 + ci;
                    const float xv = s_ft[c * NHW + px];
                    const u64 xd = pk2(xv, xv);
                    const ulonglong2* wp2 = (const ulonglong2*)(s_wp + c * 12);
                    ulonglong2 wA = wp2[0];
                    ulonglong2 wB = wp2[1];
                    float w8 = s_wp[c * 12 + 8];
                    fma2(S[0], xd, wA.x);
                    fma2(S[1], xd, wA.y);
                    fma2(S[2], xd, wB.x);
                    fma2(S[3], xd, wB.y);
                    fma2(S[4], xd, pk2(w8, 0.0f));
                }
            }
        }
        __syncthreads();
    }
}

__global__ void __launch_bounds__(NT, 1)
btl_kernel(
    const float* __restrict__ search, const float* __restrict__ kern,
    const float* __restrict__ ca_w1, const float* __restrict__ ca_b1,
    const float* __restrict__ ca_w2, const float* __restrict__ ca_b2,
    const float* __restrict__ cls_dw, const float* __restrict__ cls_pw,
    const float* __restrict__ cls_bng, const float* __restrict__ cls_bnb,
    const float* __restrict__ cls_bnm, const float* __restrict__ cls_bnv,
    const float* __restrict__ cls_predw, const float* __restrict__ cls_predb,
    const float* __restrict__ box_dw, const float* __restrict__ box_pw,
    const float* __restrict__ box_bng, const float* __restrict__ box_bnb,
    const float* __restrict__ box_bnm, const float* __restrict__ box_bnv,
    const float* __restrict__ box_predw, const float* __restrict__ box_predb,
    const float* __restrict__ adjust, const float* __restrict__ biasp,
    float* __restrict__ out)
{
    extern __shared__ float sm[];
    const int tid  = threadIdx.x;
    const int lane = tid & 31;
    const int warp = tid >> 5;
    const int b    = blockIdx.x;

    float* s_att  = sm + MS_ATT;
    float* s_h    = sm + MS_H;
    float* s_a    = sm + MS_A;
    float* s_clso = sm + MS_CLSO;
    float* s_corr = sm + SM_CORR;

    // ===== Phase A: correlation GEMM corr[64p x 256px], K=112 =====
    float* s_search = sm + SM_DW;                    // 4096 floats
    u64*   s_zd     = (u64*)(sm + SM_DW + 4096);     // 1024 u64

    const float* gS = search + (size_t)b * NC * NHW;
    const float* gZ = kern   + (size_t)b * NC * NP;

    u64 cacc[2][4];
#pragma unroll
    for (int j = 0; j < 2; j++)
#pragma unroll
        for (int q = 0; q < 4; q++) cacc[j][q] = 0ull;

    for (int c0 = 0; c0 < NC; c0 += CCH) {
        __syncthreads();
        const float4* src4 = (const float4*)(gS + c0 * NHW);
        float4* dst4 = (float4*)s_search;
#pragma unroll
        for (int i = tid; i < CCH * NHW / 4; i += NT) dst4[i] = src4[i];
        const float* zsrc = gZ + c0 * NP;
#pragma unroll
        for (int i = tid; i < CCH * NP; i += NT) {
            float v = zsrc[i];
            s_zd[i] = pk2(v, v);
        }
        __syncthreads();

#pragma unroll 2
        for (int cc = 0; cc < CCH; cc++) {
            ulonglong2 zq = *(const ulonglong2*)(s_zd + cc * NP + warp * 2); // broadcast
            u64 zr[2] = {zq.x, zq.y};
            ulonglong2 x0 = *(const ulonglong2*)(s_search + cc * NHW + 4 * lane);
            ulonglong2 x1 = *(const ulonglong2*)(s_search + cc * NHW + 128 + 4 * lane);
            u64 xr[4] = {x0.x, x0.y, x1.x, x1.y};
#pragma unroll
            for (int j = 0; j < 2; j++)
#pragma unroll
                for (int q = 0; q < 4; q++) fma2(cacc[j][q], zr[j], xr[q]);
        }
    }

    // store corr (packed) + per-p means via shuffle
#pragma unroll
    for (int j = 0; j < 2; j++) {
        const int p = warp * 2 + j;
        float ps = 0.0f;
#pragma unroll
        for (int q = 0; q < 4; q++) {
            float a0, a1; up2(cacc[j][q], a0, a1);
            const int px0 = (q >> 1) * 128 + 4 * lane + (q & 1) * 2;
            *(u64*)(s_corr + p * NHW + px0) = cacc[j][q];
            ps += a0 + a1;
        }
#pragma unroll
        for (int o = 16; o > 0; o >>= 1) ps += __shfl_xor_sync(0xffffffffu, ps, o);
        if (lane == 0) s_att[p] = ps * (1.0f / 256.0f);
    }
    __syncthreads();

    // ===== Phase B: channel-attention MLP =====
    if (tid < 64) {
        float s1 = ca_b1[tid];
        const float* w = ca_w1 + tid * 64;
#pragma unroll 8
        for (int j = 0; j < 64; j++) s1 = fmaf(w[j], s_att[j], s1);
        s_h[tid] = fmaxf(s1, 0.0f);
    }
    __syncthreads();
    if (tid < 64) {
        float s2 = ca_b2[tid];
        const float* w = ca_w2 + tid * 64;
#pragma unroll 8
        for (int j = 0; j < 64; j++) s2 = fmaf(w[j], s_h[j], s2);
        s_a[tid] = 1.0f / (1.0f + expf(-s2));
    }
    __syncthreads();

    // ===== cls tower =====
    {
        u64 Sc[5];
#pragma unroll
        for (int i = 0; i < 5; i++) Sc[i] = 0ull;
        tower<1, 5>(sm, tid, lane, warp, cls_dw, cls_pw,
                    cls_bng, cls_bnb, cls_bnm, cls_bnv, cls_predw, Sc);

        // write cls tap-sum partials: s_dw[(grp*9+k)*256 + px], grp = c-quarter
        {
            const int px = tid & 255, grp = tid >> 8;
            float* dst = sm + SM_DW;
#pragma unroll
            for (int kp = 0; kp < 4; kp++) {
                float a0, a1; up2(Sc[kp], a0, a1);
                dst[(grp * 9 + 2 * kp) * 256 + px]     = a0;
                dst[(grp * 9 + 2 * kp + 1) * 256 + px] = a1;
            }
            float a0, a1; up2(Sc[4], a0, a1);
            dst[(grp * 9 + 8) * 256 + px] = a0;
        }
        __syncthreads();

        // masked 9-tap gather over 4 groups -> s_clso
        if (tid < 256) {
            const int px = tid, y = px >> 4, x = px & 15;
            const float* dst = sm + SM_DW;
            float acc = 0.0f;
#pragma unroll
            for (int dy = -1; dy <= 1; dy++) {
                if (y + dy < 0 || y + dy > 15) continue;
#pragma unroll
                for (int dx = -1; dx <= 1; dx++) {
                    if (x + dx < 0 || x + dx > 15) continue;
                    const int k = (dy + 1) * 3 + (dx + 1);
                    const int q = px + dy * 16 + dx;
                    acc += dst[(k)      * 256 + q] + dst[(9 + k)  * 256 + q]
                         + dst[(18 + k) * 256 + q] + dst[(27 + k) * 256 + q];
                }
            }
            s_clso[px] = acc;
        }
        __syncthreads();
    }

    // ===== box tower =====
    u64 Sb[9];
#pragma unroll
    for (int i = 0; i < 9; i++) Sb[i] = 0ull;
    tower<4, 9>(sm, tid, lane, warp, box_dw, box_pw,
                box_bng, box_bnb, box_bnm, box_bnv, box_predw, Sb);

    // write box tap-sum partials: [k][px][4oc]; ch selects buffer, op selects u64 half
    {
        const int px = tid & 255, grp = tid >> 8;
        const int ch = grp & 1, op = grp >> 1;
        float* dst = (ch == 0) ? (sm + SM_DW) : (sm + SM_CORR);
#pragma unroll
        for (int k = 0; k < 9; k++)
            *(u64*)(dst + (k * 256 + px) * 4 + op * 2) = Sb[k];
    }
    __syncthreads();

    // ===== epilogue: masked box gather + stores (thread = pixel) =====
    if (tid < 256) {
        const int px = tid, y = px >> 4, x = px & 15;
        out[(size_t)NB * 4 * NHW + (size_t)b * NHW + px] =
            0.1f * (s_clso[px] + cls_predb[0]);

        float bx0 = 0.0f, bx1 = 0.0f, bx2 = 0.0f, bx3 = 0.0f;
        const float* d0 = sm + SM_DW;
        const float* d1 = sm + SM_CORR;
#pragma unroll
        for (int dy = -1; dy <= 1; dy++) {
            if (y + dy < 0 || y + dy > 15) continue;
#pragma unroll
            for (int dx = -1; dx <= 1; dx++) {
                if (x + dx < 0 || x + dx > 15) continue;
                const int k = (dy + 1) * 3 + (dx + 1);
                const int q = (k * 256 + px + dy * 16 + dx) * 4;
                float4 v0 = *(const float4*)(d0 + q);
                float4 v1 = *(const float4*)(d1 + q);
                bx0 += v0.x + v1.x; bx1 += v0.y + v1.y;
                bx2 += v0.z + v1.z; bx3 += v0.w + v1.w;
            }
        }
        const float adj = adjust[0];
        out[((size_t)b * 4 + 0) * NHW + px] = expf(adj * (bx0 + box_predb[0]) + biasp[0]);
        out[((size_t)b * 4 + 1) * NHW + px] = expf(adj * (bx1 + box_predb[1]) + biasp[1]);
        out[((size_t)b * 4 + 2) * NHW + px] = expf(adj * (bx2 + box_predb[2]) + biasp[2]);
        out[((size_t)b * 4 + 3) * NHW + px] = expf(adj * (bx3 + box_predb[3]) + biasp[3]);
    }
}

extern "C" void kernel_launch(void* const* d_in, const int* in_sizes, int n_in,
                              void* d_out, int out_size)
{
    const float* search    = (const float*)d_in[0];
    const float* kern      = (const float*)d_in[1];
    const float* ca_w1     = (const float*)d_in[2];
    const float* ca_b1     = (const float*)d_in[3];
    const float* ca_w2     = (const float*)d_in[4];
    const float* ca_b2     = (const float*)d_in[5];
    const float* cls_dw    = (const float*)d_in[6];
    const float* cls_pw    = (const float*)d_in[7];
    const float* cls_bng   = (const float*)d_in[8];
    const float* cls_bnb   = (const float*)d_in[9];
    const float* cls_bnm   = (const float*)d_in[10];
    const float* cls_bnv   = (const float*)d_in[11];
    const float* cls_predw = (const float*)d_in[12];
    const float* cls_predb = (const float*)d_in[13];
    const float* box_dw    = (const float*)d_in[14];
    const float* box_pw    = (const float*)d_in[15];
    const float* box_bng   = (const float*)d_in[16];
    const float* box_bnb   = (const float*)d_in[17];
    const float* box_bnm   = (const float*)d_in[18];
    const float* box_bnv   = (const float*)d_in[19];
    const float* box_predw = (const float*)d_in[20];
    const float* box_predb = (const float*)d_in[21];
    const float* adjust    = (const float*)d_in[22];
    const float* biasp     = (const float*)d_in[23];

    const int smbytes = SM_TOTF * 4;  // 229376 B
    cudaFuncSetAttribute(btl_kernel, cudaFuncAttributeMaxDynamicSharedMemorySize, smbytes);

    btl_kernel<<<NB, NT, smbytes>>>(
        search, kern, ca_w1, ca_b1, ca_w2, ca_b2,
        cls_dw, cls_pw, cls_bng, cls_bnb, cls_bnm, cls_bnv, cls_predw, cls_predb,
        box_dw, box_pw, box_bng, box_bnb, box_bnm, box_bnv, box_predw, box_predb,
        adjust, biasp, (float*)d_out);
}

// round 6
// speedup vs baseline: 1.6276x; 1.0355x over previous
#include <cuda_runtime.h>
#include <math.h>

#define NB   512
#define NC   112
#define NP   64
#define NHW  256
#define NOC  256
#define CCH  16
#define NT   1024   // threads per CTA (32 warps)

typedef unsigned long long u64;

// ---- f32x2 helpers ----
__device__ __forceinline__ u64 pk2(float lo, float hi) {
    u64 r; asm("mov.b64 %0, {%1,%2};" : "=l"(r) : "f"(lo), "f"(hi)); return r;
}
__device__ __forceinline__ void up2(u64 v, float& a, float& b) {
    asm("mov.b64 {%0,%1}, %2;" : "=f"(a), "=f"(b) : "l"(v));
}
__device__ __forceinline__ void fma2(u64& d, u64 a, u64 b) {
    asm("fma.rn.f32x2 %0, %1, %2, %0;" : "+l"(d) : "l"(a), "l"(b));
}

// ---- shared memory layout (float index). total 57344 floats = 229376 B ----
#define SM_MISC 0        // 4096
#define SM_CORR 4096     // 64*256
#define SM_DW   20480    // 64*256
#define SM_FT   36864    // 64*256
#define SM_PWT  53248    // 64*64
#define SM_TOTF 57344

#define MS_ATT   0      // 64
#define MS_H     64     // 64
#define MS_A     128    // 64
#define MS_DWW   192    // 576
#define MS_BNSC  768    // 256
#define MS_BNSH  1024   // 256
#define MS_WP    1280   // 2560 (box, padded 20/c/op) or 768 (cls, padded 12/c)
#define MS_CLSO  3840   // 256

// One tower. Tap-sum partials S per thread:
// NPRED==1: thread group = c-quarter (16 c). S[5]: k-pairs (0,1)(2,3)(4,5)(6,7)(8,-).
// NPRED==4: thread group = (c-half, oc-pair). S[9]: S[k] = (oc_lo, oc_hi) pair.
template<int NPRED, int NS>
__device__ __forceinline__ void tower(
    float* sm, int tid, int lane, int warp,
    const float* __restrict__ dwW, const float* __restrict__ pwW,
    const float* __restrict__ bng, const float* __restrict__ bnb,
    const float* __restrict__ bnm, const float* __restrict__ bnv,
    const float* __restrict__ predW, u64 (&S)[NS])
{
    float* s_a    = sm + MS_A;
    float* s_dww  = sm + MS_DWW;
    float* s_bnsc = sm + MS_BNSC;
    float* s_bnsh = sm + MS_BNSH;
    float* s_wp   = sm + MS_WP;
    float* s_corr = sm + SM_CORR;
    float* s_dw   = sm + SM_DW;
    float* s_ft   = sm + SM_FT;
    float* s_pwt  = sm + SM_PWT;

    // stage depthwise weights + folded BN affine
    for (int i = tid; i < NP * 9; i += NT) s_dww[i] = dwW[i];
    if (tid < NOC) {
        float sc = bng[tid] * rsqrtf(bnv[tid] + 1e-5f);
        s_bnsc[tid] = sc;
        s_bnsh[tid] = bnb[tid] - bnm[tid] * sc;
    }
    __syncthreads();

    // ---- depthwise 3x3 (+attention fold). p-quarter x 256 px ----
    {
        const int px = tid & 255, pq = tid >> 8;
        const int y = px >> 4, x = px & 15;
        const bool okU = y > 0, okD = y < 15, okL = x > 0, okR = x < 15;
#pragma unroll 4
        for (int pi = 0; pi < 16; pi++) {
            const int p = pq * 16 + pi;
            const float* r = s_corr + p * NHW + px;
            const float* w = s_dww + p * 9;
            float acc = r[0] * w[4];
            if (okU) { acc = fmaf(r[-16], w[1], acc);
                       if (okL) acc = fmaf(r[-17], w[0], acc);
                       if (okR) acc = fmaf(r[-15], w[2], acc); }
            if (okD) { acc = fmaf(r[16], w[7], acc);
                       if (okL) acc = fmaf(r[15], w[6], acc);
                       if (okR) acc = fmaf(r[17], w[8], acc); }
            if (okL) acc = fmaf(r[-1], w[3], acc);
            if (okR) acc = fmaf(r[1],  w[5], acc);
            s_dw[p * NHW + px] = acc * s_a[p];
        }
    }
    __syncthreads();

    const int og  = warp >> 2;          // 8 o-groups of 8 o (4 native pairs)
    const int pxq = warp & 3;           // 4 px-quarters of 64 px
    const int ob  = og * 8;
    const int pxb = pxq * 64 + lane * 2;

    for (int ot = 0; ot < 4; ot++) {
        // stage pointwise weights (k-major)
        for (int i = tid; i < 64 * 64; i += NT) {
            int o = i >> 6, k = i & 63;
            s_pwt[k * 64 + o] = pwW[(ot * 64 + o) * 64 + k];
        }
        // stage pred-conv weights
        if (NPRED == 4) {
            for (int i = tid; i < 64 * 2 * 20; i += NT) {
                int c = i / 40, r = i % 40, op = r / 20, t = r % 20;
                float v = 0.0f;
                if (t < 18) {
                    int k = t >> 1, h = t & 1;
                    v = predW[(op * 2 + h) * 2304 + (ot * 64 + c) * 9 + k];
                }
                s_wp[i] = v;
            }
        } else {
            for (int i = tid; i < 768; i += NT) {
                int c = i / 12, k = i % 12;
                s_wp[i] = (k < 9) ? predW[(ot * 64 + c) * 9 + k] : 0.0f;
            }
        }
        __syncthreads();

        // ---- pointwise GEMM: warp tile 8o(4 pairs) x 64px, K=64 ----
        u64 acc[4][2];
#pragma unroll
        for (int j = 0; j < 4; j++) { acc[j][0] = 0ull; acc[j][1] = 0ull; }

#pragma unroll 4
        for (int k = 0; k < 64; k++) {
            const float* wp = s_pwt + k * 64 + ob;
            ulonglong2 wA = *(const ulonglong2*)wp;        // native (o,o+1) pairs
            ulonglong2 wB = *(const ulonglong2*)(wp + 4);
            u64 wr[4] = {wA.x, wA.y, wB.x, wB.y};
            u64 xp = *(const u64*)(s_dw + k * NHW + pxb);
            float x0, x1; up2(xp, x0, x1);
            u64 xd0 = pk2(x0, x0), xd1 = pk2(x1, x1);
#pragma unroll
            for (int j = 0; j < 4; j++) {
                fma2(acc[j][0], wr[j], xd0);
                fma2(acc[j][1], wr[j], xd1);
            }
        }

        // BN + ReLU -> s_ft
#pragma unroll
        for (int j = 0; j < 4; j++) {
            const int o = ot * 64 + ob + 2 * j;
            const float sc0 = s_bnsc[o],     sh0 = s_bnsh[o];
            const float sc1 = s_bnsc[o + 1], sh1 = s_bnsh[o + 1];
#pragma unroll
            for (int q = 0; q < 2; q++) {
                float a0, a1; up2(acc[j][q], a0, a1);
                a0 = fmaxf(fmaf(a0, sc0, sh0), 0.0f);
                a1 = fmaxf(fmaf(a1, sc1, sh1), 0.0f);
                s_ft[(ob + 2 * j)     * NHW + pxb + q] = a0;
                s_ft[(ob + 2 * j + 1) * NHW + pxb + q] = a1;
            }
        }
        __syncthreads();

        // ---- tap-sum accumulation (no neighbor gather) ----
        {
            const int px = tid & 255, grp = tid >> 8;
            if (NPRED == 4) {
                const int ch = grp & 1, op = grp >> 1;
#pragma unroll 2
                for (int ci = 0; ci < 32; ci++) {
                    const int c = ch * 32 + ci;
                    const float xv = s_ft[c * NHW + px];
                    const u64 xd = pk2(xv, xv);
                    const float* wb = s_wp + (c * 2 + op) * 20;
                    const ulonglong2* w2 = (const ulonglong2*)wb;   // 16B aligned
                    ulonglong2 wa = w2[0], wc = w2[1], wd = w2[2], we = w2[3];
                    u64 w8 = *(const u64*)(wb + 16);
                    fma2(S[0], xd, wa.x); fma2(S[1], xd, wa.y);
                    fma2(S[2], xd, wc.x); fma2(S[3], xd, wc.y);
                    fma2(S[4], xd, wd.x); fma2(S[5], xd, wd.y);
                    fma2(S[6], xd, we.x); fma2(S[7], xd, we.y);
                    fma2(S[8], xd, w8);
                }
            } else {
                const int cq = grp;
#pragma unroll 2
                for (int ci = 0; ci < 16; ci++) {
                    const int c = cq * 16 + ci;
                    const float xv = s_ft[c * NHW + px];
                    const u64 xd = pk2(xv, xv);
                    const ulonglong2* wp2 = (const ulonglong2*)(s_wp + c * 12);
                    ulonglong2 wA = wp2[0];
                    ulonglong2 wB = wp2[1];
                    float w8 = s_wp[c * 12 + 8];
                    fma2(S[0], xd, wA.x);
                    fma2(S[1], xd, wA.y);
                    fma2(S[2], xd, wB.x);
                    fma2(S[3], xd, wB.y);
                    fma2(S[4], xd, pk2(w8, 0.0f));
                }
            }
        }
        __syncthreads();
    }
}

__global__ void __launch_bounds__(NT, 1)
btl_kernel(
    const float* __restrict__ search, const float* __restrict__ kern,
    const float* __restrict__ ca_w1, const float* __restrict__ ca_b1,
    const float* __restrict__ ca_w2, const float* __restrict__ ca_b2,
    const float* __restrict__ cls_dw, const float* __restrict__ cls_pw,
    const float* __restrict__ cls_bng, const float* __restrict__ cls_bnb,
    const float* __restrict__ cls_bnm, const float* __restrict__ cls_bnv,
    const float* __restrict__ cls_predw, const float* __restrict__ cls_predb,
    const float* __restrict__ box_dw, const float* __restrict__ box_pw,
    const float* __restrict__ box_bng, const float* __restrict__ box_bnb,
    const float* __restrict__ box_bnm, const float* __restrict__ box_bnv,
    const float* __restrict__ box_predw, const float* __restrict__ box_predb,
    const float* __restrict__ adjust, const float* __restrict__ biasp,
    float* __restrict__ out)
{
    extern __shared__ float sm[];
    const int tid  = threadIdx.x;
    const int lane = tid & 31;
    const int warp = tid >> 5;
    const int b    = blockIdx.x;

    float* s_att  = sm + MS_ATT;
    float* s_h    = sm + MS_H;
    float* s_a    = sm + MS_A;
    float* s_clso = sm + MS_CLSO;
    float* s_corr = sm + SM_CORR;

    // ===== Phase A: correlation GEMM corr[64p x 256px], K=112 =====
    // warp tile: 8 p (4 native pairs) x 64 px
    float* s_search = sm + SM_DW;                    // 4096 floats
    float* s_z      = sm + SM_DW + 4096;             // CCH*64 raw floats

    const float* gS = search + (size_t)b * NC * NHW;
    const float* gZ = kern   + (size_t)b * NC * NP;

    const int pg  = warp >> 2;          // 8 p-groups
    const int pxq = warp & 3;           // 4 px-quarters
    const int pb  = pg * 8;
    const int pxb = pxq * 64 + lane * 2;

    u64 cacc[4][2];
#pragma unroll
    for (int j = 0; j < 4; j++) { cacc[j][0] = 0ull; cacc[j][1] = 0ull; }

    for (int c0 = 0; c0 < NC; c0 += CCH) {
        __syncthreads();
        const float4* src4 = (const float4*)(gS + c0 * NHW);
        float4* dst4 = (float4*)s_search;
#pragma unroll
        for (int i = tid; i < CCH * NHW / 4; i += NT) dst4[i] = src4[i];
        const float* zsrc = gZ + c0 * NP;
#pragma unroll
        for (int i = tid; i < CCH * NP; i += NT) s_z[i] = zsrc[i];
        __syncthreads();

#pragma unroll 4
        for (int cc = 0; cc < CCH; cc++) {
            const float* zp = s_z + cc * NP + pb;
            ulonglong2 zA = *(const ulonglong2*)zp;       // native (p,p+1) pairs
            ulonglong2 zB = *(const ulonglong2*)(zp + 4);
            u64 zr[4] = {zA.x, zA.y, zB.x, zB.y};
            u64 xp = *(const u64*)(s_search + cc * NHW + pxb);
            float x0, x1; up2(xp, x0, x1);
            u64 xd0 = pk2(x0, x0), xd1 = pk2(x1, x1);
#pragma unroll
            for (int j = 0; j < 4; j++) {
                fma2(cacc[j][0], zr[j], xd0);
                fma2(cacc[j][1], zr[j], xd1);
            }
        }
    }

    // store corr
#pragma unroll
    for (int j = 0; j < 4; j++) {
#pragma unroll
        for (int q = 0; q < 2; q++) {
            float a0, a1; up2(cacc[j][q], a0, a1);
            s_corr[(pb + 2 * j)     * NHW + pxb + q] = a0;
            s_corr[(pb + 2 * j + 1) * NHW + pxb + q] = a1;
        }
    }
    __syncthreads();

    // per-p means: warp handles 2 p's
    {
        const int p0 = warp * 2;
#pragma unroll
        for (int j = 0; j < 2; j++) {
            const int p = p0 + j;
            float ps = 0.0f;
#pragma unroll
            for (int i = 0; i < 8; i++) ps += s_corr[p * NHW + lane + 32 * i];
#pragma unroll
            for (int o = 16; o > 0; o >>= 1) ps += __shfl_xor_sync(0xffffffffu, ps, o);
            if (lane == 0) s_att[p] = ps * (1.0f / 256.0f);
        }
    }
    __syncthreads();

    // ===== Phase B: channel-attention MLP =====
    if (tid < 64) {
        float s1 = ca_b1[tid];
        const float* w = ca_w1 + tid * 64;
#pragma unroll 8
        for (int j = 0; j < 64; j++) s1 = fmaf(w[j], s_att[j], s1);
        s_h[tid] = fmaxf(s1, 0.0f);
    }
    __syncthreads();
    if (tid < 64) {
        float s2 = ca_b2[tid];
        const float* w = ca_w2 + tid * 64;
#pragma unroll 8
        for (int j = 0; j < 64; j++) s2 = fmaf(w[j], s_h[j], s2);
        s_a[tid] = 1.0f / (1.0f + expf(-s2));
    }
    __syncthreads();

    // ===== cls tower =====
    {
        u64 Sc[5];
#pragma unroll
        for (int i = 0; i < 5; i++) Sc[i] = 0ull;
        tower<1, 5>(sm, tid, lane, warp, cls_dw, cls_pw,
                    cls_bng, cls_bnb, cls_bnm, cls_bnv, cls_predw, Sc);

        // write cls tap-sum partials: s_dw[(grp*9+k)*256 + px], grp = c-quarter
        {
            const int px = tid & 255, grp = tid >> 8;
            float* dst = sm + SM_DW;
#pragma unroll
            for (int kp = 0; kp < 4; kp++) {
                float a0, a1; up2(Sc[kp], a0, a1);
                dst[(grp * 9 + 2 * kp) * 256 + px]     = a0;
                dst[(grp * 9 + 2 * kp + 1) * 256 + px] = a1;
            }
            float a0, a1; up2(Sc[4], a0, a1);
            dst[(grp * 9 + 8) * 256 + px] = a0;
        }
        __syncthreads();

        // masked 9-tap gather over 4 groups -> s_clso
        if (tid < 256) {
            const int px = tid, y = px >> 4, x = px & 15;
            const float* dst = sm + SM_DW;
            float acc = 0.0f;
#pragma unroll
            for (int dy = -1; dy <= 1; dy++) {
                if (y + dy < 0 || y + dy > 15) continue;
#pragma unroll
                for (int dx = -1; dx <= 1; dx++) {
                    if (x + dx < 0 || x + dx > 15) continue;
                    const int k = (dy + 1) * 3 + (dx + 1);
                    const int q = px + dy * 16 + dx;
                    acc += dst[(k)      * 256 + q] + dst[(9 + k)  * 256 + q]
                         + dst[(18 + k) * 256 + q] + dst[(27 + k) * 256 + q];
                }
            }
            s_clso[px] = acc;
        }
        __syncthreads();
    }

    // ===== box tower =====
    u64 Sb[9];
#pragma unroll
    for (int i = 0; i < 9; i++) Sb[i] = 0ull;
    tower<4, 9>(sm, tid, lane, warp, box_dw, box_pw,
                box_bng, box_bnb, box_bnm, box_bnv, box_predw, Sb);

    // write box tap-sum partials: [k][px][4oc]; ch selects buffer, op selects u64 half
    {
        const int px = tid & 255, grp = tid >> 8;
        const int ch = grp & 1, op = grp >> 1;
        float* dst = (ch == 0) ? (sm + SM_DW) : (sm + SM_CORR);
#pragma unroll
        for (int k = 0; k < 9; k++)
            *(u64*)(dst + (k * 256 + px) * 4 + op * 2) = Sb[k];
    }
    __syncthreads();

    // ===== epilogue: masked box gather + stores (thread = pixel) =====
    if (tid < 256) {
        const int px = tid, y = px >> 4, x = px & 15;
        out[(size_t)NB * 4 * NHW + (size_t)b * NHW + px] =
            0.1f * (s_clso[px] + cls_predb[0]);

        float bx0 = 0.0f, bx1 = 0.0f, bx2 = 0.0f, bx3 = 0.0f;
        const float* d0 = sm + SM_DW;
        const float* d1 = sm + SM_CORR;
#pragma unroll
        for (int dy = -1; dy <= 1; dy++) {
            if (y + dy < 0 || y + dy > 15) continue;
#pragma unroll
            for (int dx = -1; dx <= 1; dx++) {
                if (x + dx < 0 || x + dx > 15) continue;
                const int k = (dy + 1) * 3 + (dx + 1);
                const int q = (k * 256 + px + dy * 16 + dx) * 4;
                float4 v0 = *(const float4*)(d0 + q);
                float4 v1 = *(const float4*)(d1 + q);
                bx0 += v0.x + v1.x; bx1 += v0.y + v1.y;
                bx2 += v0.z + v1.z; bx3 += v0.w + v1.w;
            }
        }
        const float adj = adjust[0];
        out[((size_t)b * 4 + 0) * NHW + px] = expf(adj * (bx0 + box_predb[0]) + biasp[0]);
        out[((size_t)b * 4 + 1) * NHW + px] = expf(adj * (bx1 + box_predb[1]) + biasp[1]);
        out[((size_t)b * 4 + 2) * NHW + px] = expf(adj * (bx2 + box_predb[2]) + biasp[2]);
        out[((size_t)b * 4 + 3) * NHW + px] = expf(adj * (bx3 + box_predb[3]) + biasp[3]);
    }
}

extern "C" void kernel_launch(void* const* d_in, const int* in_sizes, int n_in,
                              void* d_out, int out_size)
{
    const float* search    = (const float*)d_in[0];
    const float* kern      = (const float*)d_in[1];
    const float* ca_w1     = (const float*)d_in[2];
    const float* ca_b1     = (const float*)d_in[3];
    const float* ca_w2     = (const float*)d_in[4];
    const float* ca_b2     = (const float*)d_in[5];
    const float* cls_dw    = (const float*)d_in[6];
    const float* cls_pw    = (const float*)d_in[7];
    const float* cls_bng   = (const float*)d_in[8];
    const float* cls_bnb   = (const float*)d_in[9];
    const float* cls_bnm   = (const float*)d_in[10];
    const float* cls_bnv   = (const float*)d_in[11];
    const float* cls_predw = (const float*)d_in[12];
    const float* cls_predb = (const float*)d_in[13];
    const float* box_dw    = (const float*)d_in[14];
    const float* box_pw    = (const float*)d_in[15];
    const float* box_bng   = (const float*)d_in[16];
    const float* box_bnb   = (const float*)d_in[17];
    const float* box_bnm   = (const float*)d_in[18];
    const float* box_bnv   = (const float*)d_in[19];
    const float* box_predw = (const float*)d_in[20];
    const float* box_predb = (const float*)d_in[21];
    const float* adjust    = (const float*)d_in[22];
    const float* biasp     = (const float*)d_in[23];

    const int smbytes = SM_TOTF * 4;  // 229376 B
    cudaFuncSetAttribute(btl_kernel, cudaFuncAttributeMaxDynamicSharedMemorySize, smbytes);

    btl_kernel<<<NB, NT, smbytes>>>(
        search, kern, ca_w1, ca_b1, ca_w2, ca_b2,
        cls_dw, cls_pw, cls_bng, cls_bnb, cls_bnm, cls_bnv, cls_predw, cls_predb,
        box_dw, box_pw, box_bng, box_bnb, box_bnm, box_bnv, box_predw, box_predb,
        adjust, biasp, (float*)d_out);
}

// round 8
// speedup vs baseline: 1.8338x; 1.1267x over previous
#include <cuda_runtime.h>
#include <math.h>

#define NB   512
#define NC   112
#define NP   64
#define NHW  256
#define NOC  256
#define CCH  16
#define NT   1024   // 32 warps
#define PWS  68     // padded pwt row stride (272B = 17*16B: .128-aligned, 4-way max conflict)

typedef unsigned long long u64;

// ---- f32x2 helpers ----
__device__ __forceinline__ u64 pk2(float lo, float hi) {
    u64 r; asm("mov.b64 %0, {%1,%2};" : "=l"(r) : "f"(lo), "f"(hi)); return r;
}
__device__ __forceinline__ void up2(u64 v, float& a, float& b) {
    asm("mov.b64 {%0,%1}, %2;" : "=f"(a), "=f"(b) : "l"(v));
}
__device__ __forceinline__ void fma2(u64& d, u64 a, u64 b) {
    asm("fma.rn.f32x2 %0, %1, %2, %0;" : "+l"(d) : "l"(a), "l"(b));
}

// ---- shared memory layout (float index). total 57600 floats = 230400 B ----
#define SM_MISC 0        // 4096
#define SM_CORR 4096     // 64*256
#define SM_DW   20480    // 64*256
#define SM_FT   36864    // 64*256 (corr phase: 2x 5120-float staging buffers)
#define SM_PWT  53248    // 64*68 = 4352
#define SM_TOTF 57600

#define MS_ATT   0      // 64
#define MS_H     64     // 64
#define MS_A     128    // 64
#define MS_DWW   192    // 576
#define MS_BNSC  768    // 256
#define MS_BNSH  1024   // 256
#define MS_WP    1280   // 2560 (box) / 768 (cls)
#define MS_CLSO  3840   // 256

// One tower. Tap-sum partials S per thread:
// NPRED==1: grp = c-quarter. S[5]: k-pairs.
// NPRED==4: grp = (ch, op). S[9]: S[k] = (oc_lo, oc_hi) pair.
template<int NPRED, int NS>
__device__ __forceinline__ void tower(
    float* sm, int tid, int lane, int warp,
    const float* __restrict__ dwW, const float* __restrict__ pwW,
    const float* __restrict__ bng, const float* __restrict__ bnb,
    const float* __restrict__ bnm, const float* __restrict__ bnv,
    const float* __restrict__ predW, u64 (&S)[NS])
{
    float* s_a    = sm + MS_A;
    float* s_dww  = sm + MS_DWW;
    float* s_bnsc = sm + MS_BNSC;
    float* s_bnsh = sm + MS_BNSH;
    float* s_wp   = sm + MS_WP;
    float* s_corr = sm + SM_CORR;
    float* s_dw   = sm + SM_DW;
    float* s_ft   = sm + SM_FT;
    float* s_pwt  = sm + SM_PWT;

    // prefetch pwt tile 0 into registers (hidden under dw phase)
    float pw_pre[4];
#pragma unroll
    for (int j = 0; j < 4; j++) pw_pre[j] = pwW[tid + j * 1024];

    // stage depthwise weights + folded BN affine
    for (int i = tid; i < NP * 9; i += NT) s_dww[i] = dwW[i];
    if (tid < NOC) {
        float sc = bng[tid] * rsqrtf(bnv[tid] + 1e-5f);
        s_bnsc[tid] = sc;
        s_bnsh[tid] = bnb[tid] - bnm[tid] * sc;
    }
    __syncthreads();

    // ---- depthwise 3x3 (+attention fold). p-quarter x 256 px ----
    {
        const int px = tid & 255, pq = tid >> 8;
        const int y = px >> 4, x = px & 15;
        const bool okU = y > 0, okD = y < 15, okL = x > 0, okR = x < 15;
#pragma unroll 4
        for (int pi = 0; pi < 16; pi++) {
            const int p = pq * 16 + pi;
            const float* r = s_corr + p * NHW + px;
            const float* w = s_dww + p * 9;
            float acc = r[0] * w[4];
            if (okU) { acc = fmaf(r[-16], w[1], acc);
                       if (okL) acc = fmaf(r[-17], w[0], acc);
                       if (okR) acc = fmaf(r[-15], w[2], acc); }
            if (okD) { acc = fmaf(r[16], w[7], acc);
                       if (okL) acc = fmaf(r[15], w[6], acc);
                       if (okR) acc = fmaf(r[17], w[8], acc); }
            if (okL) acc = fmaf(r[-1], w[3], acc);
            if (okR) acc = fmaf(r[1],  w[5], acc);
            s_dw[p * NHW + px] = acc * s_a[p];
        }
    }
    __syncthreads();

    const int og  = warp >> 2;          // 8 o-groups of 8 o (4 native pairs)
    const int pxq = warp & 3;           // 4 px-quarters of 64 px
    const int ob  = og * 8;
    const int pxb = pxq * 64 + lane * 2;

#pragma unroll 1
    for (int ot = 0; ot < 4; ot++) {
        // STS prefetched pwt (k-consecutive lanes, stride PWS -> 4-way max)
#pragma unroll
        for (int j = 0; j < 4; j++) {
            int idx = tid + j * 1024;
            int o = idx >> 6, k = idx & 63;
            s_pwt[k * PWS + o] = pw_pre[j];
        }
        // stage pred-conv weights (linear STS, conflict-free)
        if (NPRED == 4) {
            for (int i = tid; i < 64 * 2 * 20; i += NT) {
                int c = i / 40, r = i % 40, op = r / 20, t = r % 20;
                float v = 0.0f;
                if (t < 18) {
                    int k = t >> 1, h = t & 1;
                    v = predW[(op * 2 + h) * 2304 + (ot * 64 + c) * 9 + k];
                }
                s_wp[i] = v;
            }
        } else {
            for (int i = tid; i < 768; i += NT) {
                int c = i / 12, k = i % 12;
                s_wp[i] = (k < 9) ? predW[(ot * 64 + c) * 9 + k] : 0.0f;
            }
        }
        __syncthreads();

        // issue LDG prefetch for next pwt tile (hidden under GEMM)
        if (ot < 3) {
#pragma unroll
            for (int j = 0; j < 4; j++)
                pw_pre[j] = pwW[(ot + 1) * 4096 + tid + j * 1024];
        }

        // ---- pointwise GEMM: warp tile 8o(4 native pairs) x 64px, K=64 ----
        u64 acc[4][2];
#pragma unroll
        for (int j = 0; j < 4; j++) { acc[j][0] = 0ull; acc[j][1] = 0ull; }

#pragma unroll 4
        for (int k = 0; k < 64; k++) {
            const float* wp = s_pwt + k * PWS + ob;
            ulonglong2 wA = *(const ulonglong2*)wp;        // native (o,o+1) pairs
            ulonglong2 wB = *(const ulonglong2*)(wp + 4);
            u64 wr[4] = {wA.x, wA.y, wB.x, wB.y};
            u64 xp = *(const u64*)(s_dw + k * NHW + pxb);
            float x0, x1; up2(xp, x0, x1);
            u64 xd0 = pk2(x0, x0), xd1 = pk2(x1, x1);
#pragma unroll
            for (int j = 0; j < 4; j++) {
                fma2(acc[j][0], wr[j], xd0);
                fma2(acc[j][1], wr[j], xd1);
            }
        }

        // BN + ReLU -> s_ft, repacked to coalesced STS.64
#pragma unroll
        for (int j = 0; j < 4; j++) {
            const int o = ot * 64 + ob + 2 * j;
            const float sc0 = s_bnsc[o],     sh0 = s_bnsh[o];
            const float sc1 = s_bnsc[o + 1], sh1 = s_bnsh[o + 1];
            float a00, a01, a10, a11;
            up2(acc[j][0], a00, a01);      // px0: (o0, o1)
            up2(acc[j][1], a10, a11);      // px1: (o0, o1)
            a00 = fmaxf(fmaf(a00, sc0, sh0), 0.0f);
            a10 = fmaxf(fmaf(a10, sc0, sh0), 0.0f);
            a01 = fmaxf(fmaf(a01, sc1, sh1), 0.0f);
            a11 = fmaxf(fmaf(a11, sc1, sh1), 0.0f);
            *(u64*)(s_ft + (ob + 2 * j)     * NHW + pxb) = pk2(a00, a10);
            *(u64*)(s_ft + (ob + 2 * j + 1) * NHW + pxb) = pk2(a01, a11);
        }
        __syncthreads();

        // ---- tap-sum accumulation (no neighbor gather) ----
        {
            const int px = tid & 255, grp = tid >> 8;
            if (NPRED == 4) {
                const int ch = grp & 1, op = grp >> 1;
#pragma unroll 2
                for (int ci = 0; ci < 32; ci++) {
                    const int c = ch * 32 + ci;
                    const float xv = s_ft[c * NHW + px];
                    const u64 xd = pk2(xv, xv);
                    const float* wb = s_wp + (c * 2 + op) * 20;
                    const ulonglong2* w2 = (const ulonglong2*)wb;
                    ulonglong2 wa = w2[0], wc = w2[1], wd = w2[2], we = w2[3];
                    u64 w8 = *(const u64*)(wb + 16);
                    fma2(S[0], xd, wa.x); fma2(S[1], xd, wa.y);
                    fma2(S[2], xd, wc.x); fma2(S[3], xd, wc.y);
                    fma2(S[4], xd, wd.x); fma2(S[5], xd, wd.y);
                    fma2(S[6], xd, we.x); fma2(S[7], xd, we.y);
                    fma2(S[8], xd, w8);
                }
            } else {
                const int cq = grp;
#pragma unroll 2
                for (int ci = 0; ci < 16; ci++) {
                    const int c = cq * 16 + ci;
                    const float xv = s_ft[c * NHW + px];
                    const u64 xd = pk2(xv, xv);
                    const ulonglong2* wp2 = (const ulonglong2*)(s_wp + c * 12);
                    ulonglong2 wA = wp2[0];
                    ulonglong2 wB = wp2[1];
                    float w8 = s_wp[c * 12 + 8];
                    fma2(S[0], xd, wA.x);
                    fma2(S[1], xd, wA.y);
                    fma2(S[2], xd, wB.x);
                    fma2(S[3], xd, wB.y);
                    fma2(S[4], xd, pk2(w8, 0.0f));
                }
            }
        }
        __syncthreads();
    }
}

__global__ void __launch_bounds__(NT, 1)
btl_kernel(
    const float* __restrict__ search, const float* __restrict__ kern,
    const float* __restrict__ ca_w1, const float* __restrict__ ca_b1,
    const float* __restrict__ ca_w2, const float* __restrict__ ca_b2,
    const float* __restrict__ cls_dw, const float* __restrict__ cls_pw,
    const float* __restrict__ cls_bng, const float* __restrict__ cls_bnb,
    const float* __restrict__ cls_bnm, const float* __restrict__ cls_bnv,
    const float* __restrict__ cls_predw, const float* __restrict__ cls_predb,
    const float* __restrict__ box_dw, const float* __restrict__ box_pw,
    const float* __restrict__ box_bng, const float* __restrict__ box_bnb,
    const float* __restrict__ box_bnm, const float* __restrict__ box_bnv,
    const float* __restrict__ box_predw, const float* __restrict__ box_predb,
    const float* __restrict__ adjust, const float* __restrict__ biasp,
    float* __restrict__ out)
{
    extern __shared__ float sm[];
    const int tid  = threadIdx.x;
    const int lane = tid & 31;
    const int warp = tid >> 5;
    const int b    = blockIdx.x;

    float* s_att  = sm + MS_ATT;
    float* s_h    = sm + MS_H;
    float* s_a    = sm + MS_A;
    float* s_clso = sm + MS_CLSO;
    float* s_corr = sm + SM_CORR;

    // ===== Phase A: correlation GEMM corr[64p x 256px], K=112 =====
    // double-buffered chunk staging in the (idle) FT region, 1 bar/chunk
    float* bufA = sm + SM_FT;          // search 4096 + z 1024 floats
    float* bufB = sm + SM_FT + 5120;

    const float* gS = search + (size_t)b * NC * NHW;
    const float* gZ = kern   + (size_t)b * NC * NP;

    const int pg  = warp >> 2;
    const int pxq = warp & 3;
    const int pb  = pg * 8;
    const int pxb = pxq * 64 + lane * 2;

    u64 cacc[4][2];
#pragma unroll
    for (int j = 0; j < 4; j++) { cacc[j][0] = 0ull; cacc[j][1] = 0ull; }

    // stage chunk 0 (one float4 + one z float per thread)
    ((float4*)bufA)[tid] = ((const float4*)gS)[tid];
    bufA[4096 + tid] = gZ[tid];
    __syncthreads();

    int sbsel = 0;
    for (int chk = 0; chk < 7; chk++) {
        // prefetch next chunk (issued before compute; latency hidden)
        float4 pre4; float prez;
        if (chk < 6) {
            pre4 = ((const float4*)(gS + (chk + 1) * CCH * NHW))[tid];
            prez = (gZ + (chk + 1) * CCH * NP)[tid];
        }
        const float* sbuf = sbsel ? bufB : bufA;
        const float* szb  = sbuf + 4096;

#pragma unroll 4
        for (int cc = 0; cc < CCH; cc++) {
            const float* zp = szb + cc * NP + pb;
            ulonglong2 zA = *(const ulonglong2*)zp;       // native (p,p+1) pairs
            ulonglong2 zB = *(const ulonglong2*)(zp + 4);
            u64 zr[4] = {zA.x, zA.y, zB.x, zB.y};
            u64 xp = *(const u64*)(sbuf + cc * NHW + pxb);
            float x0, x1; up2(xp, x0, x1);
            u64 xd0 = pk2(x0, x0), xd1 = pk2(x1, x1);
#pragma unroll
            for (int j = 0; j < 4; j++) {
                fma2(cacc[j][0], zr[j], xd0);
                fma2(cacc[j][1], zr[j], xd1);
            }
        }
        if (chk < 6) {
            float* dbuf = sbsel ? bufA : bufB;
            ((float4*)dbuf)[tid] = pre4;
            dbuf[4096 + tid] = prez;
        }
        __syncthreads();
        sbsel ^= 1;
    }

    // store corr (coalesced STS.64 via register repack)
#pragma unroll
    for (int j = 0; j < 4; j++) {
        float a00, a01, a10, a11;
        up2(cacc[j][0], a00, a01);   // px0: (p0,p1)
        up2(cacc[j][1], a10, a11);   // px1: (p0,p1)
        *(u64*)(s_corr + (pb + 2 * j)     * NHW + pxb) = pk2(a00, a10);
        *(u64*)(s_corr + (pb + 2 * j + 1) * NHW + pxb) = pk2(a01, a11);
    }
    __syncthreads();

    // per-p means
    {
        const int p0 = warp * 2;
#pragma unroll
        for (int j = 0; j < 2; j++) {
            const int p = p0 + j;
            float ps = 0.0f;
#pragma unroll
            for (int i = 0; i < 8; i++) ps += s_corr[p * NHW + lane + 32 * i];
#pragma unroll
            for (int o = 16; o > 0; o >>= 1) ps += __shfl_xor_sync(0xffffffffu, ps, o);
            if (lane == 0) s_att[p] = ps * (1.0f / 256.0f);
        }
    }
    __syncthreads();

    // ===== Phase B: channel-attention MLP =====
    if (tid < 64) {
        float s1 = ca_b1[tid];
        const float* w = ca_w1 + tid * 64;
#pragma unroll 8
        for (int j = 0; j < 64; j++) s1 = fmaf(w[j], s_att[j], s1);
        s_h[tid] = fmaxf(s1, 0.0f);
    }
    __syncthreads();
    if (tid < 64) {
        float s2 = ca_b2[tid];
        const float* w = ca_w2 + tid * 64;
#pragma unroll 8
        for (int j = 0; j < 64; j++) s2 = fmaf(w[j], s_h[j], s2);
        s_a[tid] = 1.0f / (1.0f + expf(-s2));
    }
    __syncthreads();

    // ===== cls tower =====
    {
        u64 Sc[5];
#pragma unroll
        for (int i = 0; i < 5; i++) Sc[i] = 0ull;
        tower<1, 5>(sm, tid, lane, warp, cls_dw, cls_pw,
                    cls_bng, cls_bnb, cls_bnm, cls_bnv, cls_predw, Sc);

        // write cls tap partials: s_dw[(grp*9+k)*256 + px]
        {
            const int px = tid & 255, grp = tid >> 8;
            float* dst = sm + SM_DW;
#pragma unroll
            for (int kp = 0; kp < 4; kp++) {
                float a0, a1; up2(Sc[kp], a0, a1);
                dst[(grp * 9 + 2 * kp) * 256 + px]     = a0;
                dst[(grp * 9 + 2 * kp + 1) * 256 + px] = a1;
            }
            float a0, a1; up2(Sc[4], a0, a1);
            dst[(grp * 9 + 8) * 256 + px] = a0;
        }
        __syncthreads();

        // masked 9-tap gather over 4 groups -> s_clso
        if (tid < 256) {
            const int px = tid, y = px >> 4, x = px & 15;
            const float* dst = sm + SM_DW;
            float acc = 0.0f;
#pragma unroll
            for (int dy = -1; dy <= 1; dy++) {
                if (y + dy < 0 || y + dy > 15) continue;
#pragma unroll
                for (int dx = -1; dx <= 1; dx++) {
                    if (x + dx < 0 || x + dx > 15) continue;
                    const int k = (dy + 1) * 3 + (dx + 1);
                    const int q = px + dy * 16 + dx;
                    acc += dst[(k)      * 256 + q] + dst[(9 + k)  * 256 + q]
                         + dst[(18 + k) * 256 + q] + dst[(27 + k) * 256 + q];
                }
            }
            s_clso[px] = acc;
        }
        __syncthreads();
    }

    // ===== box tower =====
    u64 Sb[9];
#pragma unroll
    for (int i = 0; i < 9; i++) Sb[i] = 0ull;
    tower<4, 9>(sm, tid, lane, warp, box_dw, box_pw,
                box_bng, box_bnb, box_bnm, box_bnv, box_predw, Sb);

    // write box tap partials: [k][px][4oc]; ch selects buffer, op selects u64 half
    {
        const int px = tid & 255, grp = tid >> 8;
        const int ch = grp & 1, op = grp >> 1;
        float* dst = (ch == 0) ? (sm + SM_DW) : (sm + SM_CORR);
#pragma unroll
        for (int k = 0; k < 9; k++)
            *(u64*)(dst + (k * 256 + px) * 4 + op * 2) = Sb[k];
    }
    __syncthreads();

    // ===== epilogue: masked box gather + stores (thread = pixel) =====
    if (tid < 256) {
        const int px = tid, y = px >> 4, x = px & 15;
        out[(size_t)NB * 4 * NHW + (size_t)b * NHW + px] =
            0.1f * (s_clso[px] + cls_predb[0]);

        float bx0 = 0.0f, bx1 = 0.0f, bx2 = 0.0f, bx3 = 0.0f;
        const float* d0 = sm + SM_DW;
        const float* d1 = sm + SM_CORR;
#pragma unroll
        for (int dy = -1; dy <= 1; dy++) {
            if (y + dy < 0 || y + dy > 15) continue;
#pragma unroll
            for (int dx = -1; dx <= 1; dx++) {
                if (x + dx < 0 || x + dx > 15) continue;
                const int k = (dy + 1) * 3 + (dx + 1);
                const int q = (k * 256 + px + dy * 16 + dx) * 4;
                float4 v0 = *(const float4*)(d0 + q);
                float4 v1 = *(const float4*)(d1 + q);
                bx0 += v0.x + v1.x; bx1 += v0.y + v1.y;
                bx2 += v0.z + v1.z; bx3 += v0.w + v1.w;
            }
        }
        const float adj = adjust[0];
        out[((size_t)b * 4 + 0) * NHW + px] = expf(adj * (bx0 + box_predb[0]) + biasp[0]);
        out[((size_t)b * 4 + 1) * NHW + px] = expf(adj * (bx1 + box_predb[1]) + biasp[1]);
        out[((size_t)b * 4 + 2) * NHW + px] = expf(adj * (bx2 + box_predb[2]) + biasp[2]);
        out[((size_t)b * 4 + 3) * NHW + px] = expf(adj * (bx3 + box_predb[3]) + biasp[3]);
    }
}

extern "C" void kernel_launch(void* const* d_in, const int* in_sizes, int n_in,
                              void* d_out, int out_size)
{
    const float* search    = (const float*)d_in[0];
    const float* kern      = (const float*)d_in[1];
    const float* ca_w1     = (const float*)d_in[2];
    const float* ca_b1     = (const float*)d_in[3];
    const float* ca_w2     = (const float*)d_in[4];
    const float* ca_b2     = (const float*)d_in[5];
    const float* cls_dw    = (const float*)d_in[6];
    const float* cls_pw    = (const float*)d_in[7];
    const float* cls_bng   = (const float*)d_in[8];
    const float* cls_bnb   = (const float*)d_in[9];
    const float* cls_bnm   = (const float*)d_in[10];
    const float* cls_bnv   = (const float*)d_in[11];
    const float* cls_predw = (const float*)d_in[12];
    const float* cls_predb = (const float*)d_in[13];
    const float* box_dw    = (const float*)d_in[14];
    const float* box_pw    = (const float*)d_in[15];
    const float* box_bng   = (const float*)d_in[16];
    const float* box_bnb   = (const float*)d_in[17];
    const float* box_bnm   = (const float*)d_in[18];
    const float* box_bnv   = (const float*)d_in[19];
    const float* box_predw = (const float*)d_in[20];
    const float* box_predb = (const float*)d_in[21];
    const float* adjust    = (const float*)d_in[22];
    const float* biasp     = (const float*)d_in[23];

    const int smbytes = SM_TOTF * 4;  // 230400 B
    cudaFuncSetAttribute(btl_kernel, cudaFuncAttributeMaxDynamicSharedMemorySize, smbytes);

    btl_kernel<<<NB, NT, smbytes>>>(
        search, kern, ca_w1, ca_b1, ca_w2, ca_b2,
        cls_dw, cls_pw, cls_bng, cls_bnb, cls_bnm, cls_bnv, cls_predw, cls_predb,
        box_dw, box_pw, box_bng, box_bnb, box_bnm, box_bnv, box_predw, box_predb,
        adjust, biasp, (float*)d_out);
}

// round 9
// speedup vs baseline: 1.8358x; 1.0011x over previous
#include <cuda_runtime.h>
#include <math.h>

#define NB   512
#define NC   112
#define NP   64
#define NHW  256
#define NOC  256
#define CCH  16
#define NT   1024   // 32 warps
#define PWS  68     // padded pwt row stride (272B = 17*16B: .128-aligned, 4-way max conflict)

typedef unsigned long long u64;

// ---- f32x2 helpers ----
__device__ __forceinline__ u64 pk2(float lo, float hi) {
    u64 r; asm("mov.b64 %0, {%1,%2};" : "=l"(r) : "f"(lo), "f"(hi)); return r;
}
__device__ __forceinline__ void up2(u64 v, float& a, float& b) {
    asm("mov.b64 {%0,%1}, %2;" : "=f"(a), "=f"(b) : "l"(v));
}
__device__ __forceinline__ void fma2(u64& d, u64 a, u64 b) {
    asm("fma.rn.f32x2 %0, %1, %2, %0;" : "+l"(d) : "l"(a), "l"(b));
}

// ---- shared memory layout (float index). total 57600 floats = 230400 B ----
#define SM_MISC 0        // 4096
#define SM_CORR 4096     // 64*256
#define SM_DW   20480    // 64*256
#define SM_FT   36864    // 64*256 (corr phase: 2x 5120-float staging buffers)
#define SM_PWT  53248    // 64*68 = 4352
#define SM_TOTF 57600

#define MS_ATT   0      // 64
#define MS_H     64     // 64
#define MS_A     128    // 64
#define MS_DWW   192    // 576
#define MS_BNSC  768    // 256
#define MS_BNSH  1024   // 256
#define MS_WP    1280   // 2560 (box) / 768 (cls)
#define MS_CLSO  3840   // 256

// One tower. Tap-sum partials S per thread:
// NPRED==1: grp = c-quarter. S[5]: k-pairs.
// NPRED==4: grp = (ch, op). S[9]: S[k] = (oc_lo, oc_hi) pair.
template<int NPRED, int NS>
__device__ __forceinline__ void tower(
    float* sm, int tid, int lane, int warp,
    const float* __restrict__ dwW, const float* __restrict__ pwW,
    const float* __restrict__ bng, const float* __restrict__ bnb,
    const float* __restrict__ bnm, const float* __restrict__ bnv,
    const float* __restrict__ predW, u64 (&S)[NS])
{
    float* s_a    = sm + MS_A;
    float* s_dww  = sm + MS_DWW;
    float* s_bnsc = sm + MS_BNSC;
    float* s_bnsh = sm + MS_BNSH;
    float* s_wp   = sm + MS_WP;
    float* s_corr = sm + SM_CORR;
    float* s_dw   = sm + SM_DW;
    float* s_ft   = sm + SM_FT;
    float* s_pwt  = sm + SM_PWT;

    // prefetch pwt tile 0 into registers (hidden under dw phase)
    float pw_pre[4];
#pragma unroll
    for (int j = 0; j < 4; j++) pw_pre[j] = pwW[tid + j * 1024];

    // stage depthwise weights + folded BN affine
    for (int i = tid; i < NP * 9; i += NT) s_dww[i] = dwW[i];
    if (tid < NOC) {
        float sc = bng[tid] * rsqrtf(bnv[tid] + 1e-5f);
        s_bnsc[tid] = sc;
        s_bnsh[tid] = bnb[tid] - bnm[tid] * sc;
    }
    __syncthreads();

    // ---- depthwise 3x3 (+attention fold). p-quarter x 256 px ----
    {
        const int px = tid & 255, pq = tid >> 8;
        const int y = px >> 4, x = px & 15;
        const bool okU = y > 0, okD = y < 15, okL = x > 0, okR = x < 15;
#pragma unroll 4
        for (int pi = 0; pi < 16; pi++) {
            const int p = pq * 16 + pi;
            const float* r = s_corr + p * NHW + px;
            const float* w = s_dww + p * 9;
            float acc = r[0] * w[4];
            if (okU) { acc = fmaf(r[-16], w[1], acc);
                       if (okL) acc = fmaf(r[-17], w[0], acc);
                       if (okR) acc = fmaf(r[-15], w[2], acc); }
            if (okD) { acc = fmaf(r[16], w[7], acc);
                       if (okL) acc = fmaf(r[15], w[6], acc);
                       if (okR) acc = fmaf(r[17], w[8], acc); }
            if (okL) acc = fmaf(r[-1], w[3], acc);
            if (okR) acc = fmaf(r[1],  w[5], acc);
            s_dw[p * NHW + px] = acc * s_a[p];
        }
    }
    __syncthreads();

    const int og  = warp >> 2;          // 8 o-groups of 8 o (4 native pairs)
    const int pxq = warp & 3;           // 4 px-quarters of 64 px
    const int ob  = og * 8;
    const int pxb = pxq * 64 + lane * 2;

#pragma unroll 1
    for (int ot = 0; ot < 4; ot++) {
        // STS prefetched pwt (k-consecutive lanes, stride PWS -> 4-way max)
#pragma unroll
        for (int j = 0; j < 4; j++) {
            int idx = tid + j * 1024;
            int o = idx >> 6, k = idx & 63;
            s_pwt[k * PWS + o] = pw_pre[j];
        }
        // stage pred-conv weights (linear STS, conflict-free)
        if (NPRED == 4) {
            for (int i = tid; i < 64 * 2 * 20; i += NT) {
                int c = i / 40, r = i % 40, op = r / 20, t = r % 20;
                float v = 0.0f;
                if (t < 18) {
                    int k = t >> 1, h = t & 1;
                    v = predW[(op * 2 + h) * 2304 + (ot * 64 + c) * 9 + k];
                }
                s_wp[i] = v;
            }
        } else {
            for (int i = tid; i < 768; i += NT) {
                int c = i / 12, k = i % 12;
                s_wp[i] = (k < 9) ? predW[(ot * 64 + c) * 9 + k] : 0.0f;
            }
        }
        __syncthreads();

        // issue LDG prefetch for next pwt tile (hidden under GEMM)
        if (ot < 3) {
#pragma unroll
            for (int j = 0; j < 4; j++)
                pw_pre[j] = pwW[(ot + 1) * 4096 + tid + j * 1024];
        }

        // ---- pointwise GEMM: warp tile 8o(4 native pairs) x 64px, K=64 ----
        u64 acc[4][2];
#pragma unroll
        for (int j = 0; j < 4; j++) { acc[j][0] = 0ull; acc[j][1] = 0ull; }

#pragma unroll 4
        for (int k = 0; k < 64; k++) {
            const float* wp = s_pwt + k * PWS + ob;
            ulonglong2 wA = *(const ulonglong2*)wp;        // native (o,o+1) pairs
            ulonglong2 wB = *(const ulonglong2*)(wp + 4);
            u64 wr[4] = {wA.x, wA.y, wB.x, wB.y};
            u64 xp = *(const u64*)(s_dw + k * NHW + pxb);
            float x0, x1; up2(xp, x0, x1);
            u64 xd0 = pk2(x0, x0), xd1 = pk2(x1, x1);
#pragma unroll
            for (int j = 0; j < 4; j++) {
                fma2(acc[j][0], wr[j], xd0);
                fma2(acc[j][1], wr[j], xd1);
            }
        }

        // BN + ReLU -> s_ft, repacked to coalesced STS.64
#pragma unroll
        for (int j = 0; j < 4; j++) {
            const int o = ot * 64 + ob + 2 * j;
            const float sc0 = s_bnsc[o],     sh0 = s_bnsh[o];
            const float sc1 = s_bnsc[o + 1], sh1 = s_bnsh[o + 1];
            float a00, a01, a10, a11;
            up2(acc[j][0], a00, a01);      // px0: (o0, o1)
            up2(acc[j][1], a10, a11);      // px1: (o0, o1)
            a00 = fmaxf(fmaf(a00, sc0, sh0), 0.0f);
            a10 = fmaxf(fmaf(a10, sc0, sh0), 0.0f);
            a01 = fmaxf(fmaf(a01, sc1, sh1), 0.0f);
            a11 = fmaxf(fmaf(a11, sc1, sh1), 0.0f);
            *(u64*)(s_ft + (ob + 2 * j)     * NHW + pxb) = pk2(a00, a10);
            *(u64*)(s_ft + (ob + 2 * j + 1) * NHW + pxb) = pk2(a01, a11);
        }
        __syncthreads();

        // ---- tap-sum accumulation (no neighbor gather) ----
        {
            const int px = tid & 255, grp = tid >> 8;
            if (NPRED == 4) {
                const int ch = grp & 1, op = grp >> 1;
#pragma unroll 2
                for (int ci = 0; ci < 32; ci++) {
                    const int c = ch * 32 + ci;
                    const float xv = s_ft[c * NHW + px];
                    const u64 xd = pk2(xv, xv);
                    const float* wb = s_wp + (c * 2 + op) * 20;
                    const ulonglong2* w2 = (const ulonglong2*)wb;
                    ulonglong2 wa = w2[0], wc = w2[1], wd = w2[2], we = w2[3];
                    u64 w8 = *(const u64*)(wb + 16);
                    fma2(S[0], xd, wa.x); fma2(S[1], xd, wa.y);
                    fma2(S[2], xd, wc.x); fma2(S[3], xd, wc.y);
                    fma2(S[4], xd, wd.x); fma2(S[5], xd, wd.y);
                    fma2(S[6], xd, we.x); fma2(S[7], xd, we.y);
                    fma2(S[8], xd, w8);
                }
            } else {
                const int cq = grp;
#pragma unroll 2
                for (int ci = 0; ci < 16; ci++) {
                    const int c = cq * 16 + ci;
                    const float xv = s_ft[c * NHW + px];
                    const u64 xd = pk2(xv, xv);
                    const ulonglong2* wp2 = (const ulonglong2*)(s_wp + c * 12);
                    ulonglong2 wA = wp2[0];
                    ulonglong2 wB = wp2[1];
                    float w8 = s_wp[c * 12 + 8];
                    fma2(S[0], xd, wA.x);
                    fma2(S[1], xd, wA.y);
                    fma2(S[2], xd, wB.x);
                    fma2(S[3], xd, wB.y);
                    fma2(S[4], xd, pk2(w8, 0.0f));
                }
            }
        }
        __syncthreads();
    }
}

__global__ void __launch_bounds__(NT, 1)
btl_kernel(
    const float* __restrict__ search, const float* __restrict__ kern,
    const float* __restrict__ ca_w1, const float* __restrict__ ca_b1,
    const float* __restrict__ ca_w2, const float* __restrict__ ca_b2,
    const float* __restrict__ cls_dw, const float* __restrict__ cls_pw,
    const float* __restrict__ cls_bng, const float* __restrict__ cls_bnb,
    const float* __restrict__ cls_bnm, const float* __restrict__ cls_bnv,
    const float* __restrict__ cls_predw, const float* __restrict__ cls_predb,
    const float* __restrict__ box_dw, const float* __restrict__ box_pw,
    const float* __restrict__ box_bng, const float* __restrict__ box_bnb,
    const float* __restrict__ box_bnm, const float* __restrict__ box_bnv,
    const float* __restrict__ box_predw, const float* __restrict__ box_predb,
    const float* __restrict__ adjust, const float* __restrict__ biasp,
    float* __restrict__ out)
{
    extern __shared__ float sm[];
    const int tid  = threadIdx.x;
    const int lane = tid & 31;
    const int warp = tid >> 5;
    const int b    = blockIdx.x;

    float* s_att  = sm + MS_ATT;
    float* s_h    = sm + MS_H;
    float* s_a    = sm + MS_A;
    float* s_clso = sm + MS_CLSO;
    float* s_corr = sm + SM_CORR;

    // ===== Phase A: correlation GEMM corr[64p x 256px], K=112 =====
    // double-buffered chunk staging in the (idle) FT region, 1 bar/chunk
    float* bufA = sm + SM_FT;          // search 4096 + z 1024 floats
    float* bufB = sm + SM_FT + 5120;

    const float* gS = search + (size_t)b * NC * NHW;
    const float* gZ = kern   + (size_t)b * NC * NP;

    const int pg  = warp >> 2;
    const int pxq = warp & 3;
    const int pb  = pg * 8;
    const int pxb = pxq * 64 + lane * 2;

    u64 cacc[4][2];
#pragma unroll
    for (int j = 0; j < 4; j++) { cacc[j][0] = 0ull; cacc[j][1] = 0ull; }

    // stage chunk 0 (one float4 + one z float per thread)
    ((float4*)bufA)[tid] = ((const float4*)gS)[tid];
    bufA[4096 + tid] = gZ[tid];
    __syncthreads();

    int sbsel = 0;
    for (int chk = 0; chk < 7; chk++) {
        // prefetch next chunk (issued before compute; latency hidden)
        float4 pre4; float prez;
        if (chk < 6) {
            pre4 = ((const float4*)(gS + (chk + 1) * CCH * NHW))[tid];
            prez = (gZ + (chk + 1) * CCH * NP)[tid];
        }
        const float* sbuf = sbsel ? bufB : bufA;
        const float* szb  = sbuf + 4096;

#pragma unroll 4
        for (int cc = 0; cc < CCH; cc++) {
            const float* zp = szb + cc * NP + pb;
            ulonglong2 zA = *(const ulonglong2*)zp;       // native (p,p+1) pairs
            ulonglong2 zB = *(const ulonglong2*)(zp + 4);
            u64 zr[4] = {zA.x, zA.y, zB.x, zB.y};
            u64 xp = *(const u64*)(sbuf + cc * NHW + pxb);
            float x0, x1; up2(xp, x0, x1);
            u64 xd0 = pk2(x0, x0), xd1 = pk2(x1, x1);
#pragma unroll
            for (int j = 0; j < 4; j++) {
                fma2(cacc[j][0], zr[j], xd0);
                fma2(cacc[j][1], zr[j], xd1);
            }
        }
        if (chk < 6) {
            float* dbuf = sbsel ? bufA : bufB;
            ((float4*)dbuf)[tid] = pre4;
            dbuf[4096 + tid] = prez;
        }
        __syncthreads();
        sbsel ^= 1;
    }

    // store corr (coalesced STS.64 via register repack)
#pragma unroll
    for (int j = 0; j < 4; j++) {
        float a00, a01, a10, a11;
        up2(cacc[j][0], a00, a01);   // px0: (p0,p1)
        up2(cacc[j][1], a10, a11);   // px1: (p0,p1)
        *(u64*)(s_corr + (pb + 2 * j)     * NHW + pxb) = pk2(a00, a10);
        *(u64*)(s_corr + (pb + 2 * j + 1) * NHW + pxb) = pk2(a01, a11);
    }
    __syncthreads();

    // per-p means
    {
        const int p0 = warp * 2;
#pragma unroll
        for (int j = 0; j < 2; j++) {
            const int p = p0 + j;
            float ps = 0.0f;
#pragma unroll
            for (int i = 0; i < 8; i++) ps += s_corr[p * NHW + lane + 32 * i];
#pragma unroll
            for (int o = 16; o > 0; o >>= 1) ps += __shfl_xor_sync(0xffffffffu, ps, o);
            if (lane == 0) s_att[p] = ps * (1.0f / 256.0f);
        }
    }
    __syncthreads();

    // ===== Phase B: channel-attention MLP =====
    if (tid < 64) {
        float s1 = ca_b1[tid];
        const float* w = ca_w1 + tid * 64;
#pragma unroll 8
        for (int j = 0; j < 64; j++) s1 = fmaf(w[j], s_att[j], s1);
        s_h[tid] = fmaxf(s1, 0.0f);
    }
    __syncthreads();
    if (tid < 64) {
        float s2 = ca_b2[tid];
        const float* w = ca_w2 + tid * 64;
#pragma unroll 8
        for (int j = 0; j < 64; j++) s2 = fmaf(w[j], s_h[j], s2);
        s_a[tid] = 1.0f / (1.0f + expf(-s2));
    }
    __syncthreads();

    // ===== cls tower =====
    {
        u64 Sc[5];
#pragma unroll
        for (int i = 0; i < 5; i++) Sc[i] = 0ull;
        tower<1, 5>(sm, tid, lane, warp, cls_dw, cls_pw,
                    cls_bng, cls_bnb, cls_bnm, cls_bnv, cls_predw, Sc);

        // write cls tap partials: s_dw[(grp*9+k)*256 + px]
        {
            const int px = tid & 255, grp = tid >> 8;
            float* dst = sm + SM_DW;
#pragma unroll
            for (int kp = 0; kp < 4; kp++) {
                float a0, a1; up2(Sc[kp], a0, a1);
                dst[(grp * 9 + 2 * kp) * 256 + px]     = a0;
                dst[(grp * 9 + 2 * kp + 1) * 256 + px] = a1;
            }
            float a0, a1; up2(Sc[4], a0, a1);
            dst[(grp * 9 + 8) * 256 + px] = a0;
        }
        __syncthreads();

        // masked 9-tap gather over 4 groups -> s_clso
        if (tid < 256) {
            const int px = tid, y = px >> 4, x = px & 15;
            const float* dst = sm + SM_DW;
            float acc = 0.0f;
#pragma unroll
            for (int dy = -1; dy <= 1; dy++) {
                if (y + dy < 0 || y + dy > 15) continue;
#pragma unroll
                for (int dx = -1; dx <= 1; dx++) {
                    if (x + dx < 0 || x + dx > 15) continue;
                    const int k = (dy + 1) * 3 + (dx + 1);
                    const int q = px + dy * 16 + dx;
                    acc += dst[(k)      * 256 + q] + dst[(9 + k)  * 256 + q]
                         + dst[(18 + k) * 256 + q] + dst[(27 + k) * 256 + q];
                }
            }
            s_clso[px] = acc;
        }
        __syncthreads();
    }

    // ===== box tower =====
    u64 Sb[9];
#pragma unroll
    for (int i = 0; i < 9; i++) Sb[i] = 0ull;
    tower<4, 9>(sm, tid, lane, warp, box_dw, box_pw,
                box_bng, box_bnb, box_bnm, box_bnv, box_predw, Sb);

    // write box tap partials: [k][px][4oc]; ch selects buffer, op selects u64 half
    {
        const int px = tid & 255, grp = tid >> 8;
        const int ch = grp & 1, op = grp >> 1;
        float* dst = (ch == 0) ? (sm + SM_DW) : (sm + SM_CORR);
#pragma unroll
        for (int k = 0; k < 9; k++)
            *(u64*)(dst + (k * 256 + px) * 4 + op * 2) = Sb[k];
    }
    __syncthreads();

    // ===== epilogue: masked box gather + stores (thread = pixel) =====
    if (tid < 256) {
        const int px = tid, y = px >> 4, x = px & 15;
        out[(size_t)NB * 4 * NHW + (size_t)b * NHW + px] =
            0.1f * (s_clso[px] + cls_predb[0]);

        float bx0 = 0.0f, bx1 = 0.0f, bx2 = 0.0f, bx3 = 0.0f;
        const float* d0 = sm + SM_DW;
        const float* d1 = sm + SM_CORR;
#pragma unroll
        for (int dy = -1; dy <= 1; dy++) {
            if (y + dy < 0 || y + dy > 15) continue;
#pragma unroll
            for (int dx = -1; dx <= 1; dx++) {
                if (x + dx < 0 || x + dx > 15) continue;
                const int k = (dy + 1) * 3 + (dx + 1);
                const int q = (k * 256 + px + dy * 16 + dx) * 4;
                float4 v0 = *(const float4*)(d0 + q);
                float4 v1 = *(const float4*)(d1 + q);
                bx0 += v0.x + v1.x; bx1 += v0.y + v1.y;
                bx2 += v0.z + v1.z; bx3 += v0.w + v1.w;
            }
        }
        const float adj = adjust[0];
        out[((size_t)b * 4 + 0) * NHW + px] = expf(adj * (bx0 + box_predb[0]) + biasp[0]);
        out[((size_t)b * 4 + 1) * NHW + px] = expf(adj * (bx1 + box_predb[1]) + biasp[1]);
        out[((size_t)b * 4 + 2) * NHW + px] = expf(adj * (bx2 + box_predb[2]) + biasp[2]);
        out[((size_t)b * 4 + 3) * NHW + px] = expf(adj * (bx3 + box_predb[3]) + biasp[3]);
    }
}

extern "C" void kernel_launch(void* const* d_in, const int* in_sizes, int n_in,
                              void* d_out, int out_size)
{
    const float* search    = (const float*)d_in[0];
    const float* kern      = (const float*)d_in[1];
    const float* ca_w1     = (const float*)d_in[2];
    const float* ca_b1     = (const float*)d_in[3];
    const float* ca_w2     = (const float*)d_in[4];
    const float* ca_b2     = (const float*)d_in[5];
    const float* cls_dw    = (const float*)d_in[6];
    const float* cls_pw    = (const float*)d_in[7];
    const float* cls_bng   = (const float*)d_in[8];
    const float* cls_bnb   = (const float*)d_in[9];
    const float* cls_bnm   = (const float*)d_in[10];
    const float* cls_bnv   = (const float*)d_in[11];
    const float* cls_predw = (const float*)d_in[12];
    const float* cls_predb = (const float*)d_in[13];
    const float* box_dw    = (const float*)d_in[14];
    const float* box_pw    = (const float*)d_in[15];
    const float* box_bng   = (const float*)d_in[16];
    const float* box_bnb   = (const float*)d_in[17];
    const float* box_bnm   = (const float*)d_in[18];
    const float* box_bnv   = (const float*)d_in[19];
    const float* box_predw = (const float*)d_in[20];
    const float* box_predb = (const float*)d_in[21];
    const float* adjust    = (const float*)d_in[22];
    const float* biasp     = (const float*)d_in[23];

    const int smbytes = SM_TOTF * 4;  // 230400 B
    cudaFuncSetAttribute(btl_kernel, cudaFuncAttributeMaxDynamicSharedMemorySize, smbytes);

    btl_kernel<<<NB, NT, smbytes>>>(
        search, kern, ca_w1, ca_b1, ca_w2, ca_b2,
        cls_dw, cls_pw, cls_bng, cls_bnb, cls_bnm, cls_bnv, cls_predw, cls_predb,
        box_dw, box_pw, box_bng, box_bnb, box_bnm, box_bnv, box_predw, box_predb,
        adjust, biasp, (float*)d_out);
}

// round 10
// speedup vs baseline: 1.9245x; 1.0483x over previous
#include <cuda_runtime.h>
#include <cuda_fp16.h>
#include <math.h>

#define NB   512
#define NC   112
#define NP   64
#define NHW  256
#define NOC  256
#define CCH  16
#define NT   1024
#define PWS  132    // pwt row stride in floats (528B, 16B-aligned, 4-way max)

typedef unsigned long long u64;
typedef unsigned int u32;

__device__ __forceinline__ u64 pk2(float lo, float hi) {
    u64 r; asm("mov.b64 %0, {%1,%2};" : "=l"(r) : "f"(lo), "f"(hi)); return r;
}
__device__ __forceinline__ void up2(u64 v, float& a, float& b) {
    asm("mov.b64 {%0,%1}, %2;" : "=f"(a), "=f"(b) : "l"(v));
}
__device__ __forceinline__ void fma2(u64& d, u64 a, u64 b) {
    asm("fma.rn.f32x2 %0, %1, %2, %0;" : "+l"(d) : "l"(a), "l"(b));
}

// ---- shared layout (float index). total 56576 floats = 226304 B ----
#define MS_ATT   0
#define MS_H     64
#define MS_A     128
#define MS_DWW   192    // 576
#define MS_BNSC  768    // 256
#define MS_BNSH  1024   // 256
#define MS_CLSO  1280   // 256
#define MS_WP    2048   // 5120 max
#define SM_CORR  7168   // 16384 f32 corr  (box phase: P partials u64[2*9*256])
#define SM_DW    23552  // 8192 f32 region = dw fp16 [64][256]
#define SM_FT    31744  // 16384 f32 region = ft fp16 [128 o][256 px] (cls: P f32[4*9*256])
#define SM_PWT   48128  // 8448 (64 k x 132)
#define SM_TOTF  56576

// ---- depthwise 3x3 (+attention) from fp32 corr -> fp16 dw ----
__device__ __forceinline__ void dw_pass(float* sm, int tid,
                                        const float* __restrict__ dwW)
{
    float* s_dww = sm + MS_DWW;
    float* s_a   = sm + MS_A;
    float* s_corr = sm + SM_CORR;
    unsigned short* dw16 = (unsigned short*)(sm + SM_DW);

    for (int i = tid; i < NP * 9; i += NT) s_dww[i] = dwW[i];
    __syncthreads();

    const int px = tid & 255, pq = tid >> 8;
    const int y = px >> 4, x = px & 15;
    const bool okU = y > 0, okD = y < 15, okL = x > 0, okR = x < 15;
#pragma unroll 4
    for (int pi = 0; pi < 16; pi++) {
        const int p = pq * 16 + pi;
        const float* r = s_corr + p * NHW + px;
        const float* w = s_dww + p * 9;
        float acc = r[0] * w[4];
        if (okU) { acc = fmaf(r[-16], w[1], acc);
                   if (okL) acc = fmaf(r[-17], w[0], acc);
                   if (okR) acc = fmaf(r[-15], w[2], acc); }
        if (okD) { acc = fmaf(r[16], w[7], acc);
                   if (okL) acc = fmaf(r[15], w[6], acc);
                   if (okR) acc = fmaf(r[17], w[8], acc); }
        if (okL) acc = fmaf(r[-1], w[3], acc);
        if (okR) acc = fmaf(r[1],  w[5], acc);
        dw16[p * 256 + px] = __half_as_ushort(__float2half_rn(acc * s_a[p]));
    }
}

// ---- one pointwise-GEMM pass: 128 o x 256 px, K=64, fp16 x, fp32 acc ----
__device__ __forceinline__ void gemm_pass(float* sm, int lane, int warp, int o_base)
{
    const float* s_pwt  = sm + SM_PWT;
    const float* s_bnsc = sm + MS_BNSC;
    const float* s_bnsh = sm + MS_BNSH;
    const unsigned short* dw16 = (const unsigned short*)(sm + SM_DW);
    u32* s_ft = (u32*)(sm + SM_FT);

    const int og = warp >> 1, pxh = warp & 1;   // 16 o-groups x 2 px-halves
    const int ob = og * 8;
    const unsigned short* dwp = dw16 + pxh * 128 + lane * 4;

    u64 acc[4][4];
#pragma unroll
    for (int j = 0; j < 4; j++)
#pragma unroll
        for (int q = 0; q < 4; q++) acc[j][q] = 0ull;

#pragma unroll 4
    for (int k = 0; k < 64; k++) {
        const float* wp = s_pwt + k * PWS + ob;
        ulonglong2 wA = *(const ulonglong2*)wp;        // native (o,o+1) f32 pairs
        ulonglong2 wB = *(const ulonglong2*)(wp + 4);
        u64 wr[4] = {wA.x, wA.y, wB.x, wB.y};
        u64 xraw = *(const u64*)(dwp + k * 256);       // 4 px fp16
        u32 xlo = (u32)xraw, xhi = (u32)(xraw >> 32);
        float2 f0 = __half22float2(*(__half2*)&xlo);
        float2 f1 = __half22float2(*(__half2*)&xhi);
        u64 xd[4] = {pk2(f0.x, f0.x), pk2(f0.y, f0.y),
                     pk2(f1.x, f1.x), pk2(f1.y, f1.y)};
#pragma unroll
        for (int j = 0; j < 4; j++)
#pragma unroll
            for (int q = 0; q < 4; q++) fma2(acc[j][q], wr[j], xd[q]);
    }

    // BN + ReLU -> ft fp16 ([o][128 px-pair u32])
#pragma unroll
    for (int j = 0; j < 4; j++) {
        const int o = o_base + ob + 2 * j;
        const float sc0 = s_bnsc[o],     sh0 = s_bnsh[o];
        const float sc1 = s_bnsc[o + 1], sh1 = s_bnsh[o + 1];
        float e[4], d[4];
#pragma unroll
        for (int q = 0; q < 4; q++) {
            float a0, a1; up2(acc[j][q], a0, a1);
            e[q] = fmaxf(fmaf(a0, sc0, sh0), 0.0f);
            d[q] = fmaxf(fmaf(a1, sc1, sh1), 0.0f);
        }
        __half2 pe0 = __floats2half2_rn(e[0], e[1]);
        __half2 pe1 = __floats2half2_rn(e[2], e[3]);
        __half2 pd0 = __floats2half2_rn(d[0], d[1]);
        __half2 pd1 = __floats2half2_rn(d[2], d[3]);
        const int base = pxh * 64 + lane * 2;
        *(uint2*)(s_ft + (ob + 2 * j)     * 128 + base) = make_uint2(*(u32*)&pe0, *(u32*)&pe1);
        *(uint2*)(s_ft + (ob + 2 * j + 1) * 128 + base) = make_uint2(*(u32*)&pd0, *(u32*)&pd1);
    }
}

__device__ __forceinline__ void stage_bn(float* sm, int tid,
    const float* __restrict__ bng, const float* __restrict__ bnb,
    const float* __restrict__ bnm, const float* __restrict__ bnv)
{
    if (tid < NOC) {
        float sc = bng[tid] * rsqrtf(bnv[tid] + 1e-5f);
        sm[MS_BNSC + tid] = sc;
        sm[MS_BNSH + tid] = bnb[tid] - bnm[tid] * sc;
    }
}

__global__ void __launch_bounds__(NT, 1)
btl_kernel(
    const float* __restrict__ search, const float* __restrict__ kern,
    const float* __restrict__ ca_w1, const float* __restrict__ ca_b1,
    const float* __restrict__ ca_w2, const float* __restrict__ ca_b2,
    const float* __restrict__ cls_dw, const float* __restrict__ cls_pw,
    const float* __restrict__ cls_bng, const float* __restrict__ cls_bnb,
    const float* __restrict__ cls_bnm, const float* __restrict__ cls_bnv,
    const float* __restrict__ cls_predw, const float* __restrict__ cls_predb,
    const float* __restrict__ box_dw, const float* __restrict__ box_pw,
    const float* __restrict__ box_bng, const float* __restrict__ box_bnb,
    const float* __restrict__ box_bnm, const float* __restrict__ box_bnv,
    const float* __restrict__ box_predw, const float* __restrict__ box_predb,
    const float* __restrict__ adjust, const float* __restrict__ biasp,
    float* __restrict__ out)
{
    extern __shared__ float sm[];
    const int tid  = threadIdx.x;
    const int lane = tid & 31;
    const int warp = tid >> 5;
    const int b    = blockIdx.x;

    float* s_att  = sm + MS_ATT;
    float* s_h    = sm + MS_H;
    float* s_a    = sm + MS_A;
    float* s_clso = sm + MS_CLSO;
    float* s_wp   = sm + MS_WP;
    float* s_corr = sm + SM_CORR;

    // ===== Phase A: correlation GEMM corr[64p x 256px], K=112 (fp32) =====
    float* bufA = sm + SM_FT;          // staging: search 4096 + z 1024
    float* bufB = sm + SM_FT + 5120;

    const float* gS = search + (size_t)b * NC * NHW;
    const float* gZ = kern   + (size_t)b * NC * NP;

    const int pg  = warp >> 2;
    const int pxq = warp & 3;
    const int pb  = pg * 8;
    const int pxb = pxq * 64 + lane * 2;

    u64 cacc[4][2];
#pragma unroll
    for (int j = 0; j < 4; j++) { cacc[j][0] = 0ull; cacc[j][1] = 0ull; }

    ((float4*)bufA)[tid] = ((const float4*)gS)[tid];
    bufA[4096 + tid] = gZ[tid];
    __syncthreads();

    int sbsel = 0;
    for (int chk = 0; chk < 7; chk++) {
        float4 pre4; float prez;
        if (chk < 6) {
            pre4 = ((const float4*)(gS + (chk + 1) * CCH * NHW))[tid];
            prez = (gZ + (chk + 1) * CCH * NP)[tid];
        }
        const float* sbuf = sbsel ? bufB : bufA;
        const float* szb  = sbuf + 4096;
#pragma unroll 4
        for (int cc = 0; cc < CCH; cc++) {
            const float* zp = szb + cc * NP + pb;
            ulonglong2 zA = *(const ulonglong2*)zp;
            ulonglong2 zB = *(const ulonglong2*)(zp + 4);
            u64 zr[4] = {zA.x, zA.y, zB.x, zB.y};
            u64 xp = *(const u64*)(sbuf + cc * NHW + pxb);
            float x0, x1; up2(xp, x0, x1);
            u64 xd0 = pk2(x0, x0), xd1 = pk2(x1, x1);
#pragma unroll
            for (int j = 0; j < 4; j++) {
                fma2(cacc[j][0], zr[j], xd0);
                fma2(cacc[j][1], zr[j], xd1);
            }
        }
        if (chk < 6) {
            float* dbuf = sbsel ? bufA : bufB;
            ((float4*)dbuf)[tid] = pre4;
            dbuf[4096 + tid] = prez;
        }
        __syncthreads();
        sbsel ^= 1;
    }

#pragma unroll
    for (int j = 0; j < 4; j++) {
        float a00, a01, a10, a11;
        up2(cacc[j][0], a00, a01);
        up2(cacc[j][1], a10, a11);
        *(u64*)(s_corr + (pb + 2 * j)     * NHW + pxb) = pk2(a00, a10);
        *(u64*)(s_corr + (pb + 2 * j + 1) * NHW + pxb) = pk2(a01, a11);
    }
    __syncthreads();

    // per-p means
    {
        const int p0 = warp * 2;
#pragma unroll
        for (int j = 0; j < 2; j++) {
            const int p = p0 + j;
            float ps = 0.0f;
#pragma unroll
            for (int i = 0; i < 8; i++) ps += s_corr[p * NHW + lane + 32 * i];
#pragma unroll
            for (int o = 16; o > 0; o >>= 1) ps += __shfl_xor_sync(0xffffffffu, ps, o);
            if (lane == 0) s_att[p] = ps * (1.0f / 256.0f);
        }
    }
    __syncthreads();

    // ===== Phase B: channel-attention MLP =====
    if (tid < 64) {
        float s1 = ca_b1[tid];
        const float* w = ca_w1 + tid * 64;
#pragma unroll 8
        for (int j = 0; j < 64; j++) s1 = fmaf(w[j], s_att[j], s1);
        s_h[tid] = fmaxf(s1, 0.0f);
    }
    __syncthreads();
    if (tid < 64) {
        float s2 = ca_b2[tid];
        const float* w = ca_w2 + tid * 64;
#pragma unroll 8
        for (int j = 0; j < 64; j++) s2 = fmaf(w[j], s_h[j], s2);
        s_a[tid] = 1.0f / (1.0f + expf(-s2));
    }
    __syncthreads();

    // =================== CLS TOWER ===================
    {
        stage_bn(sm, tid, cls_bng, cls_bnb, cls_bnm, cls_bnv);
        dw_pass(sm, tid, cls_dw);
        __syncthreads();

        u64 Sc[5];
#pragma unroll
        for (int i = 0; i < 5; i++) Sc[i] = 0ull;

        const unsigned short* ftp = (const unsigned short*)(sm + SM_FT);
        const int px = tid & 255, cq = tid >> 8;

        for (int p = 0; p < 2; p++) {
            // stage pwt (8 regs/thread) + pred weights
#pragma unroll
            for (int j = 0; j < 8; j++) {
                int i = tid + j * 1024;
                int k = i & 63, o = i >> 6;
                sm[SM_PWT + k * PWS + o] = cls_pw[(p * 128 + o) * 64 + k];
            }
            for (int i = tid; i < 1536; i += NT) {
                int c = i / 12, k = i % 12;
                s_wp[i] = (k < 9) ? cls_predw[(p * 128 + c) * 9 + k] : 0.0f;
            }
            __syncthreads();

            gemm_pass(sm, lane, warp, p * 128);
            __syncthreads();

            // tap: thread (cq of 32c, px)
#pragma unroll 2
            for (int ci = 0; ci < 32; ci++) {
                const int c = cq * 32 + ci;
                float xv = __half2float(__ushort_as_half(ftp[c * 256 + px]));
                const u64 xd = pk2(xv, xv);
                const ulonglong2* wp2 = (const ulonglong2*)(s_wp + c * 12);
                ulonglong2 wA = wp2[0];
                ulonglong2 wB = wp2[1];
                float w8 = s_wp[c * 12 + 8];
                fma2(Sc[0], xd, wA.x);
                fma2(Sc[1], xd, wA.y);
                fma2(Sc[2], xd, wB.x);
                fma2(Sc[3], xd, wB.y);
                fma2(Sc[4], xd, pk2(w8, 0.0f));
            }
            __syncthreads();
        }

        // P_cls disjoint [4 cq][9 k][256 px] into dead FT region
        float* Pc = sm + SM_FT;
#pragma unroll
        for (int kp = 0; kp < 4; kp++) {
            float a0, a1; up2(Sc[kp], a0, a1);
            Pc[(cq * 9 + 2 * kp) * 256 + px]     = a0;
            Pc[(cq * 9 + 2 * kp + 1) * 256 + px] = a1;
        }
        { float a0, a1; up2(Sc[4], a0, a1);
          Pc[(cq * 9 + 8) * 256 + px] = a0; }
        __syncthreads();

        if (tid < 256) {
            const int qx = tid, y = qx >> 4, x = qx & 15;
            float acc = 0.0f;
#pragma unroll
            for (int dy = -1; dy <= 1; dy++) {
                if (y + dy < 0 || y + dy > 15) continue;
#pragma unroll
                for (int dx = -1; dx <= 1; dx++) {
                    if (x + dx < 0 || x + dx > 15) continue;
                    const int k = (dy + 1) * 3 + (dx + 1);
                    const int q = qx + dy * 16 + dx;
                    acc += Pc[(k)      * 256 + q] + Pc[(9 + k)  * 256 + q]
                         + Pc[(18 + k) * 256 + q] + Pc[(27 + k) * 256 + q];
                }
            }
            s_clso[qx] = acc;
        }
        __syncthreads();
    }

    // =================== BOX TOWER ===================
    {
        stage_bn(sm, tid, box_bng, box_bnb, box_bnm, box_bnv);
        dw_pass(sm, tid, box_dw);   // reads corr (last use), writes dw fp16
        __syncthreads();

        u64* Pb = (u64*)(sm + SM_CORR);   // [2 op][9 k][256 px-entry] u64, corr now dead
        const u32* ftp32 = (const u32*)(sm + SM_FT);
        const int pp = tid & 127;            // px-pair index
        const int grp = tid >> 7;            // 8 groups
        const int op = grp & 1, ch = grp >> 1;   // oc-pair, c-quarter

        for (int p = 0; p < 2; p++) {
#pragma unroll
            for (int j = 0; j < 8; j++) {
                int i = tid + j * 1024;
                int k = i & 63, o = i >> 6;
                sm[SM_PWT + k * PWS + o] = box_pw[(p * 128 + o) * 64 + k];
            }
            for (int i = tid; i < 5120; i += NT) {
                int c = i / 40, r = i % 40, o2 = r / 20, t = r % 20;
                float v = 0.0f;
                if (t < 18) {
                    int k = t >> 1, h = t & 1;
                    v = box_predw[(o2 * 2 + h) * 2304 + (p * 128 + c) * 9 + k];
                }
                s_wp[i] = v;
            }
            __syncthreads();

            gemm_pass(sm, lane, warp, p * 128);
            __syncthreads();

            // tap: thread (ch of 32c, op, px-pair); S[2k+h] = (oc_lo,oc_hi) @ px h
            u64 S[18];
#pragma unroll
            for (int i = 0; i < 18; i++) S[i] = 0ull;
#pragma unroll 2
            for (int ci = 0; ci < 32; ci++) {
                const int c = ch * 32 + ci;
                u32 xw = ftp32[c * 128 + pp];
                float2 xf = __half22float2(*(__half2*)&xw);
                const u64 xd0 = pk2(xf.x, xf.x), xd1 = pk2(xf.y, xf.y);
                const float* wb = s_wp + (c * 2 + op) * 20;
                const ulonglong2* w2 = (const ulonglong2*)wb;
                ulonglong2 wa = w2[0], wc = w2[1], wd = w2[2], we = w2[3];
                u64 w8 = *(const u64*)(wb + 16);
                fma2(S[0], wa.x, xd0);  fma2(S[1], wa.x, xd1);
                fma2(S[2], wa.y, xd0);  fma2(S[3], wa.y, xd1);
                fma2(S[4], wc.x, xd0);  fma2(S[5], wc.x, xd1);
                fma2(S[6], wc.y, xd0);  fma2(S[7], wc.y, xd1);
                fma2(S[8], wd.x, xd0);  fma2(S[9], wd.x, xd1);
                fma2(S[10], wd.y, xd0); fma2(S[11], wd.y, xd1);
                fma2(S[12], we.x, xd0); fma2(S[13], we.x, xd1);
                fma2(S[14], we.y, xd0); fma2(S[15], we.y, xd1);
                fma2(S[16], w8, xd0);   fma2(S[17], w8, xd1);
            }

            // accumulate into Pb over 4 sequential ch-rounds
#pragma unroll 1
            for (int r = 0; r < 4; r++) {
                if (ch == r) {
#pragma unroll
                    for (int k = 0; k < 9; k++) {
                        u64* dst = Pb + (op * 9 + k) * 256 + 2 * pp;
                        if (p == 0 && r == 0) {
                            *(ulonglong2*)dst = make_ulonglong2(S[2 * k], S[2 * k + 1]);
                        } else {
                            ulonglong2 cur = *(ulonglong2*)dst;
                            float c0, c1, c2, c3, s0, s1, s2, s3;
                            up2(cur.x, c0, c1); up2(cur.y, c2, c3);
                            up2(S[2 * k], s0, s1); up2(S[2 * k + 1], s2, s3);
                            *(ulonglong2*)dst = make_ulonglong2(
                                pk2(c0 + s0, c1 + s1), pk2(c2 + s2, c3 + s3));
                        }
                    }
                }
                __syncthreads();
            }
        }
    }

    // ===== epilogue (thread = pixel) =====
    if (tid < 256) {
        const int qx = tid, y = qx >> 4, x = qx & 15;
        out[(size_t)NB * 4 * NHW + (size_t)b * NHW + qx] =
            0.1f * (s_clso[qx] + cls_predb[0]);

        const u64* Pb = (const u64*)(sm + SM_CORR);
        float bx0 = 0.0f, bx1 = 0.0f, bx2 = 0.0f, bx3 = 0.0f;
#pragma unroll
        for (int dy = -1; dy <= 1; dy++) {
            if (y + dy < 0 || y + dy > 15) continue;
#pragma unroll
            for (int dx = -1; dx <= 1; dx++) {
                if (x + dx < 0 || x + dx > 15) continue;
                const int k = (dy + 1) * 3 + (dx + 1);
                const int q = qx + dy * 16 + dx;
                float a0, a1, a2, a3;
                up2(Pb[(k)     * 256 + q], a0, a1);
                up2(Pb[(9 + k) * 256 + q], a2, a3);
                bx0 += a0; bx1 += a1; bx2 += a2; bx3 += a3;
            }
        }
        const float adj = adjust[0];
        out[((size_t)b * 4 + 0) * NHW + qx] = expf(adj * (bx0 + box_predb[0]) + biasp[0]);
        out[((size_t)b * 4 + 1) * NHW + qx] = expf(adj * (bx1 + box_predb[1]) + biasp[1]);
        out[((size_t)b * 4 + 2) * NHW + qx] = expf(adj * (bx2 + box_predb[2]) + biasp[2]);
        out[((size_t)b * 4 + 3) * NHW + qx] = expf(adj * (bx3 + box_predb[3]) + biasp[3]);
    }
}

extern "C" void kernel_launch(void* const* d_in, const int* in_sizes, int n_in,
                              void* d_out, int out_size)
{
    const float* search    = (const float*)d_in[0];
    const float* kern      = (const float*)d_in[1];
    const float* ca_w1     = (const float*)d_in[2];
    const float* ca_b1     = (const float*)d_in[3];
    const float* ca_w2     = (const float*)d_in[4];
    const float* ca_b2     = (const float*)d_in[5];
    const float* cls_dw    = (const float*)d_in[6];
    const float* cls_pw    = (const float*)d_in[7];
    const float* cls_bng   = (const float*)d_in[8];
    const float* cls_bnb   = (const float*)d_in[9];
    const float* cls_bnm   = (const float*)d_in[10];
    const float* cls_bnv   = (const float*)d_in[11];
    const float* cls_predw = (const float*)d_in[12];
    const float* cls_predb = (const float*)d_in[13];
    const float* box_dw    = (const float*)d_in[14];
    const float* box_pw    = (const float*)d_in[15];
    const float* box_bng   = (const float*)d_in[16];
    const float* box_bnb   = (const float*)d_in[17];
    const float* box_bnm   = (const float*)d_in[18];
    const float* box_bnv   = (const float*)d_in[19];
    const float* box_predw = (const float*)d_in[20];
    const float* box_predb = (const float*)d_in[21];
    const float* adjust    = (const float*)d_in[22];
    const float* biasp     = (const float*)d_in[23];

    const int smbytes = SM_TOTF * 4;  // 226304 B
    cudaFuncSetAttribute(btl_kernel, cudaFuncAttributeMaxDynamicSharedMemorySize, smbytes);

    btl_kernel<<<NB, NT, smbytes>>>(
        search, kern, ca_w1, ca_b1, ca_w2, ca_b2,
        cls_dw, cls_pw, cls_bng, cls_bnb, cls_bnm, cls_bnv, cls_predw, cls_predb,
        box_dw, box_pw, box_bng, box_bnb, box_bnm, box_bnv, box_predw, box_predb,
        adjust, biasp, (float*)d_out);
}

// round 11
// speedup vs baseline: 2.1496x; 1.1170x over previous
#include <cuda_runtime.h>
#include <cuda_fp16.h>
#include <math.h>

#define NB   512
#define NC   112
#define NP   64
#define NHW  256
#define NOC  256
#define CCH  16
#define NT   1024
#define PWS  132

typedef unsigned long long u64;
typedef unsigned int u32;

__device__ __forceinline__ u64 pk2(float lo, float hi) {
    u64 r; asm("mov.b64 %0, {%1,%2};" : "=l"(r) : "f"(lo), "f"(hi)); return r;
}
__device__ __forceinline__ void up2(u64 v, float& a, float& b) {
    asm("mov.b64 {%0,%1}, %2;" : "=f"(a), "=f"(b) : "l"(v));
}
__device__ __forceinline__ void fma2(u64& d, u64 a, u64 b) {
    asm("fma.rn.f32x2 %0, %1, %2, %0;" : "+l"(d) : "l"(a), "l"(b));
}

// dw scratch: [sample][tower][p 64][px 256] fp16
__device__ __half g_dw[(size_t)NB * 2 * NP * NHW];

// ======================= KERNEL 1: corr + attention + dual dw =======================
// smem (float idx): att 0, h 64, a 128, dwwc 192..768, dwwb 768..1344,
// corr 7168..23552, staging 23552..33792
#define K1_ATT  0
#define K1_H    64
#define K1_A    128
#define K1_DWC  192
#define K1_DWB  768
#define K1_CORR 7168
#define K1_STG  23552
#define K1_TOT  33792   // 135168 B

__global__ void __launch_bounds__(NT, 1)
btl_k1(const float* __restrict__ search, const float* __restrict__ kern,
       const float* __restrict__ ca_w1, const float* __restrict__ ca_b1,
       const float* __restrict__ ca_w2, const float* __restrict__ ca_b2,
       const float* __restrict__ cls_dw, const float* __restrict__ box_dw)
{
    extern __shared__ float sm[];
    const int tid  = threadIdx.x;
    const int lane = tid & 31;
    const int warp = tid >> 5;
    const int b    = blockIdx.x;

    float* s_att  = sm + K1_ATT;
    float* s_h    = sm + K1_H;
    float* s_a    = sm + K1_A;
    float* s_corr = sm + K1_CORR;
    float* bufA   = sm + K1_STG;
    float* bufB   = sm + K1_STG + 5120;

    const float* gS = search + (size_t)b * NC * NHW;
    const float* gZ = kern   + (size_t)b * NC * NP;

    const int pg  = warp >> 2;
    const int pxq = warp & 3;
    const int pb  = pg * 8;
    const int pxb = pxq * 64 + lane * 2;

    u64 cacc[4][2];
#pragma unroll
    for (int j = 0; j < 4; j++) { cacc[j][0] = 0ull; cacc[j][1] = 0ull; }

    ((float4*)bufA)[tid] = ((const float4*)gS)[tid];
    bufA[4096 + tid] = gZ[tid];
    __syncthreads();

    int sbsel = 0;
    for (int chk = 0; chk < 7; chk++) {
        float4 pre4; float prez;
        if (chk < 6) {
            pre4 = ((const float4*)(gS + (chk + 1) * CCH * NHW))[tid];
            prez = (gZ + (chk + 1) * CCH * NP)[tid];
        }
        const float* sbuf = sbsel ? bufB : bufA;
        const float* szb  = sbuf + 4096;
#pragma unroll 4
        for (int cc = 0; cc < CCH; cc++) {
            const float* zp = szb + cc * NP + pb;
            ulonglong2 zA = *(const ulonglong2*)zp;
            ulonglong2 zB = *(const ulonglong2*)(zp + 4);
            u64 zr[4] = {zA.x, zA.y, zB.x, zB.y};
            u64 xp = *(const u64*)(sbuf + cc * NHW + pxb);
            float x0, x1; up2(xp, x0, x1);
            u64 xd0 = pk2(x0, x0), xd1 = pk2(x1, x1);
#pragma unroll
            for (int j = 0; j < 4; j++) {
                fma2(cacc[j][0], zr[j], xd0);
                fma2(cacc[j][1], zr[j], xd1);
            }
        }
        if (chk < 6) {
            float* dbuf = sbsel ? bufA : bufB;
            ((float4*)dbuf)[tid] = pre4;
            dbuf[4096 + tid] = prez;
        }
        __syncthreads();
        sbsel ^= 1;
    }

#pragma unroll
    for (int j = 0; j < 4; j++) {
        float a00, a01, a10, a11;
        up2(cacc[j][0], a00, a01);
        up2(cacc[j][1], a10, a11);
        *(u64*)(s_corr + (pb + 2 * j)     * NHW + pxb) = pk2(a00, a10);
        *(u64*)(s_corr + (pb + 2 * j + 1) * NHW + pxb) = pk2(a01, a11);
    }
    __syncthreads();

    // per-p means
    {
        const int p0 = warp * 2;
#pragma unroll
        for (int j = 0; j < 2; j++) {
            const int p = p0 + j;
            float ps = 0.0f;
#pragma unroll
            for (int i = 0; i < 8; i++) ps += s_corr[p * NHW + lane + 32 * i];
#pragma unroll
            for (int o = 16; o > 0; o >>= 1) ps += __shfl_xor_sync(0xffffffffu, ps, o);
            if (lane == 0) s_att[p] = ps * (1.0f / 256.0f);
        }
    }
    // stage depthwise weights for both towers (overlap with means)
    for (int i = tid; i < NP * 9; i += NT) {
        sm[K1_DWC + i] = cls_dw[i];
        sm[K1_DWB + i] = box_dw[i];
    }
    __syncthreads();

    // attention MLP
    if (tid < 64) {
        float s1 = ca_b1[tid];
        const float* w = ca_w1 + tid * 64;
#pragma unroll 8
        for (int j = 0; j < 64; j++) s1 = fmaf(w[j], s_att[j], s1);
        s_h[tid] = fmaxf(s1, 0.0f);
    }
    __syncthreads();
    if (tid < 64) {
        float s2 = ca_b2[tid];
        const float* w = ca_w2 + tid * 64;
#pragma unroll 8
        for (int j = 0; j < 64; j++) s2 = fmaf(w[j], s_h[j], s2);
        s_a[tid] = 1.0f / (1.0f + expf(-s2));
    }
    __syncthreads();

    // merged dual depthwise 3x3 (+attention) -> g_dw fp16
    {
        const int px = tid & 255, pq = tid >> 8;
        const int y = px >> 4, x = px & 15;
        const bool okU = y > 0, okD = y < 15, okL = x > 0, okR = x < 15;
        __half* dc = g_dw + ((size_t)b * 2)     * (NP * NHW) + px;
        __half* db = g_dw + ((size_t)b * 2 + 1) * (NP * NHW) + px;
#pragma unroll 2
        for (int pi = 0; pi < 16; pi++) {
            const int p = pq * 16 + pi;
            const float* r = s_corr + p * NHW + px;
            float nv[9];
            nv[4] = r[0];
            nv[1] = okU ? r[-16] : 0.0f;
            nv[0] = (okU && okL) ? r[-17] : 0.0f;
            nv[2] = (okU && okR) ? r[-15] : 0.0f;
            nv[7] = okD ? r[16] : 0.0f;
            nv[6] = (okD && okL) ? r[15] : 0.0f;
            nv[8] = (okD && okR) ? r[17] : 0.0f;
            nv[3] = okL ? r[-1] : 0.0f;
            nv[5] = okR ? r[1] : 0.0f;
            const float* wc = sm + K1_DWC + p * 9;
            const float* wb = sm + K1_DWB + p * 9;
            float ac = 0.0f, ab = 0.0f;
#pragma unroll
            for (int k = 0; k < 9; k++) {
                ac = fmaf(nv[k], wc[k], ac);
                ab = fmaf(nv[k], wb[k], ab);
            }
            const float a = s_a[p];
            dc[p * NHW] = __float2half_rn(ac * a);
            db[p * NHW] = __float2half_rn(ab * a);
        }
    }
}

// ======================= KERNEL 2: one tower per CTA =======================
#define K2_BNSC 0       // 256
#define K2_BNSH 256     // 256
#define K2_WP   1024    // 5120
#define K2_DW   6144    // 8192 f-slots = dw fp16 [64][256]
#define K2_FT   14336   // 16384 f-slots = ft fp16 [128][256]; later cls P f32[4*9*256]
#define K2_PWT  30720   // 8448
#define K2_PB   39168   // 9216 f-slots = box P u64[2*9*256]
#define K2_TOT  48384   // 193536 B

__device__ __forceinline__ void gemm_pass2(float* sm, int lane, int warp, int o_base)
{
    const float* s_pwt  = sm + K2_PWT;
    const float* s_bnsc = sm + K2_BNSC;
    const float* s_bnsh = sm + K2_BNSH;
    const unsigned short* dw16 = (const unsigned short*)(sm + K2_DW);
    u32* s_ft = (u32*)(sm + K2_FT);

    const int og = warp >> 1, pxh = warp & 1;
    const int ob = og * 8;
    const unsigned short* dwp = dw16 + pxh * 128 + lane * 4;

    u64 acc[4][4];
#pragma unroll
    for (int j = 0; j < 4; j++)
#pragma unroll
        for (int q = 0; q < 4; q++) acc[j][q] = 0ull;

#pragma unroll 4
    for (int k = 0; k < 64; k++) {
        const float* wp = s_pwt + k * PWS + ob;
        ulonglong2 wA = *(const ulonglong2*)wp;
        ulonglong2 wB = *(const ulonglong2*)(wp + 4);
        u64 wr[4] = {wA.x, wA.y, wB.x, wB.y};
        u64 xraw = *(const u64*)(dwp + k * 256);
        u32 xlo = (u32)xraw, xhi = (u32)(xraw >> 32);
        float2 f0 = __half22float2(*(__half2*)&xlo);
        float2 f1 = __half22float2(*(__half2*)&xhi);
        u64 xd[4] = {pk2(f0.x, f0.x), pk2(f0.y, f0.y),
                     pk2(f1.x, f1.x), pk2(f1.y, f1.y)};
#pragma unroll
        for (int j = 0; j < 4; j++)
#pragma unroll
            for (int q = 0; q < 4; q++) fma2(acc[j][q], wr[j], xd[q]);
    }

#pragma unroll
    for (int j = 0; j < 4; j++) {
        const int o = o_base + ob + 2 * j;
        const float sc0 = s_bnsc[o],     sh0 = s_bnsh[o];
        const float sc1 = s_bnsc[o + 1], sh1 = s_bnsh[o + 1];
        float e[4], d[4];
#pragma unroll
        for (int q = 0; q < 4; q++) {
            float a0, a1; up2(acc[j][q], a0, a1);
            e[q] = fmaxf(fmaf(a0, sc0, sh0), 0.0f);
            d[q] = fmaxf(fmaf(a1, sc1, sh1), 0.0f);
        }
        __half2 pe0 = __floats2half2_rn(e[0], e[1]);
        __half2 pe1 = __floats2half2_rn(e[2], e[3]);
        __half2 pd0 = __floats2half2_rn(d[0], d[1]);
        __half2 pd1 = __floats2half2_rn(d[2], d[3]);
        const int base = pxh * 64 + lane * 2;
        *(uint2*)(s_ft + (ob + 2 * j)     * 128 + base) = make_uint2(*(u32*)&pe0, *(u32*)&pe1);
        *(uint2*)(s_ft + (ob + 2 * j + 1) * 128 + base) = make_uint2(*(u32*)&pd0, *(u32*)&pd1);
    }
}

__global__ void __launch_bounds__(NT, 1)
btl_k2(const float* __restrict__ cls_pw,
       const float* __restrict__ cls_bng, const float* __restrict__ cls_bnb,
       const float* __restrict__ cls_bnm, const float* __restrict__ cls_bnv,
       const float* __restrict__ cls_predw, const float* __restrict__ cls_predb,
       const float* __restrict__ box_pw,
       const float* __restrict__ box_bng, const float* __restrict__ box_bnb,
       const float* __restrict__ box_bnm, const float* __restrict__ box_bnv,
       const float* __restrict__ box_predw, const float* __restrict__ box_predb,
       const float* __restrict__ adjust, const float* __restrict__ biasp,
       float* __restrict__ out)
{
    extern __shared__ float sm[];
    const int tid  = threadIdx.x;
    const int lane = tid & 31;
    const int warp = tid >> 5;
    const int s    = blockIdx.x >> 1;
    const int t    = blockIdx.x & 1;

    // stage dw fp16 from scratch (32KB)
    {
        const uint4* src = (const uint4*)(g_dw + ((size_t)s * 2 + t) * (NP * NHW));
        uint4* dst = (uint4*)(sm + K2_DW);
        dst[tid] = src[tid];
        dst[tid + 1024] = src[tid + 1024];
    }
    // stage folded BN
    if (tid < NOC) {
        const float* bng = t ? box_bng : cls_bng;
        const float* bnb = t ? box_bnb : cls_bnb;
        const float* bnm = t ? box_bnm : cls_bnm;
        const float* bnv = t ? box_bnv : cls_bnv;
        float sc = bng[tid] * rsqrtf(bnv[tid] + 1e-5f);
        sm[K2_BNSC + tid] = sc;
        sm[K2_BNSH + tid] = bnb[tid] - bnm[tid] * sc;
    }
    __syncthreads();

    float* s_wp = sm + K2_WP;

    if (t == 0) {
        // ---------------- CLS tower ----------------
        u64 Sc[5];
#pragma unroll
        for (int i = 0; i < 5; i++) Sc[i] = 0ull;
        const unsigned short* ftp = (const unsigned short*)(sm + K2_FT);
        const int px = tid & 255, cq = tid >> 8;

        for (int p = 0; p < 2; p++) {
#pragma unroll
            for (int j = 0; j < 8; j++) {
                int i = tid + j * 1024;
                int k = i & 63, o = i >> 6;
                sm[K2_PWT + k * PWS + o] = cls_pw[(p * 128 + o) * 64 + k];
            }
            for (int i = tid; i < 1536; i += NT) {
                int c = i / 12, k = i % 12;
                s_wp[i] = (k < 9) ? cls_predw[(p * 128 + c) * 9 + k] : 0.0f;
            }
            __syncthreads();

            gemm_pass2(sm, lane, warp, p * 128);
            __syncthreads();

#pragma unroll 2
            for (int ci = 0; ci < 32; ci++) {
                const int c = cq * 32 + ci;
                float xv = __half2float(__ushort_as_half(ftp[c * 256 + px]));
                const u64 xd = pk2(xv, xv);
                const ulonglong2* wp2 = (const ulonglong2*)(s_wp + c * 12);
                ulonglong2 wA = wp2[0];
                ulonglong2 wB = wp2[1];
                float w8 = s_wp[c * 12 + 8];
                fma2(Sc[0], xd, wA.x);
                fma2(Sc[1], xd, wA.y);
                fma2(Sc[2], xd, wB.x);
                fma2(Sc[3], xd, wB.y);
                fma2(Sc[4], xd, pk2(w8, 0.0f));
            }
            __syncthreads();
        }

        // disjoint P write into dead FT region
        float* Pc = sm + K2_FT;
#pragma unroll
        for (int kp = 0; kp < 4; kp++) {
            float a0, a1; up2(Sc[kp], a0, a1);
            Pc[(cq * 9 + 2 * kp) * 256 + px]     = a0;
            Pc[(cq * 9 + 2 * kp + 1) * 256 + px] = a1;
        }
        { float a0, a1; up2(Sc[4], a0, a1);
          Pc[(cq * 9 + 8) * 256 + px] = a0; }
        __syncthreads();

        if (tid < 256) {
            const int qx = tid, y = qx >> 4, x = qx & 15;
            float acc = 0.0f;
#pragma unroll
            for (int dy = -1; dy <= 1; dy++) {
                if (y + dy < 0 || y + dy > 15) continue;
#pragma unroll
                for (int dx = -1; dx <= 1; dx++) {
                    if (x + dx < 0 || x + dx > 15) continue;
                    const int k = (dy + 1) * 3 + (dx + 1);
                    const int q = qx + dy * 16 + dx;
                    acc += Pc[(k)      * 256 + q] + Pc[(9 + k)  * 256 + q]
                         + Pc[(18 + k) * 256 + q] + Pc[(27 + k) * 256 + q];
                }
            }
            out[(size_t)NB * 4 * NHW + (size_t)s * NHW + qx] =
                0.1f * (acc + cls_predb[0]);
        }
    } else {
        // ---------------- BOX tower ----------------
        u64* Pb = (u64*)(sm + K2_PB);
        const u32* ftp32 = (const u32*)(sm + K2_FT);
        const int pp = tid & 127;
        const int grp = tid >> 7;
        const int op = grp & 1, ch = grp >> 1;

        for (int p = 0; p < 2; p++) {
#pragma unroll
            for (int j = 0; j < 8; j++) {
                int i = tid + j * 1024;
                int k = i & 63, o = i >> 6;
                sm[K2_PWT + k * PWS + o] = box_pw[(p * 128 + o) * 64 + k];
            }
            for (int i = tid; i < 5120; i += NT) {
                int c = i / 40, r = i % 40, o2 = r / 20, tt = r % 20;
                float v = 0.0f;
                if (tt < 18) {
                    int k = tt >> 1, h = tt & 1;
                    v = box_predw[(o2 * 2 + h) * 2304 + (p * 128 + c) * 9 + k];
                }
                s_wp[i] = v;
            }
            __syncthreads();

            gemm_pass2(sm, lane, warp, p * 128);
            __syncthreads();

            u64 S[18];
#pragma unroll
            for (int i = 0; i < 18; i++) S[i] = 0ull;
#pragma unroll 2
            for (int ci = 0; ci < 32; ci++) {
                const int c = ch * 32 + ci;
                u32 xw = ftp32[c * 128 + pp];
                float2 xf = __half22float2(*(__half2*)&xw);
                const u64 xd0 = pk2(xf.x, xf.x), xd1 = pk2(xf.y, xf.y);
                const float* wb = s_wp + (c * 2 + op) * 20;
                const ulonglong2* w2 = (const ulonglong2*)wb;
                ulonglong2 wa = w2[0], wc = w2[1], wd = w2[2], we = w2[3];
                u64 w8 = *(const u64*)(wb + 16);
                fma2(S[0], wa.x, xd0);  fma2(S[1], wa.x, xd1);
                fma2(S[2], wa.y, xd0);  fma2(S[3], wa.y, xd1);
                fma2(S[4], wc.x, xd0);  fma2(S[5], wc.x, xd1);
                fma2(S[6], wc.y, xd0);  fma2(S[7], wc.y, xd1);
                fma2(S[8], wd.x, xd0);  fma2(S[9], wd.x, xd1);
                fma2(S[10], wd.y, xd0); fma2(S[11], wd.y, xd1);
                fma2(S[12], we.x, xd0); fma2(S[13], we.x, xd1);
                fma2(S[14], we.y, xd0); fma2(S[15], we.y, xd1);
                fma2(S[16], w8, xd0);   fma2(S[17], w8, xd1);
            }

#pragma unroll 1
            for (int r = 0; r < 4; r++) {
                if (ch == r) {
#pragma unroll
                    for (int k = 0; k < 9; k++) {
                        u64* dst = Pb + (op * 9 + k) * 256 + 2 * pp;
                        if (p == 0 && r == 0) {
                            *(ulonglong2*)dst = make_ulonglong2(S[2 * k], S[2 * k + 1]);
                        } else {
                            ulonglong2 cur = *(ulonglong2*)dst;
                            float c0, c1, c2, c3, s0, s1, s2, s3;
                            up2(cur.x, c0, c1); up2(cur.y, c2, c3);
                            up2(S[2 * k], s0, s1); up2(S[2 * k + 1], s2, s3);
                            *(ulonglong2*)dst = make_ulonglong2(
                                pk2(c0 + s0, c1 + s1), pk2(c2 + s2, c3 + s3));
                        }
                    }
                }
                __syncthreads();
            }
        }

        if (tid < 256) {
            const int qx = tid, y = qx >> 4, x = qx & 15;
            float bx0 = 0.0f, bx1 = 0.0f, bx2 = 0.0f, bx3 = 0.0f;
#pragma unroll
            for (int dy = -1; dy <= 1; dy++) {
                if (y + dy < 0 || y + dy > 15) continue;
#pragma unroll
                for (int dx = -1; dx <= 1; dx++) {
                    if (x + dx < 0 || x + dx > 15) continue;
                    const int k = (dy + 1) * 3 + (dx + 1);
                    const int q = qx + dy * 16 + dx;
                    float a0, a1, a2, a3;
                    up2(Pb[(k)     * 256 + q], a0, a1);
                    up2(Pb[(9 + k) * 256 + q], a2, a3);
                    bx0 += a0; bx1 += a1; bx2 += a2; bx3 += a3;
                }
            }
            const float adj = adjust[0];
            out[((size_t)s * 4 + 0) * NHW + qx] = expf(adj * (bx0 + box_predb[0]) + biasp[0]);
            out[((size_t)s * 4 + 1) * NHW + qx] = expf(adj * (bx1 + box_predb[1]) + biasp[1]);
            out[((size_t)s * 4 + 2) * NHW + qx] = expf(adj * (bx2 + box_predb[2]) + biasp[2]);
            out[((size_t)s * 4 + 3) * NHW + qx] = expf(adj * (bx3 + box_predb[3]) + biasp[3]);
        }
    }
}

extern "C" void kernel_launch(void* const* d_in, const int* in_sizes, int n_in,
                              void* d_out, int out_size)
{
    const float* search    = (const float*)d_in[0];
    const float* kern      = (const float*)d_in[1];
    const float* ca_w1     = (const float*)d_in[2];
    const float* ca_b1     = (const float*)d_in[3];
    const float* ca_w2     = (const float*)d_in[4];
    const float* ca_b2     = (const float*)d_in[5];
    const float* cls_dw    = (const float*)d_in[6];
    const float* cls_pw    = (const float*)d_in[7];
    const float* cls_bng   = (const float*)d_in[8];
    const float* cls_bnb   = (const float*)d_in[9];
    const float* cls_bnm   = (const float*)d_in[10];
    const float* cls_bnv   = (const float*)d_in[11];
    const float* cls_predw = (const float*)d_in[12];
    const float* cls_predb = (const float*)d_in[13];
    const float* box_dw    = (const float*)d_in[14];
    const float* box_pw    = (const float*)d_in[15];
    const float* box_bng   = (const float*)d_in[16];
    const float* box_bnb   = (const float*)d_in[17];
    const float* box_bnm   = (const float*)d_in[18];
    const float* box_bnv   = (const float*)d_in[19];
    const float* box_predw = (const float*)d_in[20];
    const float* box_predb = (const float*)d_in[21];
    const float* adjust    = (const float*)d_in[22];
    const float* biasp     = (const float*)d_in[23];

    const int sm1 = K1_TOT * 4;   // 135168 B
    const int sm2 = K2_TOT * 4;   // 193536 B
    cudaFuncSetAttribute(btl_k1, cudaFuncAttributeMaxDynamicSharedMemorySize, sm1);
    cudaFuncSetAttribute(btl_k2, cudaFuncAttributeMaxDynamicSharedMemorySize, sm2);

    btl_k1<<<NB, NT, sm1>>>(search, kern, ca_w1, ca_b1, ca_w2, ca_b2, cls_dw, box_dw);
    btl_k2<<<NB * 2, NT, sm2>>>(cls_pw, cls_bng, cls_bnb, cls_bnm, cls_bnv,
                                cls_predw, cls_predb,
                                box_pw, box_bng, box_bnb, box_bnm, box_bnv,
                                box_predw, box_predb,
                                adjust, biasp, (float*)d_out);
}

// round 12
// speedup vs baseline: 3.5456x; 1.6494x over previous
#include <cuda_runtime.h>
#include <cuda_fp16.h>
#include <math.h>

#define NB   512
#define NC   112
#define NP   64
#define NHW  256
#define NOC  256
#define CCH  16
#define NT1  1024   // K1 threads
#define K2NT 512    // K2 threads (16 warps)

typedef unsigned long long u64;
typedef unsigned int u32;

__device__ __forceinline__ u64 pk2(float lo, float hi) {
    u64 r; asm("mov.b64 %0, {%1,%2};" : "=l"(r) : "f"(lo), "f"(hi)); return r;
}
__device__ __forceinline__ void up2(u64 v, float& a, float& b) {
    asm("mov.b64 {%0,%1}, %2;" : "=f"(a), "=f"(b) : "l"(v));
}
__device__ __forceinline__ void fma2(u64& d, u64 a, u64 b) {
    asm("fma.rn.f32x2 %0, %1, %2, %0;" : "+l"(d) : "l"(a), "l"(b));
}

// dw scratch: [sample][tower][p 64][px 256] fp16
__device__ __half g_dw[(size_t)NB * 2 * NP * NHW];

// ======================= KERNEL 1 (unchanged from R11) =======================
#define K1_ATT  0
#define K1_H    64
#define K1_A    128
#define K1_DWC  192
#define K1_DWB  768
#define K1_CORR 7168
#define K1_STG  23552
#define K1_TOT  33792   // 135168 B

__global__ void __launch_bounds__(NT1, 1)
btl_k1(const float* __restrict__ search, const float* __restrict__ kern,
       const float* __restrict__ ca_w1, const float* __restrict__ ca_b1,
       const float* __restrict__ ca_w2, const float* __restrict__ ca_b2,
       const float* __restrict__ cls_dw, const float* __restrict__ box_dw)
{
    extern __shared__ float sm[];
    const int tid  = threadIdx.x;
    const int lane = tid & 31;
    const int warp = tid >> 5;
    const int b    = blockIdx.x;

    float* s_att  = sm + K1_ATT;
    float* s_h    = sm + K1_H;
    float* s_a    = sm + K1_A;
    float* s_corr = sm + K1_CORR;
    float* bufA   = sm + K1_STG;
    float* bufB   = sm + K1_STG + 5120;

    const float* gS = search + (size_t)b * NC * NHW;
    const float* gZ = kern   + (size_t)b * NC * NP;

    const int pg  = warp >> 2;
    const int pxq = warp & 3;
    const int pb  = pg * 8;
    const int pxb = pxq * 64 + lane * 2;

    u64 cacc[4][2];
#pragma unroll
    for (int j = 0; j < 4; j++) { cacc[j][0] = 0ull; cacc[j][1] = 0ull; }

    ((float4*)bufA)[tid] = ((const float4*)gS)[tid];
    bufA[4096 + tid] = gZ[tid];
    __syncthreads();

    int sbsel = 0;
    for (int chk = 0; chk < 7; chk++) {
        float4 pre4; float prez;
        if (chk < 6) {
            pre4 = ((const float4*)(gS + (chk + 1) * CCH * NHW))[tid];
            prez = (gZ + (chk + 1) * CCH * NP)[tid];
        }
        const float* sbuf = sbsel ? bufB : bufA;
        const float* szb  = sbuf + 4096;
#pragma unroll 4
        for (int cc = 0; cc < CCH; cc++) {
            const float* zp = szb + cc * NP + pb;
            ulonglong2 zA = *(const ulonglong2*)zp;
            ulonglong2 zB = *(const ulonglong2*)(zp + 4);
            u64 zr[4] = {zA.x, zA.y, zB.x, zB.y};
            u64 xp = *(const u64*)(sbuf + cc * NHW + pxb);
            float x0, x1; up2(xp, x0, x1);
            u64 xd0 = pk2(x0, x0), xd1 = pk2(x1, x1);
#pragma unroll
            for (int j = 0; j < 4; j++) {
                fma2(cacc[j][0], zr[j], xd0);
                fma2(cacc[j][1], zr[j], xd1);
            }
        }
        if (chk < 6) {
            float* dbuf = sbsel ? bufA : bufB;
            ((float4*)dbuf)[tid] = pre4;
            dbuf[4096 + tid] = prez;
        }
        __syncthreads();
        sbsel ^= 1;
    }

#pragma unroll
    for (int j = 0; j < 4; j++) {
        float a00, a01, a10, a11;
        up2(cacc[j][0], a00, a01);
        up2(cacc[j][1], a10, a11);
        *(u64*)(s_corr + (pb + 2 * j)     * NHW + pxb) = pk2(a00, a10);
        *(u64*)(s_corr + (pb + 2 * j + 1) * NHW + pxb) = pk2(a01, a11);
    }
    __syncthreads();

    {
        const int p0 = warp * 2;
#pragma unroll
        for (int j = 0; j < 2; j++) {
            const int p = p0 + j;
            float ps = 0.0f;
#pragma unroll
            for (int i = 0; i < 8; i++) ps += s_corr[p * NHW + lane + 32 * i];
#pragma unroll
            for (int o = 16; o > 0; o >>= 1) ps += __shfl_xor_sync(0xffffffffu, ps, o);
            if (lane == 0) s_att[p] = ps * (1.0f / 256.0f);
        }
    }
    for (int i = tid; i < NP * 9; i += NT1) {
        sm[K1_DWC + i] = cls_dw[i];
        sm[K1_DWB + i] = box_dw[i];
    }
    __syncthreads();

    if (tid < 64) {
        float s1 = ca_b1[tid];
        const float* w = ca_w1 + tid * 64;
#pragma unroll 8
        for (int j = 0; j < 64; j++) s1 = fmaf(w[j], s_att[j], s1);
        s_h[tid] = fmaxf(s1, 0.0f);
    }
    __syncthreads();
    if (tid < 64) {
        float s2 = ca_b2[tid];
        const float* w = ca_w2 + tid * 64;
#pragma unroll 8
        for (int j = 0; j < 64; j++) s2 = fmaf(w[j], s_h[j], s2);
        s_a[tid] = 1.0f / (1.0f + expf(-s2));
    }
    __syncthreads();

    {
        const int px = tid & 255, pq = tid >> 8;
        const int y = px >> 4, x = px & 15;
        const bool okU = y > 0, okD = y < 15, okL = x > 0, okR = x < 15;
        __half* dc = g_dw + ((size_t)b * 2)     * (NP * NHW) + px;
        __half* db = g_dw + ((size_t)b * 2 + 1) * (NP * NHW) + px;
#pragma unroll 2
        for (int pi = 0; pi < 16; pi++) {
            const int p = pq * 16 + pi;
            const float* r = s_corr + p * NHW + px;
            float nv[9];
            nv[4] = r[0];
            nv[1] = okU ? r[-16] : 0.0f;
            nv[0] = (okU && okL) ? r[-17] : 0.0f;
            nv[2] = (okU && okR) ? r[-15] : 0.0f;
            nv[7] = okD ? r[16] : 0.0f;
            nv[6] = (okD && okL) ? r[15] : 0.0f;
            nv[8] = (okD && okR) ? r[17] : 0.0f;
            nv[3] = okL ? r[-1] : 0.0f;
            nv[5] = okR ? r[1] : 0.0f;
            const float* wc = sm + K1_DWC + p * 9;
            const float* wb = sm + K1_DWB + p * 9;
            float ac = 0.0f, ab = 0.0f;
#pragma unroll
            for (int k = 0; k < 9; k++) {
                ac = fmaf(nv[k], wc[k], ac);
                ab = fmaf(nv[k], wb[k], ab);
            }
            const float a = s_a[p];
            dc[p * NHW] = __float2half_rn(ac * a);
            db[p * NHW] = __float2half_rn(ab * a);
        }
    }
}

// ======================= KERNEL 2: mma.sync pointwise GEMM =======================
// smem float offsets:
#define K2_BNSC 0       // 256
#define K2_BNSH 256     // 256
#define K2_WP   512     // 5120
#define K2_DW   5632    // 8448 u32 = dw fp16 [64][264 halves] (528B rows)
#define K2_PWT  14080   // 4608 u32 = pwt fp16 [128][72 halves] (144B rows)
#define K2_FT   18688   // 16896 u32 = ft fp16 [128][264 halves]
#define K2_PB   35584   // 18432 f32 (= 9216 u64) partial buffers
#define K2_TOT  54016   // 216064 B

__device__ __forceinline__ u32 saddr(const void* p) {
    return (u32)__cvta_generic_to_shared(p);
}

// pointwise GEMM pass via mma.sync: 128o x 256px, K=64, fp16 in, fp32 acc
__device__ __forceinline__ void gemm_mma(float* sm, int lane, int warp, int o_base)
{
    const u32 pwt_b = saddr(sm + K2_PWT);
    const u32 dw_b  = saddr(sm + K2_DW);
    u32* s_ft = (u32*)(sm + K2_FT);
    const float* s_bnsc = sm + K2_BNSC;
    const float* s_bnsh = sm + K2_BNSH;

    const int mt = warp >> 1, h = warp & 1;
    const int m0 = mt * 16;
    const int g  = lane >> 2, t4 = lane & 3;

    // A fragments (loaded once)
    u32 A[4][4];
    {
        const u32 aoff = pwt_b
            + (u32)(m0 + (lane & 7) + ((lane >> 3) & 1) * 8) * 144u
            + (u32)((lane >> 4) & 1) * 16u;
#pragma unroll
        for (int ks = 0; ks < 4; ks++) {
            asm volatile("ldmatrix.sync.aligned.m8n8.x4.shared.b16 {%0,%1,%2,%3}, [%4];"
                : "=r"(A[ks][0]), "=r"(A[ks][1]), "=r"(A[ks][2]), "=r"(A[ks][3])
                : "r"(aoff + (u32)ks * 32u));
        }
    }

    const float sc0 = s_bnsc[o_base + m0 + g],     sh0 = s_bnsh[o_base + m0 + g];
    const float sc1 = s_bnsc[o_base + m0 + g + 8], sh1 = s_bnsh[o_base + m0 + g + 8];
    const u32 boff = dw_b + (u32)(lane & 15) * 528u + (u32)h * 256u;

#pragma unroll 4
    for (int nt = 0; nt < 16; nt++) {
        float c0 = 0.f, c1 = 0.f, c2 = 0.f, c3 = 0.f;
#pragma unroll
        for (int ks = 0; ks < 4; ks++) {
            u32 b0, b1;
            asm volatile("ldmatrix.sync.aligned.m8n8.x2.trans.shared.b16 {%0,%1}, [%2];"
                : "=r"(b0), "=r"(b1)
                : "r"(boff + (u32)ks * 8448u + (u32)nt * 16u));
            asm volatile(
                "mma.sync.aligned.m16n8k16.row.col.f32.f16.f16.f32 "
                "{%0,%1,%2,%3}, {%4,%5,%6,%7}, {%8,%9}, {%0,%1,%2,%3};"
                : "+f"(c0), "+f"(c1), "+f"(c2), "+f"(c3)
                : "r"(A[ks][0]), "r"(A[ks][1]), "r"(A[ks][2]), "r"(A[ks][3]),
                  "r"(b0), "r"(b1));
        }
        // BN + ReLU -> ft fp16
        c0 = fmaxf(fmaf(c0, sc0, sh0), 0.0f);
        c1 = fmaxf(fmaf(c1, sc0, sh0), 0.0f);
        c2 = fmaxf(fmaf(c2, sc1, sh1), 0.0f);
        c3 = fmaxf(fmaf(c3, sc1, sh1), 0.0f);
        __half2 p01 = __floats2half2_rn(c0, c1);
        __half2 p23 = __floats2half2_rn(c2, c3);
        const int n0h = h * 64 + nt * 4;
        s_ft[(m0 + g)     * 132 + n0h + t4] = *(u32*)&p01;
        s_ft[(m0 + g + 8) * 132 + n0h + t4] = *(u32*)&p23;
    }
}

__global__ void __launch_bounds__(K2NT, 1)
btl_k2(const float* __restrict__ cls_pw,
       const float* __restrict__ cls_bng, const float* __restrict__ cls_bnb,
       const float* __restrict__ cls_bnm, const float* __restrict__ cls_bnv,
       const float* __restrict__ cls_predw, const float* __restrict__ cls_predb,
       const float* __restrict__ box_pw,
       const float* __restrict__ box_bng, const float* __restrict__ box_bnb,
       const float* __restrict__ box_bnm, const float* __restrict__ box_bnv,
       const float* __restrict__ box_predw, const float* __restrict__ box_predb,
       const float* __restrict__ adjust, const float* __restrict__ biasp,
       float* __restrict__ out)
{
    extern __shared__ float sm[];
    const int tid  = threadIdx.x;
    const int lane = tid & 31;
    const int warp = tid >> 5;
    const int s    = blockIdx.x >> 1;
    const int t    = blockIdx.x & 1;

    // stage dw fp16 -> padded [64][132 u32]
    {
        const u32* src = (const u32*)(g_dw + ((size_t)s * 2 + t) * (NP * NHW));
        u32* dst = (u32*)(sm + K2_DW);
#pragma unroll
        for (int j = 0; j < 16; j++) {
            int i = tid + j * K2NT;
            dst[(i >> 7) * 132 + (i & 127)] = src[i];
        }
    }
    if (tid < NOC) {
        const float* bng = t ? box_bng : cls_bng;
        const float* bnb = t ? box_bnb : cls_bnb;
        const float* bnm = t ? box_bnm : cls_bnm;
        const float* bnv = t ? box_bnv : cls_bnv;
        float sc = bng[tid] * rsqrtf(bnv[tid] + 1e-5f);
        sm[K2_BNSC + tid] = sc;
        sm[K2_BNSH + tid] = bnb[tid] - bnm[tid] * sc;
    }
    __syncthreads();

    float* s_wp = sm + K2_WP;
    const float* pwW = t ? box_pw : cls_pw;

    if (t == 0) {
        // ---------------- CLS tower ----------------
        u64 Sc[5];
#pragma unroll
        for (int i = 0; i < 5; i++) Sc[i] = 0ull;
        const unsigned short* fth = (const unsigned short*)(sm + K2_FT);
        const int px = tid & 255, cq = tid >> 8;   // cq in 0..1

        for (int p = 0; p < 2; p++) {
            // stage pwt fp16 [128][72] (u32 half2 stores, kpair layout)
            {
                u32* pd = (u32*)(sm + K2_PWT);
#pragma unroll
                for (int j = 0; j < 8; j++) {
                    int i = tid + j * K2NT;
                    int o = i >> 5, kp = i & 31;
                    const float* wsrc = pwW + (p * 128 + o) * 64 + 2 * kp;
                    __half2 hv = __floats2half2_rn(wsrc[0], wsrc[1]);
                    pd[o * 36 + kp] = *(u32*)&hv;
                }
            }
            for (int i = tid; i < 1536; i += K2NT) {
                int c = i / 12, k = i % 12;
                s_wp[i] = (k < 9) ? cls_predw[(p * 128 + c) * 9 + k] : 0.0f;
            }
            __syncthreads();

            gemm_mma(sm, lane, warp, p * 128);
            __syncthreads();

            // tap: cq covers 64 c per pass; S accumulates across passes
#pragma unroll 2
            for (int ci = 0; ci < 64; ci++) {
                const int c = cq * 64 + ci;
                float xv = __half2float(__ushort_as_half(fth[c * 264 + px]));
                const u64 xd = pk2(xv, xv);
                const ulonglong2* wp2 = (const ulonglong2*)(s_wp + c * 12);
                ulonglong2 wA = wp2[0];
                ulonglong2 wB = wp2[1];
                float w8 = s_wp[c * 12 + 8];
                fma2(Sc[0], xd, wA.x);
                fma2(Sc[1], xd, wA.y);
                fma2(Sc[2], xd, wB.x);
                fma2(Sc[3], xd, wB.y);
                fma2(Sc[4], xd, pk2(w8, 0.0f));
            }
            __syncthreads();
        }

        // single merge: 2 disjoint buffers by cq
        float* Pc = sm + K2_PB + cq * (9 * 256);
#pragma unroll
        for (int kp = 0; kp < 4; kp++) {
            float a0, a1; up2(Sc[kp], a0, a1);
            Pc[(2 * kp) * 256 + px]     = a0;
            Pc[(2 * kp + 1) * 256 + px] = a1;
        }
        { float a0, a1; up2(Sc[4], a0, a1);
          Pc[8 * 256 + px] = a0; }
        __syncthreads();

        if (tid < 256) {
            const int qx = tid, y = qx >> 4, x = qx & 15;
            const float* P0 = sm + K2_PB;
            const float* P1 = sm + K2_PB + 9 * 256;
            float acc = 0.0f;
#pragma unroll
            for (int dy = -1; dy <= 1; dy++) {
                if (y + dy < 0 || y + dy > 15) continue;
#pragma unroll
                for (int dx = -1; dx <= 1; dx++) {
                    if (x + dx < 0 || x + dx > 15) continue;
                    const int k = (dy + 1) * 3 + (dx + 1);
                    const int q = qx + dy * 16 + dx;
                    acc += P0[k * 256 + q] + P1[k * 256 + q];
                }
            }
            out[(size_t)NB * 4 * NHW + (size_t)s * NHW + qx] =
                0.1f * (acc + cls_predb[0]);
        }
    } else {
        // ---------------- BOX tower ----------------
        const u32* ftp32 = (const u32*)(sm + K2_FT);
        const int pp = tid & 127;
        const int grp = tid >> 7;
        const int op = grp & 1, ch = grp >> 1;   // ch in 0..1

        u64 S[18];
#pragma unroll
        for (int i = 0; i < 18; i++) S[i] = 0ull;

        for (int p = 0; p < 2; p++) {
            {
                u32* pd = (u32*)(sm + K2_PWT);
#pragma unroll
                for (int j = 0; j < 8; j++) {
                    int i = tid + j * K2NT;
                    int o = i >> 5, kp = i & 31;
                    const float* wsrc = pwW + (p * 128 + o) * 64 + 2 * kp;
                    __half2 hv = __floats2half2_rn(wsrc[0], wsrc[1]);
                    pd[o * 36 + kp] = *(u32*)&hv;
                }
            }
            for (int i = tid; i < 5120; i += K2NT) {
                int c = i / 40, r = i % 40, o2 = r / 20, tt = r % 20;
                float v = 0.0f;
                if (tt < 18) {
                    int k = tt >> 1, hh = tt & 1;
                    v = box_predw[(o2 * 2 + hh) * 2304 + (p * 128 + c) * 9 + k];
                }
                s_wp[i] = v;
            }
            __syncthreads();

            gemm_mma(sm, lane, warp, p * 128);
            __syncthreads();

            // tap: (ch of 64c, op, px-pair); S persists across passes
#pragma unroll 2
            for (int ci = 0; ci < 64; ci++) {
                const int c = ch * 64 + ci;
                u32 xw = ftp32[c * 132 + pp];
                float2 xf = __half22float2(*(__half2*)&xw);
                const u64 xd0 = pk2(xf.x, xf.x), xd1 = pk2(xf.y, xf.y);
                const float* wb = s_wp + (c * 2 + op) * 20;
                const ulonglong2* w2 = (const ulonglong2*)wb;
                ulonglong2 wa = w2[0], wc = w2[1], wd = w2[2], we = w2[3];
                u64 w8 = *(const u64*)(wb + 16);
                fma2(S[0], wa.x, xd0);  fma2(S[1], wa.x, xd1);
                fma2(S[2], wa.y, xd0);  fma2(S[3], wa.y, xd1);
                fma2(S[4], wc.x, xd0);  fma2(S[5], wc.x, xd1);
                fma2(S[6], wc.y, xd0);  fma2(S[7], wc.y, xd1);
                fma2(S[8], wd.x, xd0);  fma2(S[9], wd.x, xd1);
                fma2(S[10], wd.y, xd0); fma2(S[11], wd.y, xd1);
                fma2(S[12], we.x, xd0); fma2(S[13], we.x, xd1);
                fma2(S[14], we.y, xd0); fma2(S[15], we.y, xd1);
                fma2(S[16], w8, xd0);   fma2(S[17], w8, xd1);
            }
            __syncthreads();
        }

        // single merge: 2 disjoint u64 buffers by ch
        {
            u64* Pb = (u64*)(sm + K2_PB) + (size_t)ch * 4608;
#pragma unroll
            for (int k = 0; k < 9; k++) {
                *(ulonglong2*)(Pb + (op * 9 + k) * 256 + 2 * pp) =
                    make_ulonglong2(S[2 * k], S[2 * k + 1]);
            }
        }
        __syncthreads();

        if (tid < 256) {
            const int qx = tid, y = qx >> 4, x = qx & 15;
            const u64* P0 = (const u64*)(sm + K2_PB);
            const u64* P1 = P0 + 4608;
            float bx0 = 0.f, bx1 = 0.f, bx2 = 0.f, bx3 = 0.f;
#pragma unroll
            for (int dy = -1; dy <= 1; dy++) {
                if (y + dy < 0 || y + dy > 15) continue;
#pragma unroll
                for (int dx = -1; dx <= 1; dx++) {
                    if (x + dx < 0 || x + dx > 15) continue;
                    const int k = (dy + 1) * 3 + (dx + 1);
                    const int q = qx + dy * 16 + dx;
                    float a0, a1, a2, a3;
                    up2(P0[(k) * 256 + 2 * (q >> 1) + (q & 1)] , a0, a1);
                    // NOTE: entries indexed by px-pair: q -> pair q>>1, half q&1
                    // u64 holds (oc_lo, oc_hi) for one px; recompute properly:
                    (void)a0; (void)a1;
                    u64 e0a = P0[(0 * 9 + k) * 256 + q];
                    u64 e0b = P0[(1 * 9 + k) * 256 + q];
                    u64 e1a = P1[(0 * 9 + k) * 256 + q];
                    u64 e1b = P1[(1 * 9 + k) * 256 + q];
                    float u, v;
                    up2(e0a, u, v); bx0 += u; bx1 += v;
                    up2(e1a, u, v); bx0 += u; bx1 += v;
                    up2(e0b, u, v); bx2 += u; bx3 += v;
                    up2(e1b, u, v); bx2 += u; bx3 += v;
                    up2(e0a, a2, a3); (void)a2; (void)a3;
                }
            }
            const float adj = adjust[0];
            out[((size_t)s * 4 + 0) * NHW + qx] = expf(adj * (bx0 + box_predb[0]) + biasp[0]);
            out[((size_t)s * 4 + 1) * NHW + qx] = expf(adj * (bx1 + box_predb[1]) + biasp[1]);
            out[((size_t)s * 4 + 2) * NHW + qx] = expf(adj * (bx2 + box_predb[2]) + biasp[2]);
            out[((size_t)s * 4 + 3) * NHW + qx] = expf(adj * (bx3 + box_predb[3]) + biasp[3]);
        }
    }
}

extern "C" void kernel_launch(void* const* d_in, const int* in_sizes, int n_in,
                              void* d_out, int out_size)
{
    const float* search    = (const float*)d_in[0];
    const float* kern      = (const float*)d_in[1];
    const float* ca_w1     = (const float*)d_in[2];
    const float* ca_b1     = (const float*)d_in[3];
    const float* ca_w2     = (const float*)d_in[4];
    const float* ca_b2     = (const float*)d_in[5];
    const float* cls_dw    = (const float*)d_in[6];
    const float* cls_pw    = (const float*)d_in[7];
    const float* cls_bng   = (const float*)d_in[8];
    const float* cls_bnb   = (const float*)d_in[9];
    const float* cls_bnm   = (const float*)d_in[10];
    const float* cls_bnv   = (const float*)d_in[11];
    const float* cls_predw = (const float*)d_in[12];
    const float* cls_predb = (const float*)d_in[13];
    const float* box_dw    = (const float*)d_in[14];
    const float* box_pw    = (const float*)d_in[15];
    const float* box_bng   = (const float*)d_in[16];
    const float* box_bnb   = (const float*)d_in[17];
    const float* box_bnm   = (const float*)d_in[18];
    const float* box_bnv   = (const float*)d_in[19];
    const float* box_predw = (const float*)d_in[20];
    const float* box_predb = (const float*)d_in[21];
    const float* adjust    = (const float*)d_in[22];
    const float* biasp     = (const float*)d_in[23];

    const int sm1 = K1_TOT * 4;   // 135168 B
    const int sm2 = K2_TOT * 4;   // 216064 B
    cudaFuncSetAttribute(btl_k1, cudaFuncAttributeMaxDynamicSharedMemorySize, sm1);
    cudaFuncSetAttribute(btl_k2, cudaFuncAttributeMaxDynamicSharedMemorySize, sm2);

    btl_k1<<<NB, NT1, sm1>>>(search, kern, ca_w1, ca_b1, ca_w2, ca_b2, cls_dw, box_dw);
    btl_k2<<<NB * 2, K2NT, sm2>>>(cls_pw, cls_bng, cls_bnb, cls_bnm, cls_bnv,
                                  cls_predw, cls_predb,
                                  box_pw, box_bng, box_bnb, box_bnm, box_bnv,
                                  box_predw, box_predb,
                                  adjust, biasp, (float*)d_out);
}

// round 13
// speedup vs baseline: 4.4786x; 1.2631x over previous
#include <cuda_runtime.h>
#include <cuda_fp16.h>
#include <math.h>

#define NB   512
#define NC   112
#define NP   64
#define NHW  256
#define NOC  256
#define CCH  16
#define NT1  1024   // K1 threads
#define K2NT 512    // K2 threads (16 warps)

typedef unsigned long long u64;
typedef unsigned int u32;

__device__ __forceinline__ u64 pk2(float lo, float hi) {
    u64 r; asm("mov.b64 %0, {%1,%2};" : "=l"(r) : "f"(lo), "f"(hi)); return r;
}
__device__ __forceinline__ void up2(u64 v, float& a, float& b) {
    asm("mov.b64 {%0,%1}, %2;" : "=f"(a), "=f"(b) : "l"(v));
}
__device__ __forceinline__ void fma2(u64& d, u64 a, u64 b) {
    asm("fma.rn.f32x2 %0, %1, %2, %0;" : "+l"(d) : "l"(a), "l"(b));
}

// dw scratch: [sample][tower][p 64][px 256] fp16
__device__ __half g_dw[(size_t)NB * 2 * NP * NHW];

// ======================= KERNEL 1 (unchanged) =======================
#define K1_ATT  0
#define K1_H    64
#define K1_A    128
#define K1_DWC  192
#define K1_DWB  768
#define K1_CORR 7168
#define K1_STG  23552
#define K1_TOT  33792   // 135168 B

__global__ void __launch_bounds__(NT1, 1)
btl_k1(const float* __restrict__ search, const float* __restrict__ kern,
       const float* __restrict__ ca_w1, const float* __restrict__ ca_b1,
       const float* __restrict__ ca_w2, const float* __restrict__ ca_b2,
       const float* __restrict__ cls_dw, const float* __restrict__ box_dw)
{
    extern __shared__ float sm[];
    const int tid  = threadIdx.x;
    const int lane = tid & 31;
    const int warp = tid >> 5;
    const int b    = blockIdx.x;

    float* s_att  = sm + K1_ATT;
    float* s_h    = sm + K1_H;
    float* s_a    = sm + K1_A;
    float* s_corr = sm + K1_CORR;
    float* bufA   = sm + K1_STG;
    float* bufB   = sm + K1_STG + 5120;

    const float* gS = search + (size_t)b * NC * NHW;
    const float* gZ = kern   + (size_t)b * NC * NP;

    const int pg  = warp >> 2;
    const int pxq = warp & 3;
    const int pb  = pg * 8;
    const int pxb = pxq * 64 + lane * 2;

    u64 cacc[4][2];
#pragma unroll
    for (int j = 0; j < 4; j++) { cacc[j][0] = 0ull; cacc[j][1] = 0ull; }

    ((float4*)bufA)[tid] = ((const float4*)gS)[tid];
    bufA[4096 + tid] = gZ[tid];
    __syncthreads();

    int sbsel = 0;
    for (int chk = 0; chk < 7; chk++) {
        float4 pre4; float prez;
        if (chk < 6) {
            pre4 = ((const float4*)(gS + (chk + 1) * CCH * NHW))[tid];
            prez = (gZ + (chk + 1) * CCH * NP)[tid];
        }
        const float* sbuf = sbsel ? bufB : bufA;
        const float* szb  = sbuf + 4096;
#pragma unroll 4
        for (int cc = 0; cc < CCH; cc++) {
            const float* zp = szb + cc * NP + pb;
            ulonglong2 zA = *(const ulonglong2*)zp;
            ulonglong2 zB = *(const ulonglong2*)(zp + 4);
            u64 zr[4] = {zA.x, zA.y, zB.x, zB.y};
            u64 xp = *(const u64*)(sbuf + cc * NHW + pxb);
            float x0, x1; up2(xp, x0, x1);
            u64 xd0 = pk2(x0, x0), xd1 = pk2(x1, x1);
#pragma unroll
            for (int j = 0; j < 4; j++) {
                fma2(cacc[j][0], zr[j], xd0);
                fma2(cacc[j][1], zr[j], xd1);
            }
        }
        if (chk < 6) {
            float* dbuf = sbsel ? bufA : bufB;
            ((float4*)dbuf)[tid] = pre4;
            dbuf[4096 + tid] = prez;
        }
        __syncthreads();
        sbsel ^= 1;
    }

#pragma unroll
    for (int j = 0; j < 4; j++) {
        float a00, a01, a10, a11;
        up2(cacc[j][0], a00, a01);
        up2(cacc[j][1], a10, a11);
        *(u64*)(s_corr + (pb + 2 * j)     * NHW + pxb) = pk2(a00, a10);
        *(u64*)(s_corr + (pb + 2 * j + 1) * NHW + pxb) = pk2(a01, a11);
    }
    __syncthreads();

    {
        const int p0 = warp * 2;
#pragma unroll
        for (int j = 0; j < 2; j++) {
            const int p = p0 + j;
            float ps = 0.0f;
#pragma unroll
            for (int i = 0; i < 8; i++) ps += s_corr[p * NHW + lane + 32 * i];
#pragma unroll
            for (int o = 16; o > 0; o >>= 1) ps += __shfl_xor_sync(0xffffffffu, ps, o);
            if (lane == 0) s_att[p] = ps * (1.0f / 256.0f);
        }
    }
    for (int i = tid; i < NP * 9; i += NT1) {
        sm[K1_DWC + i] = cls_dw[i];
        sm[K1_DWB + i] = box_dw[i];
    }
    __syncthreads();

    if (tid < 64) {
        float s1 = ca_b1[tid];
        const float* w = ca_w1 + tid * 64;
#pragma unroll 8
        for (int j = 0; j < 64; j++) s1 = fmaf(w[j], s_att[j], s1);
        s_h[tid] = fmaxf(s1, 0.0f);
    }
    __syncthreads();
    if (tid < 64) {
        float s2 = ca_b2[tid];
        const float* w = ca_w2 + tid * 64;
#pragma unroll 8
        for (int j = 0; j < 64; j++) s2 = fmaf(w[j], s_h[j], s2);
        s_a[tid] = 1.0f / (1.0f + expf(-s2));
    }
    __syncthreads();

    {
        const int px = tid & 255, pq = tid >> 8;
        const int y = px >> 4, x = px & 15;
        const bool okU = y > 0, okD = y < 15, okL = x > 0, okR = x < 15;
        __half* dc = g_dw + ((size_t)b * 2)     * (NP * NHW) + px;
        __half* db = g_dw + ((size_t)b * 2 + 1) * (NP * NHW) + px;
#pragma unroll 2
        for (int pi = 0; pi < 16; pi++) {
            const int p = pq * 16 + pi;
            const float* r = s_corr + p * NHW + px;
            float nv[9];
            nv[4] = r[0];
            nv[1] = okU ? r[-16] : 0.0f;
            nv[0] = (okU && okL) ? r[-17] : 0.0f;
            nv[2] = (okU && okR) ? r[-15] : 0.0f;
            nv[7] = okD ? r[16] : 0.0f;
            nv[6] = (okD && okL) ? r[15] : 0.0f;
            nv[8] = (okD && okR) ? r[17] : 0.0f;
            nv[3] = okL ? r[-1] : 0.0f;
            nv[5] = okR ? r[1] : 0.0f;
            const float* wc = sm + K1_DWC + p * 9;
            const float* wb = sm + K1_DWB + p * 9;
            float ac = 0.0f, ab = 0.0f;
#pragma unroll
            for (int k = 0; k < 9; k++) {
                ac = fmaf(nv[k], wc[k], ac);
                ab = fmaf(nv[k], wb[k], ab);
            }
            const float a = s_a[p];
            dc[p * NHW] = __float2half_rn(ac * a);
            db[p * NHW] = __float2half_rn(ab * a);
        }
    }
}

// ======================= KERNEL 2 =======================
#define K2_BNSC 0       // 256
#define K2_BNSH 256     // 256
#define K2_WP   512     // cls pred f32 (1536); box: A_tap fp16 [48][136h] (3264 u32)
#define K2_DW   5632    // 8448 u32 = dw fp16 [64][132 u32] (528B rows)
#define K2_PWT  14080   // 4608 u32 = pwt fp16 [128][36 u32] (144B rows)
#define K2_FT   18688   // 16896 u32 = ft fp16 [128][132 u32]
#define K2_PB   35584   // cls: 2x9x256 f; box: P[48][256] f = 12288
#define K2_TOT  47872   // 191488 B

__device__ __forceinline__ u32 saddr(const void* p) {
    return (u32)__cvta_generic_to_shared(p);
}

// pointwise GEMM pass via mma.sync: 128o x 256px, K=64, fp16 in, fp32 acc
__device__ __forceinline__ void gemm_mma(float* sm, int lane, int warp, int o_base)
{
    const u32 pwt_b = saddr(sm + K2_PWT);
    const u32 dw_b  = saddr(sm + K2_DW);
    u32* s_ft = (u32*)(sm + K2_FT);
    const float* s_bnsc = sm + K2_BNSC;
    const float* s_bnsh = sm + K2_BNSH;

    const int mt = warp >> 1, h = warp & 1;
    const int m0 = mt * 16;
    const int g  = lane >> 2, t4 = lane & 3;

    u32 A[4][4];
    {
        const u32 aoff = pwt_b
            + (u32)(m0 + (lane & 7) + ((lane >> 3) & 1) * 8) * 144u
            + (u32)((lane >> 4) & 1) * 16u;
#pragma unroll
        for (int ks = 0; ks < 4; ks++) {
            asm volatile("ldmatrix.sync.aligned.m8n8.x4.shared.b16 {%0,%1,%2,%3}, [%4];"
                : "=r"(A[ks][0]), "=r"(A[ks][1]), "=r"(A[ks][2]), "=r"(A[ks][3])
                : "r"(aoff + (u32)ks * 32u));
        }
    }

    const float sc0 = s_bnsc[o_base + m0 + g],     sh0 = s_bnsh[o_base + m0 + g];
    const float sc1 = s_bnsc[o_base + m0 + g + 8], sh1 = s_bnsh[o_base + m0 + g + 8];
    const u32 boff = dw_b + (u32)(lane & 15) * 528u + (u32)h * 256u;

#pragma unroll 4
    for (int nt = 0; nt < 16; nt++) {
        float c0 = 0.f, c1 = 0.f, c2 = 0.f, c3 = 0.f;
#pragma unroll
        for (int ks = 0; ks < 4; ks++) {
            u32 b0, b1;
            asm volatile("ldmatrix.sync.aligned.m8n8.x2.trans.shared.b16 {%0,%1}, [%2];"
                : "=r"(b0), "=r"(b1)
                : "r"(boff + (u32)ks * 8448u + (u32)nt * 16u));
            asm volatile(
                "mma.sync.aligned.m16n8k16.row.col.f32.f16.f16.f32 "
                "{%0,%1,%2,%3}, {%4,%5,%6,%7}, {%8,%9}, {%0,%1,%2,%3};"
                : "+f"(c0), "+f"(c1), "+f"(c2), "+f"(c3)
                : "r"(A[ks][0]), "r"(A[ks][1]), "r"(A[ks][2]), "r"(A[ks][3]),
                  "r"(b0), "r"(b1));
        }
        c0 = fmaxf(fmaf(c0, sc0, sh0), 0.0f);
        c1 = fmaxf(fmaf(c1, sc0, sh0), 0.0f);
        c2 = fmaxf(fmaf(c2, sc1, sh1), 0.0f);
        c3 = fmaxf(fmaf(c3, sc1, sh1), 0.0f);
        __half2 p01 = __floats2half2_rn(c0, c1);
        __half2 p23 = __floats2half2_rn(c2, c3);
        const int n0h = h * 64 + nt * 4;
        s_ft[(m0 + g)     * 132 + n0h + t4] = *(u32*)&p01;
        s_ft[(m0 + g + 8) * 132 + n0h + t4] = *(u32*)&p23;
    }
}

__global__ void __launch_bounds__(K2NT, 1)
btl_k2(const float* __restrict__ cls_pw,
       const float* __restrict__ cls_bng, const float* __restrict__ cls_bnb,
       const float* __restrict__ cls_bnm, const float* __restrict__ cls_bnv,
       const float* __restrict__ cls_predw, const float* __restrict__ cls_predb,
       const float* __restrict__ box_pw,
       const float* __restrict__ box_bng, const float* __restrict__ box_bnb,
       const float* __restrict__ box_bnm, const float* __restrict__ box_bnv,
       const float* __restrict__ box_predw, const float* __restrict__ box_predb,
       const float* __restrict__ adjust, const float* __restrict__ biasp,
       float* __restrict__ out)
{
    extern __shared__ float sm[];
    const int tid  = threadIdx.x;
    const int lane = tid & 31;
    const int warp = tid >> 5;
    const int s    = blockIdx.x >> 1;
    const int t    = blockIdx.x & 1;

    // stage dw fp16 -> padded [64][132 u32]
    {
        const u32* src = (const u32*)(g_dw + ((size_t)s * 2 + t) * (NP * NHW));
        u32* dst = (u32*)(sm + K2_DW);
#pragma unroll
        for (int j = 0; j < 16; j++) {
            int i = tid + j * K2NT;
            dst[(i >> 7) * 132 + (i & 127)] = src[i];
        }
    }
    if (tid < NOC) {
        const float* bng = t ? box_bng : cls_bng;
        const float* bnb = t ? box_bnb : cls_bnb;
        const float* bnm = t ? box_bnm : cls_bnm;
        const float* bnv = t ? box_bnv : cls_bnv;
        float sc = bng[tid] * rsqrtf(bnv[tid] + 1e-5f);
        sm[K2_BNSC + tid] = sc;
        sm[K2_BNSH + tid] = bnb[tid] - bnm[tid] * sc;
    }
    __syncthreads();

    const float* pwW = t ? box_pw : cls_pw;

    if (t == 0) {
        // ---------------- CLS tower (unchanged) ----------------
        float* s_wp = sm + K2_WP;
        u64 Sc[5];
#pragma unroll
        for (int i = 0; i < 5; i++) Sc[i] = 0ull;
        const unsigned short* fth = (const unsigned short*)(sm + K2_FT);
        const int px = tid & 255, cq = tid >> 8;

        for (int p = 0; p < 2; p++) {
            {
                u32* pd = (u32*)(sm + K2_PWT);
#pragma unroll
                for (int j = 0; j < 8; j++) {
                    int i = tid + j * K2NT;
                    int o = i >> 5, kp = i & 31;
                    const float* wsrc = pwW + (p * 128 + o) * 64 + 2 * kp;
                    __half2 hv = __floats2half2_rn(wsrc[0], wsrc[1]);
                    pd[o * 36 + kp] = *(u32*)&hv;
                }
            }
            for (int i = tid; i < 1536; i += K2NT) {
                int c = i / 12, k = i % 12;
                s_wp[i] = (k < 9) ? cls_predw[(p * 128 + c) * 9 + k] : 0.0f;
            }
            __syncthreads();

            gemm_mma(sm, lane, warp, p * 128);
            __syncthreads();

#pragma unroll 2
            for (int ci = 0; ci < 64; ci++) {
                const int c = cq * 64 + ci;
                float xv = __half2float(__ushort_as_half(fth[c * 264 + px]));
                const u64 xd = pk2(xv, xv);
                const ulonglong2* wp2 = (const ulonglong2*)(s_wp + c * 12);
                ulonglong2 wA = wp2[0];
                ulonglong2 wB = wp2[1];
                float w8 = s_wp[c * 12 + 8];
                fma2(Sc[0], xd, wA.x);
                fma2(Sc[1], xd, wA.y);
                fma2(Sc[2], xd, wB.x);
                fma2(Sc[3], xd, wB.y);
                fma2(Sc[4], xd, pk2(w8, 0.0f));
            }
            __syncthreads();
        }

        float* Pc = sm + K2_PB + cq * (9 * 256);
#pragma unroll
        for (int kp = 0; kp < 4; kp++) {
            float a0, a1; up2(Sc[kp], a0, a1);
            Pc[(2 * kp) * 256 + px]     = a0;
            Pc[(2 * kp + 1) * 256 + px] = a1;
        }
        { float a0, a1; up2(Sc[4], a0, a1);
          Pc[8 * 256 + px] = a0; }
        __syncthreads();

        if (tid < 256) {
            const int qx = tid, y = qx >> 4, x = qx & 15;
            const float* P0 = sm + K2_PB;
            const float* P1 = sm + K2_PB + 9 * 256;
            float acc = 0.0f;
#pragma unroll
            for (int dy = -1; dy <= 1; dy++) {
                if (y + dy < 0 || y + dy > 15) continue;
#pragma unroll
                for (int dx = -1; dx <= 1; dx++) {
                    if (x + dx < 0 || x + dx > 15) continue;
                    const int k = (dy + 1) * 3 + (dx + 1);
                    const int q = qx + dy * 16 + dx;
                    acc += P0[k * 256 + q] + P1[k * 256 + q];
                }
            }
            out[(size_t)NB * 4 * NHW + (size_t)s * NHW + qx] =
                0.1f * (acc + cls_predb[0]);
        }
    } else {
        // ---------------- BOX tower: tap-sum also via mma ----------------
        float* P = sm + K2_PB;   // [48 rows = k*4+oc][256 px] f32

        for (int p = 0; p < 2; p++) {
            // stage pwt fp16
            {
                u32* pd = (u32*)(sm + K2_PWT);
#pragma unroll
                for (int j = 0; j < 8; j++) {
                    int i = tid + j * K2NT;
                    int o = i >> 5, kp = i & 31;
                    const float* wsrc = pwW + (p * 128 + o) * 64 + 2 * kp;
                    __half2 hv = __floats2half2_rn(wsrc[0], wsrc[1]);
                    pd[o * 36 + kp] = *(u32*)&hv;
                }
            }
            // stage A_tap fp16 [48][136h]: row r = k*4+oc, col c (half2 over c-pairs)
            {
                u32* ad = (u32*)(sm + K2_WP);
                for (int i = tid; i < 48 * 64; i += K2NT) {
                    int r = i >> 6, cp = i & 63;
                    float v0 = 0.0f, v1 = 0.0f;
                    if (r < 36) {
                        int k = r >> 2, oc = r & 3;
                        const float* wsrc = box_predw + oc * 2304 + k;
                        v0 = wsrc[(p * 128 + 2 * cp) * 9];
                        v1 = wsrc[(p * 128 + 2 * cp + 1) * 9];
                    }
                    __half2 hv = __floats2half2_rn(v0, v1);
                    ad[r * 68 + cp] = *(u32*)&hv;
                }
            }
            __syncthreads();

            gemm_mma(sm, lane, warp, p * 128);
            __syncthreads();

            // tap GEMM: P[r][px] (+)= sum_c A[r][c] * ft[c][px]
            if (warp < 12) {
                const int mt = warp >> 2, nq = warp & 3;
                const int m0 = mt * 16;
                const int g = lane >> 2, t4 = lane & 3;
                const u32 aoff = saddr(sm + K2_WP)
                    + (u32)(m0 + (lane & 15)) * 272u
                    + (u32)((lane >> 4) & 1) * 16u;
                const u32 boff = saddr(sm + K2_FT)
                    + (u32)(lane & 15) * 528u + (u32)nq * 128u;

                float acc[8][4];
#pragma unroll
                for (int nt = 0; nt < 8; nt++)
#pragma unroll
                    for (int e = 0; e < 4; e++) acc[nt][e] = 0.f;

#pragma unroll
                for (int ks = 0; ks < 8; ks++) {
                    u32 A0, A1, A2, A3;
                    asm volatile("ldmatrix.sync.aligned.m8n8.x4.shared.b16 {%0,%1,%2,%3}, [%4];"
                        : "=r"(A0), "=r"(A1), "=r"(A2), "=r"(A3)
                        : "r"(aoff + (u32)ks * 32u));
#pragma unroll
                    for (int nt = 0; nt < 8; nt++) {
                        u32 b0, b1;
                        asm volatile("ldmatrix.sync.aligned.m8n8.x2.trans.shared.b16 {%0,%1}, [%2];"
                            : "=r"(b0), "=r"(b1)
                            : "r"(boff + (u32)ks * 8448u + (u32)nt * 16u));
                        asm volatile(
                            "mma.sync.aligned.m16n8k16.row.col.f32.f16.f16.f32 "
                            "{%0,%1,%2,%3}, {%4,%5,%6,%7}, {%8,%9}, {%0,%1,%2,%3};"
                            : "+f"(acc[nt][0]), "+f"(acc[nt][1]),
                              "+f"(acc[nt][2]), "+f"(acc[nt][3])
                            : "r"(A0), "r"(A1), "r"(A2), "r"(A3), "r"(b0), "r"(b1));
                    }
                }

#pragma unroll
                for (int nt = 0; nt < 8; nt++) {
                    const int col = nq * 64 + nt * 8 + 2 * t4;
                    const int r0 = m0 + g, r1 = m0 + g + 8;
                    if (p == 0) {
                        P[r0 * 256 + col]     = acc[nt][0];
                        P[r0 * 256 + col + 1] = acc[nt][1];
                        P[r1 * 256 + col]     = acc[nt][2];
                        P[r1 * 256 + col + 1] = acc[nt][3];
                    } else {
                        P[r0 * 256 + col]     += acc[nt][0];
                        P[r0 * 256 + col + 1] += acc[nt][1];
                        P[r1 * 256 + col]     += acc[nt][2];
                        P[r1 * 256 + col + 1] += acc[nt][3];
                    }
                }
            }
            __syncthreads();
        }

        // epilogue: masked gather over taps; row r = k*4+oc
        if (tid < 256) {
            const int qx = tid, y = qx >> 4, x = qx & 15;
            float bx0 = 0.f, bx1 = 0.f, bx2 = 0.f, bx3 = 0.f;
#pragma unroll
            for (int dy = -1; dy <= 1; dy++) {
                if (y + dy < 0 || y + dy > 15) continue;
#pragma unroll
                for (int dx = -1; dx <= 1; dx++) {
                    if (x + dx < 0 || x + dx > 15) continue;
                    const int k = (dy + 1) * 3 + (dx + 1);
                    const int q = qx + dy * 16 + dx;
                    bx0 += P[(k * 4 + 0) * 256 + q];
                    bx1 += P[(k * 4 + 1) * 256 + q];
                    bx2 += P[(k * 4 + 2) * 256 + q];
                    bx3 += P[(k * 4 + 3) * 256 + q];
                }
            }
            const float adj = adjust[0];
            out[((size_t)s * 4 + 0) * NHW + qx] = expf(adj * (bx0 + box_predb[0]) + biasp[0]);
            out[((size_t)s * 4 + 1) * NHW + qx] = expf(adj * (bx1 + box_predb[1]) + biasp[1]);
            out[((size_t)s * 4 + 2) * NHW + qx] = expf(adj * (bx2 + box_predb[2]) + biasp[2]);
            out[((size_t)s * 4 + 3) * NHW + qx] = expf(adj * (bx3 + box_predb[3]) + biasp[3]);
        }
    }
}

extern "C" void kernel_launch(void* const* d_in, const int* in_sizes, int n_in,
                              void* d_out, int out_size)
{
    const float* search    = (const float*)d_in[0];
    const float* kern      = (const float*)d_in[1];
    const float* ca_w1     = (const float*)d_in[2];
    const float* ca_b1     = (const float*)d_in[3];
    const float* ca_w2     = (const float*)d_in[4];
    const float* ca_b2     = (const float*)d_in[5];
    const float* cls_dw    = (const float*)d_in[6];
    const float* cls_pw    = (const float*)d_in[7];
    const float* cls_bng   = (const float*)d_in[8];
    const float* cls_bnb   = (const float*)d_in[9];
    const float* cls_bnm   = (const float*)d_in[10];
    const float* cls_bnv   = (const float*)d_in[11];
    const float* cls_predw = (const float*)d_in[12];
    const float* cls_predb = (const float*)d_in[13];
    const float* box_dw    = (const float*)d_in[14];
    const float* box_pw    = (const float*)d_in[15];
    const float* box_bng   = (const float*)d_in[16];
    const float* box_bnb   = (const float*)d_in[17];
    const float* box_bnm   = (const float*)d_in[18];
    const float* box_bnv   = (const float*)d_in[19];
    const float* box_predw = (const float*)d_in[20];
    const float* box_predb = (const float*)d_in[21];
    const float* adjust    = (const float*)d_in[22];
    const float* biasp     = (const float*)d_in[23];

    const int sm1 = K1_TOT * 4;   // 135168 B
    const int sm2 = K2_TOT * 4;   // 191488 B
    cudaFuncSetAttribute(btl_k1, cudaFuncAttributeMaxDynamicSharedMemorySize, sm1);
    cudaFuncSetAttribute(btl_k2, cudaFuncAttributeMaxDynamicSharedMemorySize, sm2);

    btl_k1<<<NB, NT1, sm1>>>(search, kern, ca_w1, ca_b1, ca_w2, ca_b2, cls_dw, box_dw);
    btl_k2<<<NB * 2, K2NT, sm2>>>(cls_pw, cls_bng, cls_bnb, cls_bnm, cls_bnv,
                                  cls_predw, cls_predb,
                                  box_pw, box_bng, box_bnb, box_bnm, box_bnv,
                                  box_predw, box_predb,
                                  adjust, biasp, (float*)d_out);
}

// round 14
// speedup vs baseline: 5.2723x; 1.1772x over previous
#include <cuda_runtime.h>
#include <cuda_fp16.h>
#include <math.h>

#define NB   512
#define NC   112
#define NP   64
#define NHW  256
#define NOC  256
#define NT1  1024   // K1 threads (32 warps)
#define K2NT 512    // K2 threads (16 warps)

typedef unsigned long long u64;
typedef unsigned int u32;

__device__ __forceinline__ u64 pk2(float lo, float hi) {
    u64 r; asm("mov.b64 %0, {%1,%2};" : "=l"(r) : "f"(lo), "f"(hi)); return r;
}
__device__ __forceinline__ void up2(u64 v, float& a, float& b) {
    asm("mov.b64 {%0,%1}, %2;" : "=f"(a), "=f"(b) : "l"(v));
}
__device__ __forceinline__ void fma2(u64& d, u64 a, u64 b) {
    asm("fma.rn.f32x2 %0, %1, %2, %0;" : "+l"(d) : "l"(a), "l"(b));
}
__device__ __forceinline__ u32 saddr(const void* p) {
    return (u32)__cvta_generic_to_shared(p);
}

// dw scratch: [sample][tower][p 64][px 256] fp16
__device__ __half g_dw[(size_t)NB * 2 * NP * NHW];

// ======================= KERNEL 1: mma corr + attention + dual dw =======================
// float-index layout:
#define K1_ATT  0
#define K1_H    64
#define K1_A    128
#define K1_DWC  192     // 576
#define K1_DWB  768     // 576
#define K1_AZ   1344    // z fp16 [64 p][120 halves] = 3840 u32 (240B rows, 16B-aligned)
#define K1_BS   5184    // search fp16 [112 c][264 halves] = 14784 u32 (528B rows)
#define K1_CORR 19968   // corr fp32 [64][256] = 16384
#define K1_TOT  36352   // 145408 B

__global__ void __launch_bounds__(NT1, 1)
btl_k1(const float* __restrict__ search, const float* __restrict__ kern,
       const float* __restrict__ ca_w1, const float* __restrict__ ca_b1,
       const float* __restrict__ ca_w2, const float* __restrict__ ca_b2,
       const float* __restrict__ cls_dw, const float* __restrict__ box_dw)
{
    extern __shared__ float sm[];
    const int tid  = threadIdx.x;
    const int lane = tid & 31;
    const int warp = tid >> 5;
    const int b    = blockIdx.x;

    float* s_att  = sm + K1_ATT;
    float* s_h    = sm + K1_H;
    float* s_a    = sm + K1_A;
    float* s_corr = sm + K1_CORR;

    const float* gS = search + (size_t)b * NC * NHW;
    const float* gZ = kern   + (size_t)b * NC * NP;

    // ---- stage search fp32 -> fp16 B operand [112][264h] ----
    {
        u32* bd = (u32*)(sm + K1_BS);
        const float4* src = (const float4*)gS;
#pragma unroll
        for (int j = 0; j < 7; j++) {
            int i = tid + j * NT1;           // i < 7168 float4s
            int c = i >> 6, col4 = i & 63;
            float4 v = src[i];
            __half2 h0 = __floats2half2_rn(v.x, v.y);
            __half2 h1 = __floats2half2_rn(v.z, v.w);
            bd[c * 132 + col4 * 2]     = *(u32*)&h0;
            bd[c * 132 + col4 * 2 + 1] = *(u32*)&h1;
        }
    }
    // ---- stage z transposed -> fp16 A operand [64 p][120h] ----
    {
        __half* ad = (__half*)(sm + K1_AZ);
#pragma unroll
        for (int j = 0; j < 7; j++) {
            int i = tid + j * NT1;           // i < 7168
            int p = i & 63, c = i >> 6;
            ad[p * 120 + c] = __float2half_rn(gZ[c * 64 + p]);
        }
    }
    // stage depthwise weights (both towers)
    for (int i = tid; i < NP * 9; i += NT1) {
        sm[K1_DWC + i] = cls_dw[i];
        sm[K1_DWB + i] = box_dw[i];
    }
    __syncthreads();

    // ---- corr GEMM via mma.sync: 64p x 256px, K=112 (7 ks) ----
    {
        const int mt = warp >> 3, ne = warp & 7;   // 4 m-tiles x 8 n-eighths
        const int m0 = mt * 16;
        const int g  = lane >> 2, t4 = lane & 3;

        u32 A[7][4];
        const u32 abase = saddr(sm + K1_AZ)
            + (u32)(m0 + (lane & 15)) * 240u + (u32)((lane >> 4) & 1) * 16u;
#pragma unroll
        for (int ks = 0; ks < 7; ks++) {
            asm volatile("ldmatrix.sync.aligned.m8n8.x4.shared.b16 {%0,%1,%2,%3}, [%4];"
                : "=r"(A[ks][0]), "=r"(A[ks][1]), "=r"(A[ks][2]), "=r"(A[ks][3])
                : "r"(abase + (u32)ks * 32u));
        }
        const u32 bbase = saddr(sm + K1_BS)
            + (u32)(lane & 15) * 528u + (u32)ne * 64u;
#pragma unroll
        for (int nt = 0; nt < 4; nt++) {
            float c0 = 0.f, c1 = 0.f, c2 = 0.f, c3 = 0.f;
#pragma unroll
            for (int ks = 0; ks < 7; ks++) {
                u32 b0, b1;
                asm volatile("ldmatrix.sync.aligned.m8n8.x2.trans.shared.b16 {%0,%1}, [%2];"
                    : "=r"(b0), "=r"(b1)
                    : "r"(bbase + (u32)ks * 8448u + (u32)nt * 16u));
                asm volatile(
                    "mma.sync.aligned.m16n8k16.row.col.f32.f16.f16.f32 "
                    "{%0,%1,%2,%3}, {%4,%5,%6,%7}, {%8,%9}, {%0,%1,%2,%3};"
                    : "+f"(c0), "+f"(c1), "+f"(c2), "+f"(c3)
                    : "r"(A[ks][0]), "r"(A[ks][1]), "r"(A[ks][2]), "r"(A[ks][3]),
                      "r"(b0), "r"(b1));
            }
            const int col = ne * 32 + nt * 8 + 2 * t4;
            s_corr[(m0 + g)     * 256 + col]     = c0;
            s_corr[(m0 + g)     * 256 + col + 1] = c1;
            s_corr[(m0 + g + 8) * 256 + col]     = c2;
            s_corr[(m0 + g + 8) * 256 + col + 1] = c3;
        }
    }
    __syncthreads();

    // per-p means (warp handles 2 p)
    {
        const int p0 = warp * 2;
#pragma unroll
        for (int j = 0; j < 2; j++) {
            const int p = p0 + j;
            float ps = 0.0f;
#pragma unroll
            for (int i = 0; i < 8; i++) ps += s_corr[p * NHW + lane + 32 * i];
#pragma unroll
            for (int o = 16; o > 0; o >>= 1) ps += __shfl_xor_sync(0xffffffffu, ps, o);
            if (lane == 0) s_att[p] = ps * (1.0f / 256.0f);
        }
    }
    __syncthreads();

    // attention MLP
    if (tid < 64) {
        float s1 = ca_b1[tid];
        const float* w = ca_w1 + tid * 64;
#pragma unroll 8
        for (int j = 0; j < 64; j++) s1 = fmaf(w[j], s_att[j], s1);
        s_h[tid] = fmaxf(s1, 0.0f);
    }
    __syncthreads();
    if (tid < 64) {
        float s2 = ca_b2[tid];
        const float* w = ca_w2 + tid * 64;
#pragma unroll 8
        for (int j = 0; j < 64; j++) s2 = fmaf(w[j], s_h[j], s2);
        s_a[tid] = 1.0f / (1.0f + expf(-s2));
    }
    __syncthreads();

    // merged dual depthwise 3x3 (+attention) -> g_dw fp16
    {
        const int px = tid & 255, pq = tid >> 8;
        const int y = px >> 4, x = px & 15;
        const bool okU = y > 0, okD = y < 15, okL = x > 0, okR = x < 15;
        __half* dc = g_dw + ((size_t)b * 2)     * (NP * NHW) + px;
        __half* db = g_dw + ((size_t)b * 2 + 1) * (NP * NHW) + px;
#pragma unroll 2
        for (int pi = 0; pi < 16; pi++) {
            const int p = pq * 16 + pi;
            const float* r = s_corr + p * NHW + px;
            float nv[9];
            nv[4] = r[0];
            nv[1] = okU ? r[-16] : 0.0f;
            nv[0] = (okU && okL) ? r[-17] : 0.0f;
            nv[2] = (okU && okR) ? r[-15] : 0.0f;
            nv[7] = okD ? r[16] : 0.0f;
            nv[6] = (okD && okL) ? r[15] : 0.0f;
            nv[8] = (okD && okR) ? r[17] : 0.0f;
            nv[3] = okL ? r[-1] : 0.0f;
            nv[5] = okR ? r[1] : 0.0f;
            const float* wc = sm + K1_DWC + p * 9;
            const float* wb = sm + K1_DWB + p * 9;
            float ac = 0.0f, ab = 0.0f;
#pragma unroll
            for (int k = 0; k < 9; k++) {
                ac = fmaf(nv[k], wc[k], ac);
                ab = fmaf(nv[k], wb[k], ab);
            }
            const float a = s_a[p];
            dc[p * NHW] = __float2half_rn(ac * a);
            db[p * NHW] = __float2half_rn(ab * a);
        }
    }
}

// ======================= KERNEL 2 (unchanged from R13) =======================
#define K2_BNSC 0
#define K2_BNSH 256
#define K2_WP   512
#define K2_DW   5632
#define K2_PWT  14080
#define K2_FT   18688
#define K2_PB   35584
#define K2_TOT  47872   // 191488 B

__device__ __forceinline__ void gemm_mma(float* sm, int lane, int warp, int o_base)
{
    const u32 pwt_b = saddr(sm + K2_PWT);
    const u32 dw_b  = saddr(sm + K2_DW);
    u32* s_ft = (u32*)(sm + K2_FT);
    const float* s_bnsc = sm + K2_BNSC;
    const float* s_bnsh = sm + K2_BNSH;

    const int mt = warp >> 1, h = warp & 1;
    const int m0 = mt * 16;
    const int g  = lane >> 2, t4 = lane & 3;

    u32 A[4][4];
    {
        const u32 aoff = pwt_b
            + (u32)(m0 + (lane & 7) + ((lane >> 3) & 1) * 8) * 144u
            + (u32)((lane >> 4) & 1) * 16u;
#pragma unroll
        for (int ks = 0; ks < 4; ks++) {
            asm volatile("ldmatrix.sync.aligned.m8n8.x4.shared.b16 {%0,%1,%2,%3}, [%4];"
                : "=r"(A[ks][0]), "=r"(A[ks][1]), "=r"(A[ks][2]), "=r"(A[ks][3])
                : "r"(aoff + (u32)ks * 32u));
        }
    }

    const float sc0 = s_bnsc[o_base + m0 + g],     sh0 = s_bnsh[o_base + m0 + g];
    const float sc1 = s_bnsc[o_base + m0 + g + 8], sh1 = s_bnsh[o_base + m0 + g + 8];
    const u32 boff = dw_b + (u32)(lane & 15) * 528u + (u32)h * 256u;

#pragma unroll 4
    for (int nt = 0; nt < 16; nt++) {
        float c0 = 0.f, c1 = 0.f, c2 = 0.f, c3 = 0.f;
#pragma unroll
        for (int ks = 0; ks < 4; ks++) {
            u32 b0, b1;
            asm volatile("ldmatrix.sync.aligned.m8n8.x2.trans.shared.b16 {%0,%1}, [%2];"
                : "=r"(b0), "=r"(b1)
                : "r"(boff + (u32)ks * 8448u + (u32)nt * 16u));
            asm volatile(
                "mma.sync.aligned.m16n8k16.row.col.f32.f16.f16.f32 "
                "{%0,%1,%2,%3}, {%4,%5,%6,%7}, {%8,%9}, {%0,%1,%2,%3};"
                : "+f"(c0), "+f"(c1), "+f"(c2), "+f"(c3)
                : "r"(A[ks][0]), "r"(A[ks][1]), "r"(A[ks][2]), "r"(A[ks][3]),
                  "r"(b0), "r"(b1));
        }
        c0 = fmaxf(fmaf(c0, sc0, sh0), 0.0f);
        c1 = fmaxf(fmaf(c1, sc0, sh0), 0.0f);
        c2 = fmaxf(fmaf(c2, sc1, sh1), 0.0f);
        c3 = fmaxf(fmaf(c3, sc1, sh1), 0.0f);
        __half2 p01 = __floats2half2_rn(c0, c1);
        __half2 p23 = __floats2half2_rn(c2, c3);
        const int n0h = h * 64 + nt * 4;
        s_ft[(m0 + g)     * 132 + n0h + t4] = *(u32*)&p01;
        s_ft[(m0 + g + 8) * 132 + n0h + t4] = *(u32*)&p23;
    }
}

__global__ void __launch_bounds__(K2NT, 1)
btl_k2(const float* __restrict__ cls_pw,
       const float* __restrict__ cls_bng, const float* __restrict__ cls_bnb,
       const float* __restrict__ cls_bnm, const float* __restrict__ cls_bnv,
       const float* __restrict__ cls_predw, const float* __restrict__ cls_predb,
       const float* __restrict__ box_pw,
       const float* __restrict__ box_bng, const float* __restrict__ box_bnb,
       const float* __restrict__ box_bnm, const float* __restrict__ box_bnv,
       const float* __restrict__ box_predw, const float* __restrict__ box_predb,
       const float* __restrict__ adjust, const float* __restrict__ biasp,
       float* __restrict__ out)
{
    extern __shared__ float sm[];
    const int tid  = threadIdx.x;
    const int lane = tid & 31;
    const int warp = tid >> 5;
    const int s    = blockIdx.x >> 1;
    const int t    = blockIdx.x & 1;

    {
        const u32* src = (const u32*)(g_dw + ((size_t)s * 2 + t) * (NP * NHW));
        u32* dst = (u32*)(sm + K2_DW);
#pragma unroll
        for (int j = 0; j < 16; j++) {
            int i = tid + j * K2NT;
            dst[(i >> 7) * 132 + (i & 127)] = src[i];
        }
    }
    if (tid < NOC) {
        const float* bng = t ? box_bng : cls_bng;
        const float* bnb = t ? box_bnb : cls_bnb;
        const float* bnm = t ? box_bnm : cls_bnm;
        const float* bnv = t ? box_bnv : cls_bnv;
        float sc = bng[tid] * rsqrtf(bnv[tid] + 1e-5f);
        sm[K2_BNSC + tid] = sc;
        sm[K2_BNSH + tid] = bnb[tid] - bnm[tid] * sc;
    }
    __syncthreads();

    const float* pwW = t ? box_pw : cls_pw;

    if (t == 0) {
        float* s_wp = sm + K2_WP;
        u64 Sc[5];
#pragma unroll
        for (int i = 0; i < 5; i++) Sc[i] = 0ull;
        const unsigned short* fth = (const unsigned short*)(sm + K2_FT);
        const int px = tid & 255, cq = tid >> 8;

        for (int p = 0; p < 2; p++) {
            {
                u32* pd = (u32*)(sm + K2_PWT);
#pragma unroll
                for (int j = 0; j < 8; j++) {
                    int i = tid + j * K2NT;
                    int o = i >> 5, kp = i & 31;
                    const float* wsrc = pwW + (p * 128 + o) * 64 + 2 * kp;
                    __half2 hv = __floats2half2_rn(wsrc[0], wsrc[1]);
                    pd[o * 36 + kp] = *(u32*)&hv;
                }
            }
            for (int i = tid; i < 1536; i += K2NT) {
                int c = i / 12, k = i % 12;
                s_wp[i] = (k < 9) ? cls_predw[(p * 128 + c) * 9 + k] : 0.0f;
            }
            __syncthreads();

            gemm_mma(sm, lane, warp, p * 128);
            __syncthreads();

#pragma unroll 2
            for (int ci = 0; ci < 64; ci++) {
                const int c = cq * 64 + ci;
                float xv = __half2float(__ushort_as_half(fth[c * 264 + px]));
                const u64 xd = pk2(xv, xv);
                const ulonglong2* wp2 = (const ulonglong2*)(s_wp + c * 12);
                ulonglong2 wA = wp2[0];
                ulonglong2 wB = wp2[1];
                float w8 = s_wp[c * 12 + 8];
                fma2(Sc[0], xd, wA.x);
                fma2(Sc[1], xd, wA.y);
                fma2(Sc[2], xd, wB.x);
                fma2(Sc[3], xd, wB.y);
                fma2(Sc[4], xd, pk2(w8, 0.0f));
            }
            __syncthreads();
        }

        float* Pc = sm + K2_PB + cq * (9 * 256);
#pragma unroll
        for (int kp = 0; kp < 4; kp++) {
            float a0, a1; up2(Sc[kp], a0, a1);
            Pc[(2 * kp) * 256 + px]     = a0;
            Pc[(2 * kp + 1) * 256 + px] = a1;
        }
        { float a0, a1; up2(Sc[4], a0, a1);
          Pc[8 * 256 + px] = a0; }
        __syncthreads();

        if (tid < 256) {
            const int qx = tid, y = qx >> 4, x = qx & 15;
            const float* P0 = sm + K2_PB;
            const float* P1 = sm + K2_PB + 9 * 256;
            float acc = 0.0f;
#pragma unroll
            for (int dy = -1; dy <= 1; dy++) {
                if (y + dy < 0 || y + dy > 15) continue;
#pragma unroll
                for (int dx = -1; dx <= 1; dx++) {
                    if (x + dx < 0 || x + dx > 15) continue;
                    const int k = (dy + 1) * 3 + (dx + 1);
                    const int q = qx + dy * 16 + dx;
                    acc += P0[k * 256 + q] + P1[k * 256 + q];
                }
            }
            out[(size_t)NB * 4 * NHW + (size_t)s * NHW + qx] =
                0.1f * (acc + cls_predb[0]);
        }
    } else {
        float* P = sm + K2_PB;   // [48][256] f32

        for (int p = 0; p < 2; p++) {
            {
                u32* pd = (u32*)(sm + K2_PWT);
#pragma unroll
                for (int j = 0; j < 8; j++) {
                    int i = tid + j * K2NT;
                    int o = i >> 5, kp = i & 31;
                    const float* wsrc = pwW + (p * 128 + o) * 64 + 2 * kp;
                    __half2 hv = __floats2half2_rn(wsrc[0], wsrc[1]);
                    pd[o * 36 + kp] = *(u32*)&hv;
                }
            }
            {
                u32* ad = (u32*)(sm + K2_WP);
                for (int i = tid; i < 48 * 64; i += K2NT) {
                    int r = i >> 6, cp = i & 63;
                    float v0 = 0.0f, v1 = 0.0f;
                    if (r < 36) {
                        int k = r >> 2, oc = r & 3;
                        const float* wsrc = box_predw + oc * 2304 + k;
                        v0 = wsrc[(p * 128 + 2 * cp) * 9];
                        v1 = wsrc[(p * 128 + 2 * cp + 1) * 9];
                    }
                    __half2 hv = __floats2half2_rn(v0, v1);
                    ad[r * 68 + cp] = *(u32*)&hv;
                }
            }
            __syncthreads();

            gemm_mma(sm, lane, warp, p * 128);
            __syncthreads();

            if (warp < 12) {
                const int mt = warp >> 2, nq = warp & 3;
                const int m0 = mt * 16;
                const int g = lane >> 2, t4 = lane & 3;
                const u32 aoff = saddr(sm + K2_WP)
                    + (u32)(m0 + (lane & 15)) * 272u
                    + (u32)((lane >> 4) & 1) * 16u;
                const u32 boff = saddr(sm + K2_FT)
                    + (u32)(lane & 15) * 528u + (u32)nq * 128u;

                float acc[8][4];
#pragma unroll
                for (int nt = 0; nt < 8; nt++)
#pragma unroll
                    for (int e = 0; e < 4; e++) acc[nt][e] = 0.f;

#pragma unroll
                for (int ks = 0; ks < 8; ks++) {
                    u32 A0, A1, A2, A3;
                    asm volatile("ldmatrix.sync.aligned.m8n8.x4.shared.b16 {%0,%1,%2,%3}, [%4];"
                        : "=r"(A0), "=r"(A1), "=r"(A2), "=r"(A3)
                        : "r"(aoff + (u32)ks * 32u));
#pragma unroll
                    for (int nt = 0; nt < 8; nt++) {
                        u32 b0, b1;
                        asm volatile("ldmatrix.sync.aligned.m8n8.x2.trans.shared.b16 {%0,%1}, [%2];"
                            : "=r"(b0), "=r"(b1)
                            : "r"(boff + (u32)ks * 8448u + (u32)nt * 16u));
                        asm volatile(
                            "mma.sync.aligned.m16n8k16.row.col.f32.f16.f16.f32 "
                            "{%0,%1,%2,%3}, {%4,%5,%6,%7}, {%8,%9}, {%0,%1,%2,%3};"
                            : "+f"(acc[nt][0]), "+f"(acc[nt][1]),
                              "+f"(acc[nt][2]), "+f"(acc[nt][3])
                            : "r"(A0), "r"(A1), "r"(A2), "r"(A3), "r"(b0), "r"(b1));
                    }
                }

#pragma unroll
                for (int nt = 0; nt < 8; nt++) {
                    const int col = nq * 64 + nt * 8 + 2 * t4;
                    const int r0 = m0 + g, r1 = m0 + g + 8;
                    if (p == 0) {
                        P[r0 * 256 + col]     = acc[nt][0];
                        P[r0 * 256 + col + 1] = acc[nt][1];
                        P[r1 * 256 + col]     = acc[nt][2];
                        P[r1 * 256 + col + 1] = acc[nt][3];
                    } else {
                        P[r0 * 256 + col]     += acc[nt][0];
                        P[r0 * 256 + col + 1] += acc[nt][1];
                        P[r1 * 256 + col]     += acc[nt][2];
                        P[r1 * 256 + col + 1] += acc[nt][3];
                    }
                }
            }
            __syncthreads();
        }

        if (tid < 256) {
            const int qx = tid, y = qx >> 4, x = qx & 15;
            float bx0 = 0.f, bx1 = 0.f, bx2 = 0.f, bx3 = 0.f;
#pragma unroll
            for (int dy = -1; dy <= 1; dy++) {
                if (y + dy < 0 || y + dy > 15) continue;
#pragma unroll
                for (int dx = -1; dx <= 1; dx++) {
                    if (x + dx < 0 || x + dx > 15) continue;
                    const int k = (dy + 1) * 3 + (dx + 1);
                    const int q = qx + dy * 16 + dx;
                    bx0 += P[(k * 4 + 0) * 256 + q];
                    bx1 += P[(k * 4 + 1) * 256 + q];
                    bx2 += P[(k * 4 + 2) * 256 + q];
                    bx3 += P[(k * 4 + 3) * 256 + q];
                }
            }
            const float adj = adjust[0];
            out[((size_t)s * 4 + 0) * NHW + qx] = expf(adj * (bx0 + box_predb[0]) + biasp[0]);
            out[((size_t)s * 4 + 1) * NHW + qx] = expf(adj * (bx1 + box_predb[1]) + biasp[1]);
            out[((size_t)s * 4 + 2) * NHW + qx] = expf(adj * (bx2 + box_predb[2]) + biasp[2]);
            out[((size_t)s * 4 + 3) * NHW + qx] = expf(adj * (bx3 + box_predb[3]) + biasp[3]);
        }
    }
}

extern "C" void kernel_launch(void* const* d_in, const int* in_sizes, int n_in,
                              void* d_out, int out_size)
{
    const float* search    = (const float*)d_in[0];
    const float* kern      = (const float*)d_in[1];
    const float* ca_w1     = (const float*)d_in[2];
    const float* ca_b1     = (const float*)d_in[3];
    const float* ca_w2     = (const float*)d_in[4];
    const float* ca_b2     = (const float*)d_in[5];
    const float* cls_dw    = (const float*)d_in[6];
    const float* cls_pw    = (const float*)d_in[7];
    const float* cls_bng   = (const float*)d_in[8];
    const float* cls_bnb   = (const float*)d_in[9];
    const float* cls_bnm   = (const float*)d_in[10];
    const float* cls_bnv   = (const float*)d_in[11];
    const float* cls_predw = (const float*)d_in[12];
    const float* cls_predb = (const float*)d_in[13];
    const float* box_dw    = (const float*)d_in[14];
    const float* box_pw    = (const float*)d_in[15];
    const float* box_bng   = (const float*)d_in[16];
    const float* box_bnb   = (const float*)d_in[17];
    const float* box_bnm   = (const float*)d_in[18];
    const float* box_bnv   = (const float*)d_in[19];
    const float* box_predw = (const float*)d_in[20];
    const float* box_predb = (const float*)d_in[21];
    const float* adjust    = (const float*)d_in[22];
    const float* biasp     = (const float*)d_in[23];

    const int sm1 = K1_TOT * 4;   // 145408 B
    const int sm2 = K2_TOT * 4;   // 191488 B
    cudaFuncSetAttribute(btl_k1, cudaFuncAttributeMaxDynamicSharedMemorySize, sm1);
    cudaFuncSetAttribute(btl_k2, cudaFuncAttributeMaxDynamicSharedMemorySize, sm2);

    btl_k1<<<NB, NT1, sm1>>>(search, kern, ca_w1, ca_b1, ca_w2, ca_b2, cls_dw, box_dw);
    btl_k2<<<NB * 2, K2NT, sm2>>>(cls_pw, cls_bng, cls_bnb, cls_bnm, cls_bnv,
                                  cls_predw, cls_predb,
                                  box_pw, box_bng, box_bnb, box_bnm, box_bnv,
                                  box_predw, box_predb,
                                  adjust, biasp, (float*)d_out);
}

// round 15
// speedup vs baseline: 6.0949x; 1.1560x over previous
#include <cuda_runtime.h>
#include <cuda_fp16.h>
#include <math.h>

#define NB   512
#define NC   112
#define NP   64
#define NHW  256
#define NOC  256
#define NT1  1024   // K1 threads (32 warps)
#define K2NT 512    // K2 threads (16 warps)

typedef unsigned long long u64;
typedef unsigned int u32;

__device__ __forceinline__ u32 saddr(const void* p) {
    return (u32)__cvta_generic_to_shared(p);
}

// dw scratch: [sample][tower][p 64][px 256] fp16
__device__ __half g_dw[(size_t)NB * 2 * NP * NHW];

// ======================= KERNEL 1 (unchanged from R14) =======================
#define K1_ATT  0
#define K1_H    64
#define K1_A    128
#define K1_DWC  192
#define K1_DWB  768
#define K1_AZ   1344    // z fp16 [64 p][120 h] (240B rows)
#define K1_BS   5184    // search fp16 [112 c][264 h] (528B rows)
#define K1_CORR 19968   // corr fp32 [64][256]
#define K1_TOT  36352   // 145408 B

__global__ void __launch_bounds__(NT1, 1)
btl_k1(const float* __restrict__ search, const float* __restrict__ kern,
       const float* __restrict__ ca_w1, const float* __restrict__ ca_b1,
       const float* __restrict__ ca_w2, const float* __restrict__ ca_b2,
       const float* __restrict__ cls_dw, const float* __restrict__ box_dw)
{
    extern __shared__ float sm[];
    const int tid  = threadIdx.x;
    const int lane = tid & 31;
    const int warp = tid >> 5;
    const int b    = blockIdx.x;

    float* s_att  = sm + K1_ATT;
    float* s_h    = sm + K1_H;
    float* s_a    = sm + K1_A;
    float* s_corr = sm + K1_CORR;

    const float* gS = search + (size_t)b * NC * NHW;
    const float* gZ = kern   + (size_t)b * NC * NP;

    {
        u32* bd = (u32*)(sm + K1_BS);
        const float4* src = (const float4*)gS;
#pragma unroll
        for (int j = 0; j < 7; j++) {
            int i = tid + j * NT1;
            int c = i >> 6, col4 = i & 63;
            float4 v = src[i];
            __half2 h0 = __floats2half2_rn(v.x, v.y);
            __half2 h1 = __floats2half2_rn(v.z, v.w);
            bd[c * 132 + col4 * 2]     = *(u32*)&h0;
            bd[c * 132 + col4 * 2 + 1] = *(u32*)&h1;
        }
    }
    {
        __half* ad = (__half*)(sm + K1_AZ);
#pragma unroll
        for (int j = 0; j < 7; j++) {
            int i = tid + j * NT1;
            int p = i & 63, c = i >> 6;
            ad[p * 120 + c] = __float2half_rn(gZ[c * 64 + p]);
        }
    }
    for (int i = tid; i < NP * 9; i += NT1) {
        sm[K1_DWC + i] = cls_dw[i];
        sm[K1_DWB + i] = box_dw[i];
    }
    __syncthreads();

    {
        const int mt = warp >> 3, ne = warp & 7;
        const int m0 = mt * 16;
        const int g  = lane >> 2, t4 = lane & 3;

        u32 A[7][4];
        const u32 abase = saddr(sm + K1_AZ)
            + (u32)(m0 + (lane & 15)) * 240u + (u32)((lane >> 4) & 1) * 16u;
#pragma unroll
        for (int ks = 0; ks < 7; ks++) {
            asm volatile("ldmatrix.sync.aligned.m8n8.x4.shared.b16 {%0,%1,%2,%3}, [%4];"
                : "=r"(A[ks][0]), "=r"(A[ks][1]), "=r"(A[ks][2]), "=r"(A[ks][3])
                : "r"(abase + (u32)ks * 32u));
        }
        const u32 bbase = saddr(sm + K1_BS)
            + (u32)(lane & 15) * 528u + (u32)ne * 64u;
#pragma unroll
        for (int nt = 0; nt < 4; nt++) {
            float c0 = 0.f, c1 = 0.f, c2 = 0.f, c3 = 0.f;
#pragma unroll
            for (int ks = 0; ks < 7; ks++) {
                u32 b0, b1;
                asm volatile("ldmatrix.sync.aligned.m8n8.x2.trans.shared.b16 {%0,%1}, [%2];"
                    : "=r"(b0), "=r"(b1)
                    : "r"(bbase + (u32)ks * 8448u + (u32)nt * 16u));
                asm volatile(
                    "mma.sync.aligned.m16n8k16.row.col.f32.f16.f16.f32 "
                    "{%0,%1,%2,%3}, {%4,%5,%6,%7}, {%8,%9}, {%0,%1,%2,%3};"
                    : "+f"(c0), "+f"(c1), "+f"(c2), "+f"(c3)
                    : "r"(A[ks][0]), "r"(A[ks][1]), "r"(A[ks][2]), "r"(A[ks][3]),
                      "r"(b0), "r"(b1));
            }
            const int col = ne * 32 + nt * 8 + 2 * t4;
            s_corr[(m0 + g)     * 256 + col]     = c0;
            s_corr[(m0 + g)     * 256 + col + 1] = c1;
            s_corr[(m0 + g + 8) * 256 + col]     = c2;
            s_corr[(m0 + g + 8) * 256 + col + 1] = c3;
        }
    }
    __syncthreads();

    {
        const int p0 = warp * 2;
#pragma unroll
        for (int j = 0; j < 2; j++) {
            const int p = p0 + j;
            float ps = 0.0f;
#pragma unroll
            for (int i = 0; i < 8; i++) ps += s_corr[p * NHW + lane + 32 * i];
#pragma unroll
            for (int o = 16; o > 0; o >>= 1) ps += __shfl_xor_sync(0xffffffffu, ps, o);
            if (lane == 0) s_att[p] = ps * (1.0f / 256.0f);
        }
    }
    __syncthreads();

    if (tid < 64) {
        float s1 = ca_b1[tid];
        const float* w = ca_w1 + tid * 64;
#pragma unroll 8
        for (int j = 0; j < 64; j++) s1 = fmaf(w[j], s_att[j], s1);
        s_h[tid] = fmaxf(s1, 0.0f);
    }
    __syncthreads();
    if (tid < 64) {
        float s2 = ca_b2[tid];
        const float* w = ca_w2 + tid * 64;
#pragma unroll 8
        for (int j = 0; j < 64; j++) s2 = fmaf(w[j], s_h[j], s2);
        s_a[tid] = 1.0f / (1.0f + expf(-s2));
    }
    __syncthreads();

    {
        const int px = tid & 255, pq = tid >> 8;
        const int y = px >> 4, x = px & 15;
        const bool okU = y > 0, okD = y < 15, okL = x > 0, okR = x < 15;
        __half* dc = g_dw + ((size_t)b * 2)     * (NP * NHW) + px;
        __half* db = g_dw + ((size_t)b * 2 + 1) * (NP * NHW) + px;
#pragma unroll 2
        for (int pi = 0; pi < 16; pi++) {
            const int p = pq * 16 + pi;
            const float* r = s_corr + p * NHW + px;
            float nv[9];
            nv[4] = r[0];
            nv[1] = okU ? r[-16] : 0.0f;
            nv[0] = (okU && okL) ? r[-17] : 0.0f;
            nv[2] = (okU && okR) ? r[-15] : 0.0f;
            nv[7] = okD ? r[16] : 0.0f;
            nv[6] = (okD && okL) ? r[15] : 0.0f;
            nv[8] = (okD && okR) ? r[17] : 0.0f;
            nv[3] = okL ? r[-1] : 0.0f;
            nv[5] = okR ? r[1] : 0.0f;
            const float* wc = sm + K1_DWC + p * 9;
            const float* wb = sm + K1_DWB + p * 9;
            float ac = 0.0f, ab = 0.0f;
#pragma unroll
            for (int k = 0; k < 9; k++) {
                ac = fmaf(nv[k], wc[k], ac);
                ab = fmaf(nv[k], wb[k], ab);
            }
            const float a = s_a[p];
            dc[p * NHW] = __float2half_rn(ac * a);
            db[p * NHW] = __float2half_rn(ab * a);
        }
    }
}

// ======================= KERNEL 2 =======================
#define K2_BNSC 0
#define K2_BNSH 256
#define K2_WP   512     // A_tap fp16: box [48][68 u32], cls [16][68 u32]
#define K2_DW   5632    // dw fp16 [64][132 u32]
#define K2_PWT  14080   // pwt fp16 [128][36 u32]
#define K2_FT   18688   // ft fp16 [128][132 u32]
#define K2_PB   35584   // P: box [48][256] f32, cls [16][256] f32
#define K2_TOT  47872   // 191488 B

__device__ __forceinline__ void gemm_mma(float* sm, int lane, int warp, int o_base)
{
    const u32 pwt_b = saddr(sm + K2_PWT);
    const u32 dw_b  = saddr(sm + K2_DW);
    u32* s_ft = (u32*)(sm + K2_FT);
    const float* s_bnsc = sm + K2_BNSC;
    const float* s_bnsh = sm + K2_BNSH;

    const int mt = warp >> 1, h = warp & 1;
    const int m0 = mt * 16;
    const int g  = lane >> 2, t4 = lane & 3;

    u32 A[4][4];
    {
        const u32 aoff = pwt_b
            + (u32)(m0 + (lane & 7) + ((lane >> 3) & 1) * 8) * 144u
            + (u32)((lane >> 4) & 1) * 16u;
#pragma unroll
        for (int ks = 0; ks < 4; ks++) {
            asm volatile("ldmatrix.sync.aligned.m8n8.x4.shared.b16 {%0,%1,%2,%3}, [%4];"
                : "=r"(A[ks][0]), "=r"(A[ks][1]), "=r"(A[ks][2]), "=r"(A[ks][3])
                : "r"(aoff + (u32)ks * 32u));
        }
    }

    const float sc0 = s_bnsc[o_base + m0 + g],     sh0 = s_bnsh[o_base + m0 + g];
    const float sc1 = s_bnsc[o_base + m0 + g + 8], sh1 = s_bnsh[o_base + m0 + g + 8];
    const u32 boff = dw_b + (u32)(lane & 15) * 528u + (u32)h * 256u;

#pragma unroll 4
    for (int nt = 0; nt < 16; nt++) {
        float c0 = 0.f, c1 = 0.f, c2 = 0.f, c3 = 0.f;
#pragma unroll
        for (int ks = 0; ks < 4; ks++) {
            u32 b0, b1;
            asm volatile("ldmatrix.sync.aligned.m8n8.x2.trans.shared.b16 {%0,%1}, [%2];"
                : "=r"(b0), "=r"(b1)
                : "r"(boff + (u32)ks * 8448u + (u32)nt * 16u));
            asm volatile(
                "mma.sync.aligned.m16n8k16.row.col.f32.f16.f16.f32 "
                "{%0,%1,%2,%3}, {%4,%5,%6,%7}, {%8,%9}, {%0,%1,%2,%3};"
                : "+f"(c0), "+f"(c1), "+f"(c2), "+f"(c3)
                : "r"(A[ks][0]), "r"(A[ks][1]), "r"(A[ks][2]), "r"(A[ks][3]),
                  "r"(b0), "r"(b1));
        }
        c0 = fmaxf(fmaf(c0, sc0, sh0), 0.0f);
        c1 = fmaxf(fmaf(c1, sc0, sh0), 0.0f);
        c2 = fmaxf(fmaf(c2, sc1, sh1), 0.0f);
        c3 = fmaxf(fmaf(c3, sc1, sh1), 0.0f);
        __half2 p01 = __floats2half2_rn(c0, c1);
        __half2 p23 = __floats2half2_rn(c2, c3);
        const int n0h = h * 64 + nt * 4;
        s_ft[(m0 + g)     * 132 + n0h + t4] = *(u32*)&p01;
        s_ft[(m0 + g + 8) * 132 + n0h + t4] = *(u32*)&p23;
    }
}

// tap GEMM: P[m0+g / +8][col] (+)= sum_c A_tap[r][c] * ft[c][px]
// box: 12 warps, mt=warp>>2 (3 tiles), nq=warp&3 (64 px), NT=8
// cls: 8 warps,  mt=0,            nq=warp    (32 px), NT=4
template<int NT_I>
__device__ __forceinline__ void tap_mma(float* sm, int lane, int mt, int nq,
                                        float* P, bool accum)
{
    const int m0 = mt * 16;
    const int g = lane >> 2, t4 = lane & 3;
    const u32 aoff = saddr(sm + K2_WP)
        + (u32)(m0 + (lane & 15)) * 272u
        + (u32)((lane >> 4) & 1) * 16u;
    const u32 boff = saddr(sm + K2_FT)
        + (u32)(lane & 15) * 528u + (u32)(nq * NT_I * 16);

    float acc[NT_I][4];
#pragma unroll
    for (int nt = 0; nt < NT_I; nt++)
#pragma unroll
        for (int e = 0; e < 4; e++) acc[nt][e] = 0.f;

#pragma unroll
    for (int ks = 0; ks < 8; ks++) {
        u32 A0, A1, A2, A3;
        asm volatile("ldmatrix.sync.aligned.m8n8.x4.shared.b16 {%0,%1,%2,%3}, [%4];"
            : "=r"(A0), "=r"(A1), "=r"(A2), "=r"(A3)
            : "r"(aoff + (u32)ks * 32u));
#pragma unroll
        for (int nt = 0; nt < NT_I; nt++) {
            u32 b0, b1;
            asm volatile("ldmatrix.sync.aligned.m8n8.x2.trans.shared.b16 {%0,%1}, [%2];"
                : "=r"(b0), "=r"(b1)
                : "r"(boff + (u32)ks * 8448u + (u32)nt * 16u));
            asm volatile(
                "mma.sync.aligned.m16n8k16.row.col.f32.f16.f16.f32 "
                "{%0,%1,%2,%3}, {%4,%5,%6,%7}, {%8,%9}, {%0,%1,%2,%3};"
                : "+f"(acc[nt][0]), "+f"(acc[nt][1]),
                  "+f"(acc[nt][2]), "+f"(acc[nt][3])
                : "r"(A0), "r"(A1), "r"(A2), "r"(A3), "r"(b0), "r"(b1));
        }
    }

#pragma unroll
    for (int nt = 0; nt < NT_I; nt++) {
        const int col = nq * (NT_I * 8) + nt * 8 + 2 * t4;
        const int r0 = m0 + g, r1 = m0 + g + 8;
        if (!accum) {
            P[r0 * 256 + col]     = acc[nt][0];
            P[r0 * 256 + col + 1] = acc[nt][1];
            P[r1 * 256 + col]     = acc[nt][2];
            P[r1 * 256 + col + 1] = acc[nt][3];
        } else {
            P[r0 * 256 + col]     += acc[nt][0];
            P[r0 * 256 + col + 1] += acc[nt][1];
            P[r1 * 256 + col]     += acc[nt][2];
            P[r1 * 256 + col + 1] += acc[nt][3];
        }
    }
}

__global__ void __launch_bounds__(K2NT, 1)
btl_k2(const float* __restrict__ cls_pw,
       const float* __restrict__ cls_bng, const float* __restrict__ cls_bnb,
       const float* __restrict__ cls_bnm, const float* __restrict__ cls_bnv,
       const float* __restrict__ cls_predw, const float* __restrict__ cls_predb,
       const float* __restrict__ box_pw,
       const float* __restrict__ box_bng, const float* __restrict__ box_bnb,
       const float* __restrict__ box_bnm, const float* __restrict__ box_bnv,
       const float* __restrict__ box_predw, const float* __restrict__ box_predb,
       const float* __restrict__ adjust, const float* __restrict__ biasp,
       float* __restrict__ out)
{
    extern __shared__ float sm[];
    const int tid  = threadIdx.x;
    const int lane = tid & 31;
    const int warp = tid >> 5;
    const int s    = blockIdx.x >> 1;
    const int t    = blockIdx.x & 1;

    // stage dw fp16 -> padded [64][132 u32]
    {
        const u32* src = (const u32*)(g_dw + ((size_t)s * 2 + t) * (NP * NHW));
        u32* dst = (u32*)(sm + K2_DW);
#pragma unroll
        for (int j = 0; j < 16; j++) {
            int i = tid + j * K2NT;
            dst[(i >> 7) * 132 + (i & 127)] = src[i];
        }
    }
    if (tid < NOC) {
        const float* bng = t ? box_bng : cls_bng;
        const float* bnb = t ? box_bnb : cls_bnb;
        const float* bnm = t ? box_bnm : cls_bnm;
        const float* bnv = t ? box_bnv : cls_bnv;
        float sc = bng[tid] * rsqrtf(bnv[tid] + 1e-5f);
        sm[K2_BNSC + tid] = sc;
        sm[K2_BNSH + tid] = bnb[tid] - bnm[tid] * sc;
    }

    const float* pwW = t ? box_pw : cls_pw;
    const float* predW = t ? box_predw : cls_predw;
    u32* pd = (u32*)(sm + K2_PWT);
    u32* ad = (u32*)(sm + K2_WP);
    float* P = sm + K2_PB;

    // ---- stage pass-0 pwt + A_tap ----
#pragma unroll
    for (int j = 0; j < 8; j++) {
        int i = tid + j * K2NT;
        int o = i >> 5, kp = i & 31;
        const float* wsrc = pwW + o * 64 + 2 * kp;
        __half2 hv = __floats2half2_rn(wsrc[0], wsrc[1]);
        pd[o * 36 + kp] = *(u32*)&hv;
    }
    if (t == 1) {
        for (int i = tid; i < 48 * 64; i += K2NT) {
            int r = i >> 6, cp = i & 63;
            float v0 = 0.0f, v1 = 0.0f;
            if (r < 36) {
                int k = r >> 2, oc = r & 3;
                const float* wsrc = predW + oc * 2304 + k;
                v0 = wsrc[(2 * cp) * 9];
                v1 = wsrc[(2 * cp + 1) * 9];
            }
            __half2 hv = __floats2half2_rn(v0, v1);
            ad[r * 68 + cp] = *(u32*)&hv;
        }
    } else {
        for (int i = tid; i < 16 * 64; i += K2NT) {
            int r = i >> 6, cp = i & 63;
            float v0 = 0.0f, v1 = 0.0f;
            if (r < 9) {
                v0 = predW[(2 * cp) * 9 + r];
                v1 = predW[(2 * cp + 1) * 9 + r];
            }
            __half2 hv = __floats2half2_rn(v0, v1);
            ad[r * 68 + cp] = *(u32*)&hv;
        }
    }
    __syncthreads();

    // ---- prefetch pass-1 pwt into registers (raw floats; hidden under GEMM0) ----
    float pwf0[8], pwf1[8];
#pragma unroll
    for (int j = 0; j < 8; j++) {
        int i = tid + j * K2NT;
        int o = i >> 5, kp = i & 31;
        const float* wsrc = pwW + (128 + o) * 64 + 2 * kp;
        pwf0[j] = wsrc[0];
        pwf1[j] = wsrc[1];
    }

    gemm_mma(sm, lane, warp, 0);
    __syncthreads();

    // ---- STS prefetched pwt (pass 1), then tap pass 0 ----
#pragma unroll
    for (int j = 0; j < 8; j++) {
        int i = tid + j * K2NT;
        int o = i >> 5, kp = i & 31;
        __half2 hv = __floats2half2_rn(pwf0[j], pwf1[j]);
        pd[o * 36 + kp] = *(u32*)&hv;
    }
    if (t == 1) {
        if (warp < 12) tap_mma<8>(sm, lane, warp >> 2, warp & 3, P, false);
    } else {
        if (warp < 8)  tap_mma<4>(sm, lane, 0, warp, P, false);
    }
    __syncthreads();

    // ---- stage pass-1 A_tap, GEMM pass 1 ----
    if (t == 1) {
        for (int i = tid; i < 48 * 64; i += K2NT) {
            int r = i >> 6, cp = i & 63;
            float v0 = 0.0f, v1 = 0.0f;
            if (r < 36) {
                int k = r >> 2, oc = r & 3;
                const float* wsrc = predW + oc * 2304 + k;
                v0 = wsrc[(128 + 2 * cp) * 9];
                v1 = wsrc[(128 + 2 * cp + 1) * 9];
            }
            __half2 hv = __floats2half2_rn(v0, v1);
            ad[r * 68 + cp] = *(u32*)&hv;
        }
    } else {
        for (int i = tid; i < 16 * 64; i += K2NT) {
            int r = i >> 6, cp = i & 63;
            float v0 = 0.0f, v1 = 0.0f;
            if (r < 9) {
                v0 = predW[(128 + 2 * cp) * 9 + r];
                v1 = predW[(128 + 2 * cp + 1) * 9 + r];
            }
            __half2 hv = __floats2half2_rn(v0, v1);
            ad[r * 68 + cp] = *(u32*)&hv;
        }
    }
    gemm_mma(sm, lane, warp, 128);
    __syncthreads();

    // ---- tap pass 1 (accumulate) ----
    if (t == 1) {
        if (warp < 12) tap_mma<8>(sm, lane, warp >> 2, warp & 3, P, true);
    } else {
        if (warp < 8)  tap_mma<4>(sm, lane, 0, warp, P, true);
    }
    __syncthreads();

    // ---- epilogue ----
    if (tid < 256) {
        const int qx = tid, y = qx >> 4, x = qx & 15;
        if (t == 0) {
            float acc = 0.0f;
#pragma unroll
            for (int dy = -1; dy <= 1; dy++) {
                if (y + dy < 0 || y + dy > 15) continue;
#pragma unroll
                for (int dx = -1; dx <= 1; dx++) {
                    if (x + dx < 0 || x + dx > 15) continue;
                    const int k = (dy + 1) * 3 + (dx + 1);
                    acc += P[k * 256 + qx + dy * 16 + dx];
                }
            }
            out[(size_t)NB * 4 * NHW + (size_t)s * NHW + qx] =
                0.1f * (acc + cls_predb[0]);
        } else {
            float bx0 = 0.f, bx1 = 0.f, bx2 = 0.f, bx3 = 0.f;
#pragma unroll
            for (int dy = -1; dy <= 1; dy++) {
                if (y + dy < 0 || y + dy > 15) continue;
#pragma unroll
                for (int dx = -1; dx <= 1; dx++) {
                    if (x + dx < 0 || x + dx > 15) continue;
                    const int k = (dy + 1) * 3 + (dx + 1);
                    const int q = qx + dy * 16 + dx;
                    bx0 += P[(k * 4 + 0) * 256 + q];
                    bx1 += P[(k * 4 + 1) * 256 + q];
                    bx2 += P[(k * 4 + 2) * 256 + q];
                    bx3 += P[(k * 4 + 3) * 256 + q];
                }
            }
            const float adj = adjust[0];
            out[((size_t)s * 4 + 0) * NHW + qx] = expf(adj * (bx0 + box_predb[0]) + biasp[0]);
            out[((size_t)s * 4 + 1) * NHW + qx] = expf(adj * (bx1 + box_predb[1]) + biasp[1]);
            out[((size_t)s * 4 + 2) * NHW + qx] = expf(adj * (bx2 + box_predb[2]) + biasp[2]);
            out[((size_t)s * 4 + 3) * NHW + qx] = expf(adj * (bx3 + box_predb[3]) + biasp[3]);
        }
    }
}

extern "C" void kernel_launch(void* const* d_in, const int* in_sizes, int n_in,
                              void* d_out, int out_size)
{
    const float* search    = (const float*)d_in[0];
    const float* kern      = (const float*)d_in[1];
    const float* ca_w1     = (const float*)d_in[2];
    const float* ca_b1     = (const float*)d_in[3];
    const float* ca_w2     = (const float*)d_in[4];
    const float* ca_b2     = (const float*)d_in[5];
    const float* cls_dw    = (const float*)d_in[6];
    const float* cls_pw    = (const float*)d_in[7];
    const float* cls_bng   = (const float*)d_in[8];
    const float* cls_bnb   = (const float*)d_in[9];
    const float* cls_bnm   = (const float*)d_in[10];
    const float* cls_bnv   = (const float*)d_in[11];
    const float* cls_predw = (const float*)d_in[12];
    const float* cls_predb = (const float*)d_in[13];
    const float* box_dw    = (const float*)d_in[14];
    const float* box_pw    = (const float*)d_in[15];
    const float* box_bng   = (const float*)d_in[16];
    const float* box_bnb   = (const float*)d_in[17];
    const float* box_bnm   = (const float*)d_in[18];
    const float* box_bnv   = (const float*)d_in[19];
    const float* box_predw = (const float*)d_in[20];
    const float* box_predb = (const float*)d_in[21];
    const float* adjust    = (const float*)d_in[22];
    const float* biasp     = (const float*)d_in[23];

    const int sm1 = K1_TOT * 4;   // 145408 B
    const int sm2 = K2_TOT * 4;   // 191488 B
    cudaFuncSetAttribute(btl_k1, cudaFuncAttributeMaxDynamicSharedMemorySize, sm1);
    cudaFuncSetAttribute(btl_k2, cudaFuncAttributeMaxDynamicSharedMemorySize, sm2);

    btl_k1<<<NB, NT1, sm1>>>(search, kern, ca_w1, ca_b1, ca_w2, ca_b2, cls_dw, box_dw);
    btl_k2<<<NB * 2, K2NT, sm2>>>(cls_pw, cls_bng, cls_bnb, cls_bnm, cls_bnv,
                                  cls_predw, cls_predb,
                                  box_pw, box_bng, box_bnb, box_bnm, box_bnv,
                                  box_predw, box_predb,
                                  adjust, biasp, (float*)d_out);
}